// round 7
// baseline (speedup 1.0000x reference)
#include <cuda_runtime.h>
#include <cuda_fp16.h>
#include <math.h>

#define BB 16
#define SS 1024
#define EE 256
#define HH 8
#define DHD 32
#define MROWS (BB*SS)   // 16384
#define GP 20           // smem pitch (uints); rows 80B apart, 16B aligned, LDSM conflict-free
#define SA_U (128*GP)   // 2560 uints per buffer

// ---------------- scratch ----------------------------------------------------
__device__ unsigned g_wt[6][2][256*128];     // weight planes [n][kpair] hi/lo
__device__ unsigned g_rbh[SS*512];           // rel_bias * log2e, fp16 pairs
__device__ unsigned g_lnh[MROWS*128];
__device__ unsigned g_mth[MROWS*128];
__device__ unsigned g_qph[MROWS*128];        // pre-scaled by log2e/sqrt(DH)
__device__ unsigned g_kph[MROWS*128];
__device__ unsigned g_vph[MROWS*128];
__device__ unsigned g_oph[MROWS*128];
__device__ unsigned g_g1h[MROWS*128];
__device__ float g_gate0[MROWS*EE], g_gate1[MROWS*EE], g_mlp[MROWS*EE];

// ---------------- helpers -----------------------------------------------------
__device__ __forceinline__ unsigned pkh(float a, float b) {
    __half2 t = __floats2half2_rn(a, b);
    return *reinterpret_cast<unsigned*>(&t);
}
__device__ __forceinline__ void split_pack(float a, float b, unsigned &hi, unsigned &lo) {
    __half ah = __float2half_rn(a);
    __half bh = __float2half_rn(b);
    float ar = a - __half2float(ah);
    float br = b - __half2float(bh);
    __half2 H = __halves2half2(ah, bh);
    __half2 L = __floats2half2_rn(ar, br);
    hi = *reinterpret_cast<unsigned*>(&H);
    lo = *reinterpret_cast<unsigned*>(&L);
}
__device__ __forceinline__ void mmah(float* c,
    unsigned a0, unsigned a1, unsigned a2, unsigned a3,
    unsigned b0, unsigned b1)
{
    asm volatile(
        "mma.sync.aligned.m16n8k16.row.col.f32.f16.f16.f32 "
        "{%0,%1,%2,%3},{%4,%5,%6,%7},{%8,%9},{%0,%1,%2,%3};"
        : "+f"(c[0]), "+f"(c[1]), "+f"(c[2]), "+f"(c[3])
        : "r"(a0), "r"(a1), "r"(a2), "r"(a3), "r"(b0), "r"(b1));
}
__device__ __forceinline__ void ldsm4(unsigned &r0, unsigned &r1, unsigned &r2, unsigned &r3, unsigned addr) {
    asm volatile("ldmatrix.sync.aligned.m8n8.x4.shared.b16 {%0,%1,%2,%3}, [%4];"
        : "=r"(r0), "=r"(r1), "=r"(r2), "=r"(r3) : "r"(addr));
}
__device__ __forceinline__ void ldsm4t(unsigned &r0, unsigned &r1, unsigned &r2, unsigned &r3, unsigned addr) {
    asm volatile("ldmatrix.sync.aligned.m8n8.x4.trans.shared.b16 {%0,%1,%2,%3}, [%4];"
        : "=r"(r0), "=r"(r1), "=r"(r2), "=r"(r3) : "r"(addr));
}
__device__ __forceinline__ void cpa16(unsigned dst, const void* src) {
    asm volatile("cp.async.cg.shared.global [%0], [%1], 16;" :: "r"(dst), "l"(src));
}
__device__ __forceinline__ void cpa_commit() {
    asm volatile("cp.async.commit_group;");
}
__device__ __forceinline__ float ex2(float x) {
    float r; asm("ex2.approx.ftz.f32 %0, %1;" : "=f"(r) : "f"(x)); return r;
}
__device__ __forceinline__ float wsum(float v) {
    #pragma unroll
    for (int o = 16; o > 0; o >>= 1) v += __shfl_xor_sync(0xffffffffu, v, o);
    return v;
}

#define L2E 1.4426950408889634f

// ---------------- fused prep: weight split + bias split + LN -----------------
// grid: [0,96) wsplit, [96,1120) bsplit, [1120,3168) ln
__global__ __launch_bounds__(256) void prep(
    const float* __restrict__ x, const float* __restrict__ lng,
    const float* __restrict__ lnb,
    const float* __restrict__ Wq, const float* __restrict__ Wk,
    const float* __restrict__ Wv, const float* __restrict__ gW,
    const float* __restrict__ Wo, const float* __restrict__ mW,
    const float* __restrict__ rel)
{
    __shared__ float s[64][65];
    int bx = blockIdx.x, tid = threadIdx.x;
    if (bx < 96) {
        int w = bx >> 4, rem = bx & 15;
        int k0 = (rem >> 2) * 64, n0 = (rem & 3) * 64;
        const float* W;
        switch (w) {
            case 0: W = Wq; break; case 1: W = Wk; break; case 2: W = Wv; break;
            case 3: W = gW; break; case 4: W = Wo; break; default: W = mW; break;
        }
        for (int i = tid; i < 4096; i += 256) {
            int r = i >> 6, c = i & 63;
            s[r][c] = W[(size_t)(k0 + r)*EE + n0 + c];
        }
        __syncthreads();
        for (int i = tid; i < 2048; i += 256) {
            int n = i >> 5, kp = i & 31;
            unsigned hi, lo;
            split_pack(s[2*kp][n], s[2*kp+1][n], hi, lo);
            int o = (n0 + n)*128 + k0/2 + kp;
            g_wt[w][0][o] = hi;
            g_wt[w][1][o] = lo;
        }
    } else if (bx < 1120) {
        int row = bx - 96;
        #pragma unroll
        for (int j = 0; j < 2; j++) {
            int i = tid + j*256;
            float2 v = *(const float2*)&rel[(size_t)row*SS + 2*i];
            g_rbh[row*512 + i] = pkh(v.x*L2E, v.y*L2E);
        }
    } else {
        int warp = tid >> 5, lane = tid & 31;
        int row = (bx - 1120)*8 + warp;
        const float* xr = x + (size_t)row*EE + lane*8;
        float4 a0 = *(const float4*)xr;
        float4 a1 = *(const float4*)(xr + 4);
        float xv[8] = {a0.x,a0.y,a0.z,a0.w,a1.x,a1.y,a1.z,a1.w};
        float sm = 0.f;
        #pragma unroll
        for (int i = 0; i < 8; i++) sm += xv[i];
        float mean = wsum(sm) * (1.f/EE);
        float vs = 0.f;
        #pragma unroll
        for (int i = 0; i < 8; i++) { float d = xv[i]-mean; vs += d*d; }
        float rstd = rsqrtf(wsum(vs)*(1.f/EE) + 1e-5f);
        float4 g0 = *(const float4*)(lng + lane*8);
        float4 g1 = *(const float4*)(lng + lane*8 + 4);
        float4 b0 = *(const float4*)(lnb + lane*8);
        float4 b1 = *(const float4*)(lnb + lane*8 + 4);
        float gg[8] = {g0.x,g0.y,g0.z,g0.w,g1.x,g1.y,g1.z,g1.w};
        float bb[8] = {b0.x,b0.y,b0.z,b0.w,b1.x,b1.y,b1.z,b1.w};
        float ln[8];
        #pragma unroll
        for (int i = 0; i < 8; i++) ln[i] = (xv[i]-mean)*rstd*gg[i] + bb[i];
        uint4 u, um;
        u.x = pkh(ln[0],ln[1]); u.y = pkh(ln[2],ln[3]);
        u.z = pkh(ln[4],ln[5]); u.w = pkh(ln[6],ln[7]);
        um.x = pkh(xv[0],xv[1]); um.y = pkh(xv[2],xv[3]);
        um.z = pkh(xv[4],xv[5]); um.w = pkh(xv[6],xv[7]);
        *(uint4*)&g_lnh[row*128 + lane*4] = u;
        *(uint4*)&g_mth[row*128 + lane*4] = um;
    }
}

// ---------------- final: out = gate1 * LN(mlp) + gate1 ------------------------
__global__ __launch_bounds__(256) void final_kernel(
    const float* __restrict__ g, const float* __restrict__ b,
    float* __restrict__ out)
{
    int warp = threadIdx.x >> 5, lane = threadIdx.x & 31;
    int row = blockIdx.x*8 + warp;
    const float* mr = g_mlp + (size_t)row*EE + lane*8;
    float4 a0 = *(const float4*)mr;
    float4 a1 = *(const float4*)(mr + 4);
    float xv[8] = {a0.x,a0.y,a0.z,a0.w,a1.x,a1.y,a1.z,a1.w};
    float s = 0.f;
    #pragma unroll
    for (int i = 0; i < 8; i++) s += xv[i];
    float mean = wsum(s) * (1.f/EE);
    float vs = 0.f;
    #pragma unroll
    for (int i = 0; i < 8; i++) { float d = xv[i]-mean; vs += d*d; }
    float rstd = rsqrtf(wsum(vs)*(1.f/EE) + 1e-5f);
    float4 g0 = *(const float4*)(g + lane*8);
    float4 g1v = *(const float4*)(g + lane*8 + 4);
    float4 b0 = *(const float4*)(b + lane*8);
    float4 b1 = *(const float4*)(b + lane*8 + 4);
    float gg[8] = {g0.x,g0.y,g0.z,g0.w,g1v.x,g1v.y,g1v.z,g1v.w};
    float bb[8] = {b0.x,b0.y,b0.z,b0.w,b1.x,b1.y,b1.z,b1.w};
    const float* gr = g_gate1 + (size_t)row*EE + lane*8;
    float4 q0 = *(const float4*)gr;
    float4 q1 = *(const float4*)(gr + 4);
    float gv[8] = {q0.x,q0.y,q0.z,q0.w,q1.x,q1.y,q1.z,q1.w};
    float o[8];
    #pragma unroll
    for (int i = 0; i < 8; i++) {
        float lnm = (xv[i]-mean)*rstd*gg[i] + bb[i];
        o[i] = gv[i]*lnm + gv[i];
    }
    float* orow = out + (size_t)row*EE + lane*8;
    *(float4*)orow       = make_float4(o[0],o[1],o[2],o[3]);
    *(float4*)(orow + 4) = make_float4(o[4],o[5],o[6],o[7]);
}

// ---------------- fp16 GEMM, 128x128 tile, cp.async double-buffered ----------
// dyn smem layout (uints): sA[2]@0, sBh[2]@5120, sBl[2]@10240
__global__ __launch_bounds__(256) void gemm_h(
    const float* __restrict__ bq, const float* __restrict__ bk,
    const float* __restrict__ bv, const float* __restrict__ gb,
    const float* __restrict__ bo, const float* __restrict__ mb,
    const float* __restrict__ Matrix, int op_base)
{
    extern __shared__ __align__(16) unsigned smem[];
    int op = op_base + blockIdx.z;
    const unsigned* Ah;
    const float* bias;
    switch (op) {
        case 0: Ah = g_lnh; bias = bq; break;
        case 1: Ah = g_lnh; bias = bk; break;
        case 2: Ah = g_lnh; bias = bv; break;
        case 3: Ah = g_mth; bias = gb; break;
        case 4: Ah = g_oph; bias = bo; break;
        default: Ah = g_g1h; bias = mb; break;
    }
    bool p2 = (op >= 4);
    const unsigned* Wh = g_wt[op][0];
    const unsigned* Wl = g_wt[op][1];

    int tid = threadIdx.x, lane = tid & 31, warp = tid >> 5;
    int wm = warp >> 1, wn = warp & 1;
    int g = lane >> 2, t = lane & 3;
    int m0 = blockIdx.y * 128, n0 = blockIdx.x * 128;

    unsigned s_u = (unsigned)__cvta_generic_to_shared(smem);
    // byte offsets of regions
    const unsigned A_OFF = 0, BH_OFF = 2*SA_U*4, BL_OFF = 4*SA_U*4;
    const unsigned BUF = SA_U*4;   // 10240 B per buffer

    int l16 = lane & 15, secA = lane >> 4;
    unsigned aFrag = s_u + A_OFF + (((wm*32 + l16)*GP) + secA*4)*4;
    int l8 = lane & 7, qd = lane >> 3;
    unsigned bFrag = (((wn*64 + (qd>>1)*8 + l8)*GP) + (qd&1)*4)*4;

    // per-thread load indices (2 uint4 per region)
    int arow[2], af4[2];
    #pragma unroll
    for (int j = 0; j < 2; j++) { int idx = tid + j*256; arow[j] = idx >> 2; af4[j] = idx & 3; }

    float acc[2][8][4];
    #pragma unroll
    for (int mt = 0; mt < 2; mt++)
        #pragma unroll
        for (int nt = 0; nt < 8; nt++)
            #pragma unroll
            for (int i = 0; i < 4; i++) acc[mt][nt][i] = 0.f;

    // issue chunk 0
    #pragma unroll
    for (int j = 0; j < 2; j++) {
        unsigned d = s_u + A_OFF + (arow[j]*GP + af4[j]*4)*4;
        cpa16(d, &Ah[(size_t)(m0 + arow[j])*128 + af4[j]*4]);
        unsigned db = s_u + BH_OFF + (arow[j]*GP + af4[j]*4)*4;
        cpa16(db, &Wh[(size_t)(n0 + arow[j])*128 + af4[j]*4]);
        if (p2) {
            unsigned dl = s_u + BL_OFF + (arow[j]*GP + af4[j]*4)*4;
            cpa16(dl, &Wl[(size_t)(n0 + arow[j])*128 + af4[j]*4]);
        }
    }
    cpa_commit();

    #pragma unroll 1
    for (int c = 0; c < 8; c++) {
        if (c < 7) {
            int cc = (c+1)*16, bsel = (c+1) & 1;
            #pragma unroll
            for (int j = 0; j < 2; j++) {
                unsigned d = s_u + A_OFF + bsel*BUF + (arow[j]*GP + af4[j]*4)*4;
                cpa16(d, &Ah[(size_t)(m0 + arow[j])*128 + cc + af4[j]*4]);
                unsigned db = s_u + BH_OFF + bsel*BUF + (arow[j]*GP + af4[j]*4)*4;
                cpa16(db, &Wh[(size_t)(n0 + arow[j])*128 + cc + af4[j]*4]);
                if (p2) {
                    unsigned dl = s_u + BL_OFF + bsel*BUF + (arow[j]*GP + af4[j]*4)*4;
                    cpa16(dl, &Wl[(size_t)(n0 + arow[j])*128 + cc + af4[j]*4]);
                }
            }
            cpa_commit();
            asm volatile("cp.async.wait_group 1;");
        } else {
            asm volatile("cp.async.wait_group 0;");
        }
        __syncthreads();

        int bsel = c & 1;
        #pragma unroll
        for (int kk = 0; kk < 2; kk++) {
            unsigned a[2][4];
            #pragma unroll
            for (int mt = 0; mt < 2; mt++)
                ldsm4(a[mt][0], a[mt][1], a[mt][2], a[mt][3],
                      aFrag + bsel*BUF + mt*1280 + kk*32);
            #pragma unroll
            for (int pr = 0; pr < 4; pr++) {
                unsigned b0, b1, b2, b3;
                ldsm4(b0, b1, b2, b3, s_u + BH_OFF + bsel*BUF + bFrag + pr*1280 + kk*32);
                #pragma unroll
                for (int mt = 0; mt < 2; mt++) {
                    mmah(acc[mt][2*pr  ], a[mt][0], a[mt][1], a[mt][2], a[mt][3], b0, b1);
                    mmah(acc[mt][2*pr+1], a[mt][0], a[mt][1], a[mt][2], a[mt][3], b2, b3);
                }
                if (p2) {
                    unsigned c0, c1, c2, c3;
                    ldsm4(c0, c1, c2, c3, s_u + BL_OFF + bsel*BUF + bFrag + pr*1280 + kk*32);
                    #pragma unroll
                    for (int mt = 0; mt < 2; mt++) {
                        mmah(acc[mt][2*pr  ], a[mt][0], a[mt][1], a[mt][2], a[mt][3], c0, c1);
                        mmah(acc[mt][2*pr+1], a[mt][0], a[mt][1], a[mt][2], a[mt][3], c2, c3);
                    }
                }
            }
        }
        __syncthreads();
    }

    const float qscale = 0.17677669529663687f * L2E;  // 1/sqrt(32) * log2e
    #pragma unroll
    for (int mt = 0; mt < 2; mt++) {
        int row0 = m0 + wm*32 + mt*16 + g;
        int row1 = row0 + 8;
        #pragma unroll
        for (int nt = 0; nt < 8; nt++) {
            int col = n0 + wn*64 + nt*8 + t*2;
            int cp  = col >> 1;
            float bv0 = bias[col], bv1 = bias[col+1];
            float v00 = acc[mt][nt][0] + bv0, v01 = acc[mt][nt][1] + bv1;
            float v10 = acc[mt][nt][2] + bv0, v11 = acc[mt][nt][3] + bv1;
            if (op == 0) {
                g_qph[row0*128 + cp] = pkh(v00*qscale, v01*qscale);
                g_qph[row1*128 + cp] = pkh(v10*qscale, v11*qscale);
            } else if (op == 1) {
                g_kph[row0*128 + cp] = pkh(v00, v01);
                g_kph[row1*128 + cp] = pkh(v10, v11);
            } else if (op == 2) {
                g_vph[row0*128 + cp] = pkh(v00, v01);
                g_vph[row1*128 + cp] = pkh(v10, v11);
            } else if (op == 3 || op == 5) {
                float* dst = (op == 3) ? g_gate0 : g_mlp;
                v00 = 1.f/(1.f + __expf(-v00)); v01 = 1.f/(1.f + __expf(-v01));
                v10 = 1.f/(1.f + __expf(-v10)); v11 = 1.f/(1.f + __expf(-v11));
                *(float2*)&dst[(size_t)row0*EE + col] = make_float2(v00, v01);
                *(float2*)&dst[(size_t)row1*EE + col] = make_float2(v10, v11);
            } else {  // op 4
                size_t i0 = (size_t)row0*EE + col, i1 = (size_t)row1*EE + col;
                float2 ga0 = *(const float2*)&g_gate0[i0];
                float2 ga1 = *(const float2*)&g_gate0[i1];
                float2 mx0 = *(const float2*)&Matrix[i0];
                float2 mx1 = *(const float2*)&Matrix[i1];
                v00 = ga0.x*v00 + mx0.x;  v01 = ga0.y*v01 + mx0.y;
                v10 = ga1.x*v10 + mx1.x;  v11 = ga1.y*v11 + mx1.y;
                *(float2*)&g_gate1[i0] = make_float2(v00, v01);
                *(float2*)&g_gate1[i1] = make_float2(v10, v11);
                g_g1h[row0*128 + cp] = pkh(v00, v01);
                g_g1h[row1*128 + cp] = pkh(v10, v11);
            }
        }
    }
}

// ---------------- fp16 flash attention, cp.async double-buffered --------------
__global__ __launch_bounds__(256) void attn_h()
{
    __shared__ __align__(16) unsigned sK[2][64*GP];
    __shared__ __align__(16) unsigned sV[2][64*GP];

    int tid = threadIdx.x, lane = tid & 31, wq = tid >> 5;
    int g = lane >> 2, t = lane & 3;
    int bh = blockIdx.x, b = bh >> 3, hd = bh & 7;
    int q0 = blockIdx.y * 128;

    int r0 = q0 + wq*16 + g;
    int qrow0 = b*SS + r0, qrow1 = qrow0 + 8;

    unsigned sK_u = (unsigned)__cvta_generic_to_shared(sK);
    unsigned sV_u = (unsigned)__cvta_generic_to_shared(sV);
    const unsigned KBUF = 64*GP*4;     // 5120 B
    int l8 = lane & 7, qd = lane >> 3;
    unsigned kFrag = sK_u + (((qd>>1)*8 + l8)*GP + (qd&1)*4)*4;
    unsigned vFrag = sV_u + (((qd&1)*8 + l8)*GP)*4 + (qd>>1)*16;

    unsigned qhf[2][4];
    #pragma unroll
    for (int kk = 0; kk < 2; kk++) {
        int b0 = qrow0*128 + hd*16 + kk*8 + t;
        int b1 = qrow1*128 + hd*16 + kk*8 + t;
        qhf[kk][0] = g_qph[b0]; qhf[kk][1] = g_qph[b1];
        qhf[kk][2] = g_qph[b0+4]; qhf[kk][3] = g_qph[b1+4];
    }

    float O[4][4];
    #pragma unroll
    for (int dn = 0; dn < 4; dn++)
        #pragma unroll
        for (int i = 0; i < 4; i++) O[dn][i] = 0.f;
    float m0s = -1e30f, m1s = -1e30f, l0s = 0.f, l1s = 0.f;

    int ldr = tid >> 2, ldf = tid & 3;
    unsigned kDst = sK_u + (ldr*GP + ldf*4)*4;
    unsigned vDst = sV_u + (ldr*GP + ldf*4)*4;

    // issue tile 0
    cpa16(kDst, &g_kph[(size_t)(b*SS + ldr)*128 + hd*16 + ldf*4]);
    cpa16(vDst, &g_vph[(size_t)(b*SS + ldr)*128 + hd*16 + ldf*4]);
    cpa_commit();

    #pragma unroll 1
    for (int kt = 0; kt < 16; kt++) {
        int k0 = kt*64;
        if (kt < 15) {
            int bsel = (kt+1) & 1;
            cpa16(kDst + bsel*KBUF, &g_kph[(size_t)(b*SS + k0+64 + ldr)*128 + hd*16 + ldf*4]);
            cpa16(vDst + bsel*KBUF, &g_vph[(size_t)(b*SS + k0+64 + ldr)*128 + hd*16 + ldf*4]);
            cpa_commit();
            asm volatile("cp.async.wait_group 1;");
        } else {
            asm volatile("cp.async.wait_group 0;");
        }
        __syncthreads();
        int bsel = kt & 1;

        // scores (log2-domain: q pre-scaled by log2e/sqrt(dh), bias pre-scaled)
        float S_[8][4];
        #pragma unroll
        for (int nt = 0; nt < 8; nt++)
            #pragma unroll
            for (int i = 0; i < 4; i++) S_[nt][i] = 0.f;
        #pragma unroll
        for (int kk = 0; kk < 2; kk++) {
            #pragma unroll
            for (int p = 0; p < 4; p++) {
                unsigned k0r, k1r, k2r, k3r;
                ldsm4(k0r, k1r, k2r, k3r, kFrag + bsel*KBUF + p*1280 + kk*32);
                mmah(S_[2*p  ], qhf[kk][0], qhf[kk][1], qhf[kk][2], qhf[kk][3], k0r, k1r);
                mmah(S_[2*p+1], qhf[kk][0], qhf[kk][1], qhf[kk][2], qhf[kk][3], k2r, k3r);
            }
        }
        #pragma unroll
        for (int nt = 0; nt < 8; nt++) {
            int pc = (k0 >> 1) + nt*4 + t;
            unsigned u0 = g_rbh[r0*512 + pc];
            unsigned u1 = g_rbh[(r0+8)*512 + pc];
            float2 b0v = __half22float2(*reinterpret_cast<__half2*>(&u0));
            float2 b1v = __half22float2(*reinterpret_cast<__half2*>(&u1));
            S_[nt][0] += b0v.x; S_[nt][1] += b0v.y;
            S_[nt][2] += b1v.x; S_[nt][3] += b1v.y;
        }

        float tm0 = -1e30f, tm1 = -1e30f;
        #pragma unroll
        for (int nt = 0; nt < 8; nt++) {
            tm0 = fmaxf(tm0, fmaxf(S_[nt][0], S_[nt][1]));
            tm1 = fmaxf(tm1, fmaxf(S_[nt][2], S_[nt][3]));
        }
        tm0 = fmaxf(tm0, __shfl_xor_sync(0xffffffffu, tm0, 1));
        tm0 = fmaxf(tm0, __shfl_xor_sync(0xffffffffu, tm0, 2));
        tm1 = fmaxf(tm1, __shfl_xor_sync(0xffffffffu, tm1, 1));
        tm1 = fmaxf(tm1, __shfl_xor_sync(0xffffffffu, tm1, 2));
        float nm0 = fmaxf(m0s, tm0), nm1 = fmaxf(m1s, tm1);
        float sc0 = ex2(m0s - nm0), sc1 = ex2(m1s - nm1);
        float rs0 = 0.f, rs1 = 0.f;
        unsigned pf[8][2];
        #pragma unroll
        for (int nt = 0; nt < 8; nt++) {
            float p0 = ex2(S_[nt][0] - nm0);
            float p1 = ex2(S_[nt][1] - nm0);
            float p2 = ex2(S_[nt][2] - nm1);
            float p3 = ex2(S_[nt][3] - nm1);
            rs0 += p0 + p1;  rs1 += p2 + p3;
            pf[nt][0] = pkh(p0, p1);
            pf[nt][1] = pkh(p2, p3);
        }
        rs0 += __shfl_xor_sync(0xffffffffu, rs0, 1);
        rs0 += __shfl_xor_sync(0xffffffffu, rs0, 2);
        rs1 += __shfl_xor_sync(0xffffffffu, rs1, 1);
        rs1 += __shfl_xor_sync(0xffffffffu, rs1, 2);
        l0s = l0s*sc0 + rs0;
        l1s = l1s*sc1 + rs1;
        m0s = nm0;  m1s = nm1;
        #pragma unroll
        for (int dn = 0; dn < 4; dn++) {
            O[dn][0] *= sc0; O[dn][1] *= sc0;
            O[dn][2] *= sc1; O[dn][3] *= sc1;
        }

        #pragma unroll
        for (int kk = 0; kk < 4; kk++) {
            unsigned a0 = pf[2*kk][0], a1 = pf[2*kk][1];
            unsigned a2 = pf[2*kk+1][0], a3 = pf[2*kk+1][1];
            #pragma unroll
            for (int p = 0; p < 2; p++) {
                unsigned v0, v1, v2, v3;
                ldsm4t(v0, v1, v2, v3, vFrag + bsel*KBUF + kk*1280 + p*32);
                mmah(O[2*p  ], a0, a1, a2, a3, v0, v1);
                mmah(O[2*p+1], a0, a1, a2, a3, v2, v3);
            }
        }
        __syncthreads();
    }

    float il0 = 1.f/l0s, il1 = 1.f/l1s;
    #pragma unroll
    for (int dn = 0; dn < 4; dn++) {
        int cp = hd*16 + dn*4 + t;
        g_oph[qrow0*128 + cp] = pkh(O[dn][0]*il0, O[dn][1]*il0);
        g_oph[qrow1*128 + cp] = pkh(O[dn][2]*il1, O[dn][3]*il1);
    }
}

// ---------------- launch ------------------------------------------------------
extern "C" void kernel_launch(void* const* d_in, const int* in_sizes, int n_in,
                              void* d_out, int out_size)
{
    const float* Matrix = (const float*)d_in[0];
    const float* ln_g   = (const float*)d_in[1];
    const float* ln_b   = (const float*)d_in[2];
    const float* Wq     = (const float*)d_in[3];
    const float* bq     = (const float*)d_in[4];
    const float* Wk     = (const float*)d_in[5];
    const float* bk     = (const float*)d_in[6];
    const float* Wv     = (const float*)d_in[7];
    const float* bv     = (const float*)d_in[8];
    const float* Wo     = (const float*)d_in[9];
    const float* bo     = (const float*)d_in[10];
    const float* rel    = (const float*)d_in[11];
    const float* gW     = (const float*)d_in[12];
    const float* gb     = (const float*)d_in[13];
    const float* mW     = (const float*)d_in[14];
    const float* mb     = (const float*)d_in[15];
    float* out = (float*)d_out;

    static bool attr_set = false;
    if (!attr_set) {
        cudaFuncSetAttribute(gemm_h, cudaFuncAttributeMaxDynamicSharedMemorySize, 6*SA_U*4);
        attr_set = true;
    }

    prep<<<3168, 256>>>(Matrix, ln_g, ln_b, Wq, Wk, Wv, gW, Wo, mW, rel);

    gemm_h<<<dim3(2,128,4), 256, 4*SA_U*4>>>(bq, bk, bv, gb, bo, mb, Matrix, 0);
    attn_h<<<dim3(BB*HH, SS/128), 256>>>();
    gemm_h<<<dim3(2,128,1), 256, 6*SA_U*4>>>(bq, bk, bv, gb, bo, mb, Matrix, 4);
    gemm_h<<<dim3(2,128,1), 256, 6*SA_U*4>>>(bq, bk, bv, gb, bo, mb, Matrix, 5);

    final_kernel<<<MROWS/8, 256>>>(ln_g, ln_b, out);
}

// round 8
// speedup vs baseline: 1.0848x; 1.0848x over previous
#include <cuda_runtime.h>
#include <cuda_fp16.h>
#include <math.h>

#define BB 16
#define SS 1024
#define EE 256
#define HH 8
#define DHD 32
#define MROWS (BB*SS)   // 16384
#define GP 20           // smem pitch (uints); rows 80B apart, 16B aligned, LDSM conflict-free
#define SA_U (128*GP)   // 2560 uints per buffer

// ---------------- scratch ----------------------------------------------------
__device__ unsigned g_wt[6][2][256*128];     // weight planes [n][kpair] hi/lo
__device__ unsigned g_rbh[SS*512];           // rel_bias * log2e, fp16 pairs
__device__ unsigned g_lnh[MROWS*128];
__device__ unsigned g_mth[MROWS*128];
__device__ unsigned g_qph[MROWS*128];        // pre-scaled by log2e/sqrt(DH)
__device__ unsigned g_kph[MROWS*128];
__device__ unsigned g_vph[MROWS*128];
__device__ unsigned g_oph[MROWS*128];
__device__ unsigned g_g1h[MROWS*128];
__device__ float g_gate0[MROWS*EE], g_gate1[MROWS*EE], g_mlp[MROWS*EE];

// ---------------- helpers -----------------------------------------------------
__device__ __forceinline__ unsigned pkh(float a, float b) {
    __half2 t = __floats2half2_rn(a, b);
    return *reinterpret_cast<unsigned*>(&t);
}
__device__ __forceinline__ void split_pack(float a, float b, unsigned &hi, unsigned &lo) {
    __half ah = __float2half_rn(a);
    __half bh = __float2half_rn(b);
    float ar = a - __half2float(ah);
    float br = b - __half2float(bh);
    __half2 H = __halves2half2(ah, bh);
    __half2 L = __floats2half2_rn(ar, br);
    hi = *reinterpret_cast<unsigned*>(&H);
    lo = *reinterpret_cast<unsigned*>(&L);
}
__device__ __forceinline__ void mmah(float* c,
    unsigned a0, unsigned a1, unsigned a2, unsigned a3,
    unsigned b0, unsigned b1)
{
    asm volatile(
        "mma.sync.aligned.m16n8k16.row.col.f32.f16.f16.f32 "
        "{%0,%1,%2,%3},{%4,%5,%6,%7},{%8,%9},{%0,%1,%2,%3};"
        : "+f"(c[0]), "+f"(c[1]), "+f"(c[2]), "+f"(c[3])
        : "r"(a0), "r"(a1), "r"(a2), "r"(a3), "r"(b0), "r"(b1));
}
__device__ __forceinline__ void ldsm4(unsigned &r0, unsigned &r1, unsigned &r2, unsigned &r3, unsigned addr) {
    asm volatile("ldmatrix.sync.aligned.m8n8.x4.shared.b16 {%0,%1,%2,%3}, [%4];"
        : "=r"(r0), "=r"(r1), "=r"(r2), "=r"(r3) : "r"(addr));
}
__device__ __forceinline__ void ldsm4t(unsigned &r0, unsigned &r1, unsigned &r2, unsigned &r3, unsigned addr) {
    asm volatile("ldmatrix.sync.aligned.m8n8.x4.trans.shared.b16 {%0,%1,%2,%3}, [%4];"
        : "=r"(r0), "=r"(r1), "=r"(r2), "=r"(r3) : "r"(addr));
}
__device__ __forceinline__ void cpa16(unsigned dst, const void* src) {
    asm volatile("cp.async.cg.shared.global [%0], [%1], 16;" :: "r"(dst), "l"(src));
}
__device__ __forceinline__ void cpa_commit() {
    asm volatile("cp.async.commit_group;");
}
__device__ __forceinline__ float ex2(float x) {
    float r; asm("ex2.approx.ftz.f32 %0, %1;" : "=f"(r) : "f"(x)); return r;
}
__device__ __forceinline__ float wsum(float v) {
    #pragma unroll
    for (int o = 16; o > 0; o >>= 1) v += __shfl_xor_sync(0xffffffffu, v, o);
    return v;
}

#define L2E 1.4426950408889634f

// ---------------- fused prep: weight split + bias split + LN -----------------
__global__ __launch_bounds__(256) void prep(
    const float* __restrict__ x, const float* __restrict__ lng,
    const float* __restrict__ lnb,
    const float* __restrict__ Wq, const float* __restrict__ Wk,
    const float* __restrict__ Wv, const float* __restrict__ gW,
    const float* __restrict__ Wo, const float* __restrict__ mW,
    const float* __restrict__ rel)
{
    __shared__ float s[64][65];
    int bx = blockIdx.x, tid = threadIdx.x;
    if (bx < 96) {
        int w = bx >> 4, rem = bx & 15;
        int k0 = (rem >> 2) * 64, n0 = (rem & 3) * 64;
        const float* W;
        switch (w) {
            case 0: W = Wq; break; case 1: W = Wk; break; case 2: W = Wv; break;
            case 3: W = gW; break; case 4: W = Wo; break; default: W = mW; break;
        }
        for (int i = tid; i < 4096; i += 256) {
            int r = i >> 6, c = i & 63;
            s[r][c] = W[(size_t)(k0 + r)*EE + n0 + c];
        }
        __syncthreads();
        for (int i = tid; i < 2048; i += 256) {
            int n = i >> 5, kp = i & 31;
            unsigned hi, lo;
            split_pack(s[2*kp][n], s[2*kp+1][n], hi, lo);
            int o = (n0 + n)*128 + k0/2 + kp;
            g_wt[w][0][o] = hi;
            g_wt[w][1][o] = lo;
        }
    } else if (bx < 1120) {
        int row = bx - 96;
        #pragma unroll
        for (int j = 0; j < 2; j++) {
            int i = tid + j*256;
            float2 v = *(const float2*)&rel[(size_t)row*SS + 2*i];
            g_rbh[row*512 + i] = pkh(v.x*L2E, v.y*L2E);
        }
    } else {
        int warp = tid >> 5, lane = tid & 31;
        int row = (bx - 1120)*8 + warp;
        const float* xr = x + (size_t)row*EE + lane*8;
        float4 a0 = *(const float4*)xr;
        float4 a1 = *(const float4*)(xr + 4);
        float xv[8] = {a0.x,a0.y,a0.z,a0.w,a1.x,a1.y,a1.z,a1.w};
        float sm = 0.f;
        #pragma unroll
        for (int i = 0; i < 8; i++) sm += xv[i];
        float mean = wsum(sm) * (1.f/EE);
        float vs = 0.f;
        #pragma unroll
        for (int i = 0; i < 8; i++) { float d = xv[i]-mean; vs += d*d; }
        float rstd = rsqrtf(wsum(vs)*(1.f/EE) + 1e-5f);
        float4 g0 = *(const float4*)(lng + lane*8);
        float4 g1 = *(const float4*)(lng + lane*8 + 4);
        float4 b0 = *(const float4*)(lnb + lane*8);
        float4 b1 = *(const float4*)(lnb + lane*8 + 4);
        float gg[8] = {g0.x,g0.y,g0.z,g0.w,g1.x,g1.y,g1.z,g1.w};
        float bb[8] = {b0.x,b0.y,b0.z,b0.w,b1.x,b1.y,b1.z,b1.w};
        float ln[8];
        #pragma unroll
        for (int i = 0; i < 8; i++) ln[i] = (xv[i]-mean)*rstd*gg[i] + bb[i];
        uint4 u, um;
        u.x = pkh(ln[0],ln[1]); u.y = pkh(ln[2],ln[3]);
        u.z = pkh(ln[4],ln[5]); u.w = pkh(ln[6],ln[7]);
        um.x = pkh(xv[0],xv[1]); um.y = pkh(xv[2],xv[3]);
        um.z = pkh(xv[4],xv[5]); um.w = pkh(xv[6],xv[7]);
        *(uint4*)&g_lnh[row*128 + lane*4] = u;
        *(uint4*)&g_mth[row*128 + lane*4] = um;
    }
}

// ---------------- final: out = gate1 * LN(mlp) + gate1 ------------------------
__global__ __launch_bounds__(256) void final_kernel(
    const float* __restrict__ g, const float* __restrict__ b,
    float* __restrict__ out)
{
    int warp = threadIdx.x >> 5, lane = threadIdx.x & 31;
    int row = blockIdx.x*8 + warp;
    const float* mr = g_mlp + (size_t)row*EE + lane*8;
    float4 a0 = *(const float4*)mr;
    float4 a1 = *(const float4*)(mr + 4);
    float xv[8] = {a0.x,a0.y,a0.z,a0.w,a1.x,a1.y,a1.z,a1.w};
    float s = 0.f;
    #pragma unroll
    for (int i = 0; i < 8; i++) s += xv[i];
    float mean = wsum(s) * (1.f/EE);
    float vs = 0.f;
    #pragma unroll
    for (int i = 0; i < 8; i++) { float d = xv[i]-mean; vs += d*d; }
    float rstd = rsqrtf(wsum(vs)*(1.f/EE) + 1e-5f);
    float4 g0 = *(const float4*)(g + lane*8);
    float4 g1v = *(const float4*)(g + lane*8 + 4);
    float4 b0 = *(const float4*)(b + lane*8);
    float4 b1 = *(const float4*)(b + lane*8 + 4);
    float gg[8] = {g0.x,g0.y,g0.z,g0.w,g1v.x,g1v.y,g1v.z,g1v.w};
    float bb[8] = {b0.x,b0.y,b0.z,b0.w,b1.x,b1.y,b1.z,b1.w};
    const float* gr = g_gate1 + (size_t)row*EE + lane*8;
    float4 q0 = *(const float4*)gr;
    float4 q1 = *(const float4*)(gr + 4);
    float gv[8] = {q0.x,q0.y,q0.z,q0.w,q1.x,q1.y,q1.z,q1.w};
    float o[8];
    #pragma unroll
    for (int i = 0; i < 8; i++) {
        float lnm = (xv[i]-mean)*rstd*gg[i] + bb[i];
        o[i] = gv[i]*lnm + gv[i];
    }
    float* orow = out + (size_t)row*EE + lane*8;
    *(float4*)orow       = make_float4(o[0],o[1],o[2],o[3]);
    *(float4*)(orow + 4) = make_float4(o[4],o[5],o[6],o[7]);
}

// ---------------- fp16 GEMM, 128x128 tile, cp.async, 2 blocks/SM --------------
__global__ __launch_bounds__(256, 2) void gemm_h(
    const float* __restrict__ bq, const float* __restrict__ bk,
    const float* __restrict__ bv, const float* __restrict__ gb,
    const float* __restrict__ bo, const float* __restrict__ mb,
    const float* __restrict__ Matrix, int op_base)
{
    extern __shared__ __align__(16) unsigned smem[];
    int op = op_base + blockIdx.z;
    const unsigned* Ah;
    const float* bias;
    switch (op) {
        case 0: Ah = g_lnh; bias = bq; break;
        case 1: Ah = g_lnh; bias = bk; break;
        case 2: Ah = g_lnh; bias = bv; break;
        case 3: Ah = g_mth; bias = gb; break;
        case 4: Ah = g_oph; bias = bo; break;
        default: Ah = g_g1h; bias = mb; break;
    }
    bool p2 = (op >= 4);
    const unsigned* Wh = g_wt[op][0];
    const unsigned* Wl = g_wt[op][1];

    int tid = threadIdx.x, lane = tid & 31, warp = tid >> 5;
    int wm = warp >> 1, wn = warp & 1;
    int g = lane >> 2, t = lane & 3;
    int m0 = blockIdx.y * 128, n0 = blockIdx.x * 128;

    unsigned s_u = (unsigned)__cvta_generic_to_shared(smem);
    const unsigned A_OFF = 0, BH_OFF = 2*SA_U*4, BL_OFF = 4*SA_U*4;
    const unsigned BUF = SA_U*4;   // 10240 B per buffer

    int l16 = lane & 15, secA = lane >> 4;
    unsigned aFrag = s_u + A_OFF + (((wm*32 + l16)*GP) + secA*4)*4;
    int l8 = lane & 7, qd = lane >> 3;
    unsigned bFrag = (((wn*64 + (qd>>1)*8 + l8)*GP) + (qd&1)*4)*4;

    int arow[2], af4[2];
    #pragma unroll
    for (int j = 0; j < 2; j++) { int idx = tid + j*256; arow[j] = idx >> 2; af4[j] = idx & 3; }

    float acc[2][8][4];
    #pragma unroll
    for (int mt = 0; mt < 2; mt++)
        #pragma unroll
        for (int nt = 0; nt < 8; nt++)
            #pragma unroll
            for (int i = 0; i < 4; i++) acc[mt][nt][i] = 0.f;

    #pragma unroll
    for (int j = 0; j < 2; j++) {
        unsigned d = s_u + A_OFF + (arow[j]*GP + af4[j]*4)*4;
        cpa16(d, &Ah[(size_t)(m0 + arow[j])*128 + af4[j]*4]);
        unsigned db = s_u + BH_OFF + (arow[j]*GP + af4[j]*4)*4;
        cpa16(db, &Wh[(size_t)(n0 + arow[j])*128 + af4[j]*4]);
        if (p2) {
            unsigned dl = s_u + BL_OFF + (arow[j]*GP + af4[j]*4)*4;
            cpa16(dl, &Wl[(size_t)(n0 + arow[j])*128 + af4[j]*4]);
        }
    }
    cpa_commit();

    #pragma unroll 1
    for (int c = 0; c < 8; c++) {
        if (c < 7) {
            int cc = (c+1)*16, bsel = (c+1) & 1;
            #pragma unroll
            for (int j = 0; j < 2; j++) {
                unsigned d = s_u + A_OFF + bsel*BUF + (arow[j]*GP + af4[j]*4)*4;
                cpa16(d, &Ah[(size_t)(m0 + arow[j])*128 + cc + af4[j]*4]);
                unsigned db = s_u + BH_OFF + bsel*BUF + (arow[j]*GP + af4[j]*4)*4;
                cpa16(db, &Wh[(size_t)(n0 + arow[j])*128 + cc + af4[j]*4]);
                if (p2) {
                    unsigned dl = s_u + BL_OFF + bsel*BUF + (arow[j]*GP + af4[j]*4)*4;
                    cpa16(dl, &Wl[(size_t)(n0 + arow[j])*128 + cc + af4[j]*4]);
                }
            }
            cpa_commit();
            asm volatile("cp.async.wait_group 1;");
        } else {
            asm volatile("cp.async.wait_group 0;");
        }
        __syncthreads();

        int bsel = c & 1;
        #pragma unroll
        for (int kk = 0; kk < 2; kk++) {
            unsigned a[2][4];
            #pragma unroll
            for (int mt = 0; mt < 2; mt++)
                ldsm4(a[mt][0], a[mt][1], a[mt][2], a[mt][3],
                      aFrag + bsel*BUF + mt*1280 + kk*32);
            #pragma unroll
            for (int pr = 0; pr < 4; pr++) {
                unsigned b0, b1, b2, b3;
                ldsm4(b0, b1, b2, b3, s_u + BH_OFF + bsel*BUF + bFrag + pr*1280 + kk*32);
                #pragma unroll
                for (int mt = 0; mt < 2; mt++) {
                    mmah(acc[mt][2*pr  ], a[mt][0], a[mt][1], a[mt][2], a[mt][3], b0, b1);
                    mmah(acc[mt][2*pr+1], a[mt][0], a[mt][1], a[mt][2], a[mt][3], b2, b3);
                }
                if (p2) {
                    unsigned c0, c1, c2, c3;
                    ldsm4(c0, c1, c2, c3, s_u + BL_OFF + bsel*BUF + bFrag + pr*1280 + kk*32);
                    #pragma unroll
                    for (int mt = 0; mt < 2; mt++) {
                        mmah(acc[mt][2*pr  ], a[mt][0], a[mt][1], a[mt][2], a[mt][3], c0, c1);
                        mmah(acc[mt][2*pr+1], a[mt][0], a[mt][1], a[mt][2], a[mt][3], c2, c3);
                    }
                }
            }
        }
        __syncthreads();
    }

    const float qscale = 0.17677669529663687f * L2E;
    #pragma unroll
    for (int mt = 0; mt < 2; mt++) {
        int row0 = m0 + wm*32 + mt*16 + g;
        int row1 = row0 + 8;
        #pragma unroll
        for (int nt = 0; nt < 8; nt++) {
            int col = n0 + wn*64 + nt*8 + t*2;
            int cp  = col >> 1;
            float bv0 = bias[col], bv1 = bias[col+1];
            float v00 = acc[mt][nt][0] + bv0, v01 = acc[mt][nt][1] + bv1;
            float v10 = acc[mt][nt][2] + bv0, v11 = acc[mt][nt][3] + bv1;
            if (op == 0) {
                g_qph[row0*128 + cp] = pkh(v00*qscale, v01*qscale);
                g_qph[row1*128 + cp] = pkh(v10*qscale, v11*qscale);
            } else if (op == 1) {
                g_kph[row0*128 + cp] = pkh(v00, v01);
                g_kph[row1*128 + cp] = pkh(v10, v11);
            } else if (op == 2) {
                g_vph[row0*128 + cp] = pkh(v00, v01);
                g_vph[row1*128 + cp] = pkh(v10, v11);
            } else if (op == 3 || op == 5) {
                float* dst = (op == 3) ? g_gate0 : g_mlp;
                v00 = 1.f/(1.f + __expf(-v00)); v01 = 1.f/(1.f + __expf(-v01));
                v10 = 1.f/(1.f + __expf(-v10)); v11 = 1.f/(1.f + __expf(-v11));
                *(float2*)&dst[(size_t)row0*EE + col] = make_float2(v00, v01);
                *(float2*)&dst[(size_t)row1*EE + col] = make_float2(v10, v11);
            } else {  // op 4
                size_t i0 = (size_t)row0*EE + col, i1 = (size_t)row1*EE + col;
                float2 ga0 = *(const float2*)&g_gate0[i0];
                float2 ga1 = *(const float2*)&g_gate0[i1];
                float2 mx0 = *(const float2*)&Matrix[i0];
                float2 mx1 = *(const float2*)&Matrix[i1];
                v00 = ga0.x*v00 + mx0.x;  v01 = ga0.y*v01 + mx0.y;
                v10 = ga1.x*v10 + mx1.x;  v11 = ga1.y*v11 + mx1.y;
                *(float2*)&g_gate1[i0] = make_float2(v00, v01);
                *(float2*)&g_gate1[i1] = make_float2(v10, v11);
                g_g1h[row0*128 + cp] = pkh(v00, v01);
                g_g1h[row1*128 + cp] = pkh(v10, v11);
            }
        }
    }
}

// ---------------- fp16 flash attention: h2exp2 softmax + ones-mma sums --------
__global__ __launch_bounds__(256) void attn_h()
{
    __shared__ __align__(16) unsigned sK[2][64*GP];
    __shared__ __align__(16) unsigned sV[2][64*GP];

    int tid = threadIdx.x, lane = tid & 31, wq = tid >> 5;
    int g = lane >> 2, t = lane & 3;
    int bh = blockIdx.x, b = bh >> 3, hd = bh & 7;
    int q0 = blockIdx.y * 128;

    int r0 = q0 + wq*16 + g;
    int qrow0 = b*SS + r0, qrow1 = qrow0 + 8;

    unsigned sK_u = (unsigned)__cvta_generic_to_shared(sK);
    unsigned sV_u = (unsigned)__cvta_generic_to_shared(sV);
    const unsigned KBUF = 64*GP*4;
    int l8 = lane & 7, qd = lane >> 3;
    unsigned kFrag = sK_u + (((qd>>1)*8 + l8)*GP + (qd&1)*4)*4;
    unsigned vFrag = sV_u + (((qd&1)*8 + l8)*GP)*4 + (qd>>1)*16;

    unsigned qhf[2][4];
    #pragma unroll
    for (int kk = 0; kk < 2; kk++) {
        int b0 = qrow0*128 + hd*16 + kk*8 + t;
        int b1 = qrow1*128 + hd*16 + kk*8 + t;
        qhf[kk][0] = g_qph[b0]; qhf[kk][1] = g_qph[b1];
        qhf[kk][2] = g_qph[b0+4]; qhf[kk][3] = g_qph[b1+4];
    }

    float O[4][4];
    #pragma unroll
    for (int dn = 0; dn < 4; dn++)
        #pragma unroll
        for (int i = 0; i < 4; i++) O[dn][i] = 0.f;
    float m0s = -1e30f, m1s = -1e30f, l0s = 0.f, l1s = 0.f;

    int ldr = tid >> 2, ldf = tid & 3;
    unsigned kDst = sK_u + (ldr*GP + ldf*4)*4;
    unsigned vDst = sV_u + (ldr*GP + ldf*4)*4;

    cpa16(kDst, &g_kph[(size_t)(b*SS + ldr)*128 + hd*16 + ldf*4]);
    cpa16(vDst, &g_vph[(size_t)(b*SS + ldr)*128 + hd*16 + ldf*4]);
    cpa_commit();

    const unsigned ONE2 = 0x3C003C00u;   // half2(1.0, 1.0)

    #pragma unroll 1
    for (int kt = 0; kt < 16; kt++) {
        int k0 = kt*64;
        if (kt < 15) {
            int bsel = (kt+1) & 1;
            cpa16(kDst + bsel*KBUF, &g_kph[(size_t)(b*SS + k0+64 + ldr)*128 + hd*16 + ldf*4]);
            cpa16(vDst + bsel*KBUF, &g_vph[(size_t)(b*SS + k0+64 + ldr)*128 + hd*16 + ldf*4]);
            cpa_commit();
            asm volatile("cp.async.wait_group 1;");
        } else {
            asm volatile("cp.async.wait_group 0;");
        }
        __syncthreads();
        int bsel = kt & 1;

        // scores (log2 domain)
        float S_[8][4];
        #pragma unroll
        for (int nt = 0; nt < 8; nt++)
            #pragma unroll
            for (int i = 0; i < 4; i++) S_[nt][i] = 0.f;
        #pragma unroll
        for (int kk = 0; kk < 2; kk++) {
            #pragma unroll
            for (int p = 0; p < 4; p++) {
                unsigned k0r, k1r, k2r, k3r;
                ldsm4(k0r, k1r, k2r, k3r, kFrag + bsel*KBUF + p*1280 + kk*32);
                mmah(S_[2*p  ], qhf[kk][0], qhf[kk][1], qhf[kk][2], qhf[kk][3], k0r, k1r);
                mmah(S_[2*p+1], qhf[kk][0], qhf[kk][1], qhf[kk][2], qhf[kk][3], k2r, k3r);
            }
        }
        #pragma unroll
        for (int nt = 0; nt < 8; nt++) {
            int pc = (k0 >> 1) + nt*4 + t;
            unsigned u0 = g_rbh[r0*512 + pc];
            unsigned u1 = g_rbh[(r0+8)*512 + pc];
            float2 b0v = __half22float2(*reinterpret_cast<__half2*>(&u0));
            float2 b1v = __half22float2(*reinterpret_cast<__half2*>(&u1));
            S_[nt][0] += b0v.x; S_[nt][1] += b0v.y;
            S_[nt][2] += b1v.x; S_[nt][3] += b1v.y;
        }

        // online softmax: max in fp32, exp2 in f16x2
        float tm0 = -1e30f, tm1 = -1e30f;
        #pragma unroll
        for (int nt = 0; nt < 8; nt++) {
            tm0 = fmaxf(tm0, fmaxf(S_[nt][0], S_[nt][1]));
            tm1 = fmaxf(tm1, fmaxf(S_[nt][2], S_[nt][3]));
        }
        tm0 = fmaxf(tm0, __shfl_xor_sync(0xffffffffu, tm0, 1));
        tm0 = fmaxf(tm0, __shfl_xor_sync(0xffffffffu, tm0, 2));
        tm1 = fmaxf(tm1, __shfl_xor_sync(0xffffffffu, tm1, 1));
        tm1 = fmaxf(tm1, __shfl_xor_sync(0xffffffffu, tm1, 2));
        float nm0 = fmaxf(m0s, tm0), nm1 = fmaxf(m1s, tm1);
        float sc0 = ex2(m0s - nm0), sc1 = ex2(m1s - nm1);

        unsigned pf[8][2];
        #pragma unroll
        for (int nt = 0; nt < 8; nt++) {
            __half2 d0 = __floats2half2_rn(S_[nt][0] - nm0, S_[nt][1] - nm0);
            __half2 d1 = __floats2half2_rn(S_[nt][2] - nm1, S_[nt][3] - nm1);
            __half2 p0 = h2exp2(d0);
            __half2 p1 = h2exp2(d1);
            pf[nt][0] = *reinterpret_cast<unsigned*>(&p0);
            pf[nt][1] = *reinterpret_cast<unsigned*>(&p1);
        }

        // row sums via ones-mma (replicated across quad lanes, fp32 exact)
        float rsA[4] = {0.f, 0.f, 0.f, 0.f};
        #pragma unroll
        for (int kk = 0; kk < 4; kk++)
            mmah(rsA, pf[2*kk][0], pf[2*kk][1], pf[2*kk+1][0], pf[2*kk+1][1], ONE2, ONE2);
        l0s = l0s*sc0 + rsA[0];
        l1s = l1s*sc1 + rsA[2];
        m0s = nm0;  m1s = nm1;
        #pragma unroll
        for (int dn = 0; dn < 4; dn++) {
            O[dn][0] *= sc0; O[dn][1] *= sc0;
            O[dn][2] *= sc1; O[dn][3] *= sc1;
        }

        #pragma unroll
        for (int kk = 0; kk < 4; kk++) {
            unsigned a0 = pf[2*kk][0], a1 = pf[2*kk][1];
            unsigned a2 = pf[2*kk+1][0], a3 = pf[2*kk+1][1];
            #pragma unroll
            for (int p = 0; p < 2; p++) {
                unsigned v0, v1, v2, v3;
                ldsm4t(v0, v1, v2, v3, vFrag + bsel*KBUF + kk*1280 + p*32);
                mmah(O[2*p  ], a0, a1, a2, a3, v0, v1);
                mmah(O[2*p+1], a0, a1, a2, a3, v2, v3);
            }
        }
        __syncthreads();
    }

    float il0 = 1.f/l0s, il1 = 1.f/l1s;
    #pragma unroll
    for (int dn = 0; dn < 4; dn++) {
        int cp = hd*16 + dn*4 + t;
        g_oph[qrow0*128 + cp] = pkh(O[dn][0]*il0, O[dn][1]*il0);
        g_oph[qrow1*128 + cp] = pkh(O[dn][2]*il1, O[dn][3]*il1);
    }
}

// ---------------- launch ------------------------------------------------------
extern "C" void kernel_launch(void* const* d_in, const int* in_sizes, int n_in,
                              void* d_out, int out_size)
{
    const float* Matrix = (const float*)d_in[0];
    const float* ln_g   = (const float*)d_in[1];
    const float* ln_b   = (const float*)d_in[2];
    const float* Wq     = (const float*)d_in[3];
    const float* bq     = (const float*)d_in[4];
    const float* Wk     = (const float*)d_in[5];
    const float* bk     = (const float*)d_in[6];
    const float* Wv     = (const float*)d_in[7];
    const float* bv     = (const float*)d_in[8];
    const float* Wo     = (const float*)d_in[9];
    const float* bo     = (const float*)d_in[10];
    const float* rel    = (const float*)d_in[11];
    const float* gW     = (const float*)d_in[12];
    const float* gb     = (const float*)d_in[13];
    const float* mW     = (const float*)d_in[14];
    const float* mb     = (const float*)d_in[15];
    float* out = (float*)d_out;

    static bool attr_set = false;
    if (!attr_set) {
        cudaFuncSetAttribute(gemm_h, cudaFuncAttributeMaxDynamicSharedMemorySize, 6*SA_U*4);
        attr_set = true;
    }

    prep<<<3168, 256>>>(Matrix, ln_g, ln_b, Wq, Wk, Wv, gW, Wo, mW, rel);

    gemm_h<<<dim3(2,128,4), 256, 4*SA_U*4>>>(bq, bk, bv, gb, bo, mb, Matrix, 0);
    attn_h<<<dim3(BB*HH, SS/128), 256>>>();
    gemm_h<<<dim3(2,128,1), 256, 6*SA_U*4>>>(bq, bk, bv, gb, bo, mb, Matrix, 4);
    gemm_h<<<dim3(2,128,1), 256, 6*SA_U*4>>>(bq, bk, bv, gb, bo, mb, Matrix, 5);

    final_kernel<<<MROWS/8, 256>>>(ln_g, ln_b, out);
}

// round 9
// speedup vs baseline: 1.1571x; 1.0666x over previous
#include <cuda_runtime.h>
#include <cuda_fp16.h>
#include <math.h>

#define BB 16
#define SS 1024
#define EE 256
#define HH 8
#define DHD 32
#define MROWS (BB*SS)   // 16384
#define GP 20           // smem pitch (uints); rows 80B apart, 16B aligned, LDSM conflict-free

// ---------------- scratch ----------------------------------------------------
__device__ unsigned g_wt[6][2][256*128];     // weight planes [n][kpair] hi/lo
__device__ unsigned g_rbh[SS*512];           // rel_bias * log2e, fp16 pairs
__device__ unsigned g_lnh[MROWS*128];
__device__ unsigned g_mth[MROWS*128];
__device__ unsigned g_qph[MROWS*128];        // pre-scaled by log2e/sqrt(DH)
__device__ unsigned g_kph[MROWS*128];
__device__ unsigned g_vph[MROWS*128];
__device__ unsigned g_oph[MROWS*128];
__device__ unsigned g_g1h[MROWS*128];
__device__ float g_gate0[MROWS*EE], g_gate1[MROWS*EE], g_mlp[MROWS*EE];

// ---------------- helpers -----------------------------------------------------
__device__ __forceinline__ unsigned pkh(float a, float b) {
    __half2 t = __floats2half2_rn(a, b);
    return *reinterpret_cast<unsigned*>(&t);
}
__device__ __forceinline__ void split_pack(float a, float b, unsigned &hi, unsigned &lo) {
    __half ah = __float2half_rn(a);
    __half bh = __float2half_rn(b);
    float ar = a - __half2float(ah);
    float br = b - __half2float(bh);
    __half2 H = __halves2half2(ah, bh);
    __half2 L = __floats2half2_rn(ar, br);
    hi = *reinterpret_cast<unsigned*>(&H);
    lo = *reinterpret_cast<unsigned*>(&L);
}
__device__ __forceinline__ void mmah(float* c,
    unsigned a0, unsigned a1, unsigned a2, unsigned a3,
    unsigned b0, unsigned b1)
{
    asm volatile(
        "mma.sync.aligned.m16n8k16.row.col.f32.f16.f16.f32 "
        "{%0,%1,%2,%3},{%4,%5,%6,%7},{%8,%9},{%0,%1,%2,%3};"
        : "+f"(c[0]), "+f"(c[1]), "+f"(c[2]), "+f"(c[3])
        : "r"(a0), "r"(a1), "r"(a2), "r"(a3), "r"(b0), "r"(b1));
}
__device__ __forceinline__ void ldsm4(unsigned &r0, unsigned &r1, unsigned &r2, unsigned &r3, unsigned addr) {
    asm volatile("ldmatrix.sync.aligned.m8n8.x4.shared.b16 {%0,%1,%2,%3}, [%4];"
        : "=r"(r0), "=r"(r1), "=r"(r2), "=r"(r3) : "r"(addr));
}
__device__ __forceinline__ void ldsm4t(unsigned &r0, unsigned &r1, unsigned &r2, unsigned &r3, unsigned addr) {
    asm volatile("ldmatrix.sync.aligned.m8n8.x4.trans.shared.b16 {%0,%1,%2,%3}, [%4];"
        : "=r"(r0), "=r"(r1), "=r"(r2), "=r"(r3) : "r"(addr));
}
__device__ __forceinline__ void cpa16(unsigned dst, const void* src) {
    asm volatile("cp.async.cg.shared.global [%0], [%1], 16;" :: "r"(dst), "l"(src));
}
__device__ __forceinline__ void cpa_commit() {
    asm volatile("cp.async.commit_group;");
}
__device__ __forceinline__ float ex2(float x) {
    float r; asm("ex2.approx.ftz.f32 %0, %1;" : "=f"(r) : "f"(x)); return r;
}
__device__ __forceinline__ float wsum(float v) {
    #pragma unroll
    for (int o = 16; o > 0; o >>= 1) v += __shfl_xor_sync(0xffffffffu, v, o);
    return v;
}

#define L2E 1.4426950408889634f

// ---------------- fused prep: weight split + bias split + LN -----------------
__global__ __launch_bounds__(256) void prep(
    const float* __restrict__ x, const float* __restrict__ lng,
    const float* __restrict__ lnb,
    const float* __restrict__ Wq, const float* __restrict__ Wk,
    const float* __restrict__ Wv, const float* __restrict__ gW,
    const float* __restrict__ Wo, const float* __restrict__ mW,
    const float* __restrict__ rel)
{
    __shared__ float s[64][65];
    int bx = blockIdx.x, tid = threadIdx.x;
    if (bx < 96) {
        int w = bx >> 4, rem = bx & 15;
        int k0 = (rem >> 2) * 64, n0 = (rem & 3) * 64;
        const float* W;
        switch (w) {
            case 0: W = Wq; break; case 1: W = Wk; break; case 2: W = Wv; break;
            case 3: W = gW; break; case 4: W = Wo; break; default: W = mW; break;
        }
        for (int i = tid; i < 4096; i += 256) {
            int r = i >> 6, c = i & 63;
            s[r][c] = W[(size_t)(k0 + r)*EE + n0 + c];
        }
        __syncthreads();
        for (int i = tid; i < 2048; i += 256) {
            int n = i >> 5, kp = i & 31;
            unsigned hi, lo;
            split_pack(s[2*kp][n], s[2*kp+1][n], hi, lo);
            int o = (n0 + n)*128 + k0/2 + kp;
            g_wt[w][0][o] = hi;
            g_wt[w][1][o] = lo;
        }
    } else if (bx < 1120) {
        int row = bx - 96;
        #pragma unroll
        for (int j = 0; j < 2; j++) {
            int i = tid + j*256;
            float2 v = *(const float2*)&rel[(size_t)row*SS + 2*i];
            g_rbh[row*512 + i] = pkh(v.x*L2E, v.y*L2E);
        }
    } else {
        int warp = tid >> 5, lane = tid & 31;
        int row = (bx - 1120)*8 + warp;
        const float* xr = x + (size_t)row*EE + lane*8;
        float4 a0 = *(const float4*)xr;
        float4 a1 = *(const float4*)(xr + 4);
        float xv[8] = {a0.x,a0.y,a0.z,a0.w,a1.x,a1.y,a1.z,a1.w};
        float sm = 0.f;
        #pragma unroll
        for (int i = 0; i < 8; i++) sm += xv[i];
        float mean = wsum(sm) * (1.f/EE);
        float vs = 0.f;
        #pragma unroll
        for (int i = 0; i < 8; i++) { float d = xv[i]-mean; vs += d*d; }
        float rstd = rsqrtf(wsum(vs)*(1.f/EE) + 1e-5f);
        float4 g0 = *(const float4*)(lng + lane*8);
        float4 g1 = *(const float4*)(lng + lane*8 + 4);
        float4 b0 = *(const float4*)(lnb + lane*8);
        float4 b1 = *(const float4*)(lnb + lane*8 + 4);
        float gg[8] = {g0.x,g0.y,g0.z,g0.w,g1.x,g1.y,g1.z,g1.w};
        float bb[8] = {b0.x,b0.y,b0.z,b0.w,b1.x,b1.y,b1.z,b1.w};
        float ln[8];
        #pragma unroll
        for (int i = 0; i < 8; i++) ln[i] = (xv[i]-mean)*rstd*gg[i] + bb[i];
        uint4 u, um;
        u.x = pkh(ln[0],ln[1]); u.y = pkh(ln[2],ln[3]);
        u.z = pkh(ln[4],ln[5]); u.w = pkh(ln[6],ln[7]);
        um.x = pkh(xv[0],xv[1]); um.y = pkh(xv[2],xv[3]);
        um.z = pkh(xv[4],xv[5]); um.w = pkh(xv[6],xv[7]);
        *(uint4*)&g_lnh[row*128 + lane*4] = u;
        *(uint4*)&g_mth[row*128 + lane*4] = um;
    }
}

// ---------------- final: out = gate1 * LN(mlp) + gate1 ------------------------
__global__ __launch_bounds__(256) void final_kernel(
    const float* __restrict__ g, const float* __restrict__ b,
    float* __restrict__ out)
{
    int warp = threadIdx.x >> 5, lane = threadIdx.x & 31;
    int row = blockIdx.x*8 + warp;
    const float* mr = g_mlp + (size_t)row*EE + lane*8;
    float4 a0 = *(const float4*)mr;
    float4 a1 = *(const float4*)(mr + 4);
    float xv[8] = {a0.x,a0.y,a0.z,a0.w,a1.x,a1.y,a1.z,a1.w};
    float s = 0.f;
    #pragma unroll
    for (int i = 0; i < 8; i++) s += xv[i];
    float mean = wsum(s) * (1.f/EE);
    float vs = 0.f;
    #pragma unroll
    for (int i = 0; i < 8; i++) { float d = xv[i]-mean; vs += d*d; }
    float rstd = rsqrtf(wsum(vs)*(1.f/EE) + 1e-5f);
    float4 g0 = *(const float4*)(g + lane*8);
    float4 g1v = *(const float4*)(g + lane*8 + 4);
    float4 b0 = *(const float4*)(b + lane*8);
    float4 b1 = *(const float4*)(b + lane*8 + 4);
    float gg[8] = {g0.x,g0.y,g0.z,g0.w,g1v.x,g1v.y,g1v.z,g1v.w};
    float bb[8] = {b0.x,b0.y,b0.z,b0.w,b1.x,b1.y,b1.z,b1.w};
    const float* gr = g_gate1 + (size_t)row*EE + lane*8;
    float4 q0 = *(const float4*)gr;
    float4 q1 = *(const float4*)(gr + 4);
    float gv[8] = {q0.x,q0.y,q0.z,q0.w,q1.x,q1.y,q1.z,q1.w};
    float o[8];
    #pragma unroll
    for (int i = 0; i < 8; i++) {
        float lnm = (xv[i]-mean)*rstd*gg[i] + bb[i];
        o[i] = gv[i]*lnm + gv[i];
    }
    float* orow = out + (size_t)row*EE + lane*8;
    *(float4*)orow       = make_float4(o[0],o[1],o[2],o[3]);
    *(float4*)(orow + 4) = make_float4(o[4],o[5],o[6],o[7]);
}

// ---------------- templated fp16 GEMM: MT x 128 tile, 3-stage cp.async --------
// MT=128,P2=0: ops 0..3 (1-pass). MT=64,P2=1: ops 4,5 (2-pass).
template<int MT, bool P2>
__global__ __launch_bounds__(256, 2) void gemm_t(
    const float* __restrict__ bq, const float* __restrict__ bk,
    const float* __restrict__ bv, const float* __restrict__ gb,
    const float* __restrict__ bo, const float* __restrict__ mb,
    const float* __restrict__ Matrix, int op_base)
{
    extern __shared__ __align__(16) unsigned smem[];
    constexpr int WM = MT/32;          // warps along M
    constexpr int WN = 8/WM;           // warps along N
    constexpr int NPW = 128/WN;        // N per warp
    constexpr int PR = NPW/16;         // ldsm groups along N
    constexpr int AJ = MT*4/256;       // uint4 A loads per thread per chunk
    constexpr unsigned A_STG = MT*GP*4;    // bytes per A stage
    constexpr unsigned B_STG = 128*GP*4;   // bytes per B stage
    constexpr unsigned A_OFF = 0;
    constexpr unsigned BH_OFF = 3*A_STG;
    constexpr unsigned BL_OFF = BH_OFF + 3*B_STG;

    int op = op_base + blockIdx.z;
    const unsigned* Ah;
    const float* bias;
    switch (op) {
        case 0: Ah = g_lnh; bias = bq; break;
        case 1: Ah = g_lnh; bias = bk; break;
        case 2: Ah = g_lnh; bias = bv; break;
        case 3: Ah = g_mth; bias = gb; break;
        case 4: Ah = g_oph; bias = bo; break;
        default: Ah = g_g1h; bias = mb; break;
    }
    const unsigned* Wh = g_wt[op][0];
    const unsigned* Wl = g_wt[op][1];

    int tid = threadIdx.x, lane = tid & 31, warp = tid >> 5;
    int wm = warp / WN, wn = warp % WN;
    int g = lane >> 2, t = lane & 3;
    int m0 = blockIdx.y * MT, n0 = blockIdx.x * 128;

    unsigned s_u = (unsigned)__cvta_generic_to_shared(smem);
    int l16 = lane & 15, secA = lane >> 4;
    unsigned aFrag = s_u + A_OFF + (((wm*32 + l16)*GP) + secA*4)*4;
    int l8 = lane & 7, qd = lane >> 3;
    unsigned bFrag = (((wn*NPW + (qd>>1)*8 + l8)*GP) + (qd&1)*4)*4;

    int arow[2], af4[2], brow[2], bf4[2];
    #pragma unroll
    for (int j = 0; j < 2; j++) {
        int idx = tid + j*256;
        brow[j] = idx >> 2; bf4[j] = idx & 3;
        if (j < AJ) { arow[j] = idx >> 2; af4[j] = idx & 3; }
    }

    float acc[2][2*PR][4];
    #pragma unroll
    for (int mt = 0; mt < 2; mt++)
        #pragma unroll
        for (int nt = 0; nt < 2*PR; nt++)
            #pragma unroll
            for (int i = 0; i < 4; i++) acc[mt][nt][i] = 0.f;

    auto issue = [&](int ch, int bsel) {
        int cc = ch*16;
        #pragma unroll
        for (int j = 0; j < AJ; j++)
            cpa16(s_u + A_OFF + bsel*A_STG + (arow[j]*GP + af4[j]*4)*4,
                  &Ah[(size_t)(m0 + arow[j])*128 + cc + af4[j]*4]);
        #pragma unroll
        for (int j = 0; j < 2; j++)
            cpa16(s_u + BH_OFF + bsel*B_STG + (brow[j]*GP + bf4[j]*4)*4,
                  &Wh[(size_t)(n0 + brow[j])*128 + cc + bf4[j]*4]);
        if (P2) {
            #pragma unroll
            for (int j = 0; j < 2; j++)
                cpa16(s_u + BL_OFF + bsel*B_STG + (brow[j]*GP + bf4[j]*4)*4,
                      &Wl[(size_t)(n0 + brow[j])*128 + cc + bf4[j]*4]);
        }
        cpa_commit();
    };

    issue(0, 0);
    issue(1, 1);

    #pragma unroll 1
    for (int c = 0; c < 8; c++) {
        if (c < 6) {
            issue(c+2, (c+2) % 3);
            asm volatile("cp.async.wait_group 2;");
        } else if (c == 6) {
            asm volatile("cp.async.wait_group 1;");
        } else {
            asm volatile("cp.async.wait_group 0;");
        }
        __syncthreads();

        int bsel = c % 3;
        #pragma unroll
        for (int kk = 0; kk < 2; kk++) {
            unsigned a[2][4];
            #pragma unroll
            for (int mt = 0; mt < 2; mt++)
                ldsm4(a[mt][0], a[mt][1], a[mt][2], a[mt][3],
                      aFrag + bsel*A_STG + mt*(16*GP*4) + kk*32);
            #pragma unroll
            for (int pr = 0; pr < PR; pr++) {
                unsigned b0, b1, b2, b3;
                ldsm4(b0, b1, b2, b3,
                      s_u + BH_OFF + bsel*B_STG + bFrag + pr*(16*GP*4) + kk*32);
                #pragma unroll
                for (int mt = 0; mt < 2; mt++) {
                    mmah(acc[mt][2*pr  ], a[mt][0], a[mt][1], a[mt][2], a[mt][3], b0, b1);
                    mmah(acc[mt][2*pr+1], a[mt][0], a[mt][1], a[mt][2], a[mt][3], b2, b3);
                }
                if (P2) {
                    unsigned c0, c1, c2, c3;
                    ldsm4(c0, c1, c2, c3,
                          s_u + BL_OFF + bsel*B_STG + bFrag + pr*(16*GP*4) + kk*32);
                    #pragma unroll
                    for (int mt = 0; mt < 2; mt++) {
                        mmah(acc[mt][2*pr  ], a[mt][0], a[mt][1], a[mt][2], a[mt][3], c0, c1);
                        mmah(acc[mt][2*pr+1], a[mt][0], a[mt][1], a[mt][2], a[mt][3], c2, c3);
                    }
                }
            }
        }
        __syncthreads();
    }

    const float qscale = 0.17677669529663687f * L2E;
    #pragma unroll
    for (int mt = 0; mt < 2; mt++) {
        int row0 = m0 + wm*32 + mt*16 + g;
        int row1 = row0 + 8;
        #pragma unroll
        for (int nt = 0; nt < 2*PR; nt++) {
            int col = n0 + wn*NPW + nt*8 + t*2;
            int cp  = col >> 1;
            float bv0 = bias[col], bv1 = bias[col+1];
            float v00 = acc[mt][nt][0] + bv0, v01 = acc[mt][nt][1] + bv1;
            float v10 = acc[mt][nt][2] + bv0, v11 = acc[mt][nt][3] + bv1;
            if (op == 0) {
                g_qph[row0*128 + cp] = pkh(v00*qscale, v01*qscale);
                g_qph[row1*128 + cp] = pkh(v10*qscale, v11*qscale);
            } else if (op == 1) {
                g_kph[row0*128 + cp] = pkh(v00, v01);
                g_kph[row1*128 + cp] = pkh(v10, v11);
            } else if (op == 2) {
                g_vph[row0*128 + cp] = pkh(v00, v01);
                g_vph[row1*128 + cp] = pkh(v10, v11);
            } else if (op == 3 || op == 5) {
                float* dst = (op == 3) ? g_gate0 : g_mlp;
                v00 = 1.f/(1.f + __expf(-v00)); v01 = 1.f/(1.f + __expf(-v01));
                v10 = 1.f/(1.f + __expf(-v10)); v11 = 1.f/(1.f + __expf(-v11));
                *(float2*)&dst[(size_t)row0*EE + col] = make_float2(v00, v01);
                *(float2*)&dst[(size_t)row1*EE + col] = make_float2(v10, v11);
            } else {  // op 4
                size_t i0 = (size_t)row0*EE + col, i1 = (size_t)row1*EE + col;
                float2 ga0 = *(const float2*)&g_gate0[i0];
                float2 ga1 = *(const float2*)&g_gate0[i1];
                float2 mx0 = *(const float2*)&Matrix[i0];
                float2 mx1 = *(const float2*)&Matrix[i1];
                v00 = ga0.x*v00 + mx0.x;  v01 = ga0.y*v01 + mx0.y;
                v10 = ga1.x*v10 + mx1.x;  v11 = ga1.y*v11 + mx1.y;
                *(float2*)&g_gate1[i0] = make_float2(v00, v01);
                *(float2*)&g_gate1[i1] = make_float2(v10, v11);
                g_g1h[row0*128 + cp] = pkh(v00, v01);
                g_g1h[row1*128 + cp] = pkh(v10, v11);
            }
        }
    }
}

// ---------------- fp16 flash attention: 3-stage cp.async ----------------------
__global__ __launch_bounds__(256) void attn_h()
{
    __shared__ __align__(16) unsigned sK[3][64*GP];
    __shared__ __align__(16) unsigned sV[3][64*GP];

    int tid = threadIdx.x, lane = tid & 31, wq = tid >> 5;
    int g = lane >> 2, t = lane & 3;
    int bh = blockIdx.x, b = bh >> 3, hd = bh & 7;
    int q0 = blockIdx.y * 128;

    int r0 = q0 + wq*16 + g;
    int qrow0 = b*SS + r0, qrow1 = qrow0 + 8;

    unsigned sK_u = (unsigned)__cvta_generic_to_shared(sK);
    unsigned sV_u = (unsigned)__cvta_generic_to_shared(sV);
    const unsigned KBUF = 64*GP*4;     // 5120 B per stage
    int l8 = lane & 7, qd = lane >> 3;
    unsigned kFrag = sK_u + (((qd>>1)*8 + l8)*GP + (qd&1)*4)*4;
    unsigned vFrag = sV_u + (((qd&1)*8 + l8)*GP)*4 + (qd>>1)*16;

    unsigned qhf[2][4];
    #pragma unroll
    for (int kk = 0; kk < 2; kk++) {
        int b0 = qrow0*128 + hd*16 + kk*8 + t;
        int b1 = qrow1*128 + hd*16 + kk*8 + t;
        qhf[kk][0] = g_qph[b0]; qhf[kk][1] = g_qph[b1];
        qhf[kk][2] = g_qph[b0+4]; qhf[kk][3] = g_qph[b1+4];
    }

    float O[4][4];
    #pragma unroll
    for (int dn = 0; dn < 4; dn++)
        #pragma unroll
        for (int i = 0; i < 4; i++) O[dn][i] = 0.f;
    float m0s = -1e30f, m1s = -1e30f, l0s = 0.f, l1s = 0.f;

    int ldr = tid >> 2, ldf = tid & 3;
    unsigned kDst = sK_u + (ldr*GP + ldf*4)*4;
    unsigned vDst = sV_u + (ldr*GP + ldf*4)*4;

    auto issue = [&](int kt, int bsel) {
        cpa16(kDst + bsel*KBUF, &g_kph[(size_t)(b*SS + kt*64 + ldr)*128 + hd*16 + ldf*4]);
        cpa16(vDst + bsel*KBUF, &g_vph[(size_t)(b*SS + kt*64 + ldr)*128 + hd*16 + ldf*4]);
        cpa_commit();
    };
    issue(0, 0);
    issue(1, 1);

    const unsigned ONE2 = 0x3C003C00u;   // half2(1.0, 1.0)

    #pragma unroll 1
    for (int kt = 0; kt < 16; kt++) {
        int k0 = kt*64;
        if (kt < 14) {
            issue(kt+2, (kt+2) % 3);
            asm volatile("cp.async.wait_group 2;");
        } else if (kt == 14) {
            asm volatile("cp.async.wait_group 1;");
        } else {
            asm volatile("cp.async.wait_group 0;");
        }
        __syncthreads();
        int bsel = kt % 3;

        // scores (log2 domain)
        float S_[8][4];
        #pragma unroll
        for (int nt = 0; nt < 8; nt++)
            #pragma unroll
            for (int i = 0; i < 4; i++) S_[nt][i] = 0.f;
        #pragma unroll
        for (int kk = 0; kk < 2; kk++) {
            #pragma unroll
            for (int p = 0; p < 4; p++) {
                unsigned k0r, k1r, k2r, k3r;
                ldsm4(k0r, k1r, k2r, k3r, kFrag + bsel*KBUF + p*1280 + kk*32);
                mmah(S_[2*p  ], qhf[kk][0], qhf[kk][1], qhf[kk][2], qhf[kk][3], k0r, k1r);
                mmah(S_[2*p+1], qhf[kk][0], qhf[kk][1], qhf[kk][2], qhf[kk][3], k2r, k3r);
            }
        }
        #pragma unroll
        for (int nt = 0; nt < 8; nt++) {
            int pc = (k0 >> 1) + nt*4 + t;
            unsigned u0 = g_rbh[r0*512 + pc];
            unsigned u1 = g_rbh[(r0+8)*512 + pc];
            float2 b0v = __half22float2(*reinterpret_cast<__half2*>(&u0));
            float2 b1v = __half22float2(*reinterpret_cast<__half2*>(&u1));
            S_[nt][0] += b0v.x; S_[nt][1] += b0v.y;
            S_[nt][2] += b1v.x; S_[nt][3] += b1v.y;
        }

        float tm0 = -1e30f, tm1 = -1e30f;
        #pragma unroll
        for (int nt = 0; nt < 8; nt++) {
            tm0 = fmaxf(tm0, fmaxf(S_[nt][0], S_[nt][1]));
            tm1 = fmaxf(tm1, fmaxf(S_[nt][2], S_[nt][3]));
        }
        tm0 = fmaxf(tm0, __shfl_xor_sync(0xffffffffu, tm0, 1));
        tm0 = fmaxf(tm0, __shfl_xor_sync(0xffffffffu, tm0, 2));
        tm1 = fmaxf(tm1, __shfl_xor_sync(0xffffffffu, tm1, 1));
        tm1 = fmaxf(tm1, __shfl_xor_sync(0xffffffffu, tm1, 2));
        float nm0 = fmaxf(m0s, tm0), nm1 = fmaxf(m1s, tm1);
        float sc0 = ex2(m0s - nm0), sc1 = ex2(m1s - nm1);

        unsigned pf[8][2];
        #pragma unroll
        for (int nt = 0; nt < 8; nt++) {
            __half2 d0 = __floats2half2_rn(S_[nt][0] - nm0, S_[nt][1] - nm0);
            __half2 d1 = __floats2half2_rn(S_[nt][2] - nm1, S_[nt][3] - nm1);
            __half2 p0 = h2exp2(d0);
            __half2 p1 = h2exp2(d1);
            pf[nt][0] = *reinterpret_cast<unsigned*>(&p0);
            pf[nt][1] = *reinterpret_cast<unsigned*>(&p1);
        }

        float rsA[4] = {0.f, 0.f, 0.f, 0.f};
        #pragma unroll
        for (int kk = 0; kk < 4; kk++)
            mmah(rsA, pf[2*kk][0], pf[2*kk][1], pf[2*kk+1][0], pf[2*kk+1][1], ONE2, ONE2);
        l0s = l0s*sc0 + rsA[0];
        l1s = l1s*sc1 + rsA[2];
        m0s = nm0;  m1s = nm1;
        #pragma unroll
        for (int dn = 0; dn < 4; dn++) {
            O[dn][0] *= sc0; O[dn][1] *= sc0;
            O[dn][2] *= sc1; O[dn][3] *= sc1;
        }

        #pragma unroll
        for (int kk = 0; kk < 4; kk++) {
            unsigned a0 = pf[2*kk][0], a1 = pf[2*kk][1];
            unsigned a2 = pf[2*kk+1][0], a3 = pf[2*kk+1][1];
            #pragma unroll
            for (int p = 0; p < 2; p++) {
                unsigned v0, v1, v2, v3;
                ldsm4t(v0, v1, v2, v3, vFrag + bsel*KBUF + kk*1280 + p*32);
                mmah(O[2*p  ], a0, a1, a2, a3, v0, v1);
                mmah(O[2*p+1], a0, a1, a2, a3, v2, v3);
            }
        }
        __syncthreads();
    }

    float il0 = 1.f/l0s, il1 = 1.f/l1s;
    #pragma unroll
    for (int dn = 0; dn < 4; dn++) {
        int cp = hd*16 + dn*4 + t;
        g_oph[qrow0*128 + cp] = pkh(O[dn][0]*il0, O[dn][1]*il0);
        g_oph[qrow1*128 + cp] = pkh(O[dn][2]*il1, O[dn][3]*il1);
    }
}

// ---------------- launch ------------------------------------------------------
extern "C" void kernel_launch(void* const* d_in, const int* in_sizes, int n_in,
                              void* d_out, int out_size)
{
    const float* Matrix = (const float*)d_in[0];
    const float* ln_g   = (const float*)d_in[1];
    const float* ln_b   = (const float*)d_in[2];
    const float* Wq     = (const float*)d_in[3];
    const float* bq     = (const float*)d_in[4];
    const float* Wk     = (const float*)d_in[5];
    const float* bk     = (const float*)d_in[6];
    const float* Wv     = (const float*)d_in[7];
    const float* bv     = (const float*)d_in[8];
    const float* Wo     = (const float*)d_in[9];
    const float* bo     = (const float*)d_in[10];
    const float* rel    = (const float*)d_in[11];
    const float* gW     = (const float*)d_in[12];
    const float* gb     = (const float*)d_in[13];
    const float* mW     = (const float*)d_in[14];
    const float* mb     = (const float*)d_in[15];
    float* out = (float*)d_out;

    // smem: <128,0>: 3*(128+128)*GP*4 = 61440 B ; <64,1>: 3*(64+2*128)*GP*4 = 76800 B
    const int SM1 = 3*(128*GP*4 + 128*GP*4);
    const int SM2 = 3*(64*GP*4 + 2*128*GP*4);
    static bool attr_set = false;
    if (!attr_set) {
        cudaFuncSetAttribute(gemm_t<128,false>, cudaFuncAttributeMaxDynamicSharedMemorySize, SM1);
        cudaFuncSetAttribute(gemm_t<64,true>,  cudaFuncAttributeMaxDynamicSharedMemorySize, SM2);
        attr_set = true;
    }

    prep<<<3168, 256>>>(Matrix, ln_g, ln_b, Wq, Wk, Wv, gW, Wo, mW, rel);

    gemm_t<128,false><<<dim3(2,128,4), 256, SM1>>>(bq, bk, bv, gb, bo, mb, Matrix, 0);
    attn_h<<<dim3(BB*HH, SS/128), 256>>>();
    gemm_t<64,true><<<dim3(2,256,1), 256, SM2>>>(bq, bk, bv, gb, bo, mb, Matrix, 4);
    gemm_t<64,true><<<dim3(2,256,1), 256, SM2>>>(bq, bk, bv, gb, bo, mb, Matrix, 5);

    final_kernel<<<MROWS/8, 256>>>(ln_g, ln_b, out);
}

// round 10
// speedup vs baseline: 1.2289x; 1.0620x over previous
#include <cuda_runtime.h>
#include <cuda_fp16.h>
#include <math.h>

#define BB 16
#define SS 1024
#define EE 256
#define HH 8
#define DHD 32
#define MROWS (BB*SS)   // 16384
#define GP 20           // smem pitch (uints); conflict-free for LDSM

// ---------------- scratch ----------------------------------------------------
__device__ unsigned g_wt[6][2][256*128];     // weight planes [n][kpair] hi/lo
__device__ unsigned g_rbh[SS*512];           // rel_bias * log2e, fp16 pairs
__device__ unsigned g_lnh[MROWS*128];
__device__ unsigned g_mth[MROWS*128];
__device__ unsigned g_qph[MROWS*128];        // pre-scaled by log2e/sqrt(DH)
__device__ unsigned g_kph[MROWS*128];
__device__ unsigned g_vph[MROWS*128];
__device__ unsigned g_oph[MROWS*128];
__device__ unsigned g_g0h[MROWS*128];        // gate0 fp16 pairs
__device__ unsigned g_g1h[MROWS*128];
__device__ float g_gate1[MROWS*EE];

// ---------------- helpers -----------------------------------------------------
__device__ __forceinline__ unsigned pkh(float a, float b) {
    __half2 t = __floats2half2_rn(a, b);
    return *reinterpret_cast<unsigned*>(&t);
}
__device__ __forceinline__ void split_pack(float a, float b, unsigned &hi, unsigned &lo) {
    __half ah = __float2half_rn(a);
    __half bh = __float2half_rn(b);
    float ar = a - __half2float(ah);
    float br = b - __half2float(bh);
    __half2 H = __halves2half2(ah, bh);
    __half2 L = __floats2half2_rn(ar, br);
    hi = *reinterpret_cast<unsigned*>(&H);
    lo = *reinterpret_cast<unsigned*>(&L);
}
__device__ __forceinline__ float2 up2(unsigned u) {
    return __half22float2(*reinterpret_cast<__half2*>(&u));
}
__device__ __forceinline__ void mmah(float* c,
    unsigned a0, unsigned a1, unsigned a2, unsigned a3,
    unsigned b0, unsigned b1)
{
    asm volatile(
        "mma.sync.aligned.m16n8k16.row.col.f32.f16.f16.f32 "
        "{%0,%1,%2,%3},{%4,%5,%6,%7},{%8,%9},{%0,%1,%2,%3};"
        : "+f"(c[0]), "+f"(c[1]), "+f"(c[2]), "+f"(c[3])
        : "r"(a0), "r"(a1), "r"(a2), "r"(a3), "r"(b0), "r"(b1));
}
__device__ __forceinline__ void ldsm4(unsigned &r0, unsigned &r1, unsigned &r2, unsigned &r3, unsigned addr) {
    asm volatile("ldmatrix.sync.aligned.m8n8.x4.shared.b16 {%0,%1,%2,%3}, [%4];"
        : "=r"(r0), "=r"(r1), "=r"(r2), "=r"(r3) : "r"(addr));
}
__device__ __forceinline__ void ldsm4t(unsigned &r0, unsigned &r1, unsigned &r2, unsigned &r3, unsigned addr) {
    asm volatile("ldmatrix.sync.aligned.m8n8.x4.trans.shared.b16 {%0,%1,%2,%3}, [%4];"
        : "=r"(r0), "=r"(r1), "=r"(r2), "=r"(r3) : "r"(addr));
}
__device__ __forceinline__ void cpa16(unsigned dst, const void* src) {
    asm volatile("cp.async.cg.shared.global [%0], [%1], 16;" :: "r"(dst), "l"(src));
}
__device__ __forceinline__ void cpa_commit() {
    asm volatile("cp.async.commit_group;");
}
__device__ __forceinline__ float ex2(float x) {
    float r; asm("ex2.approx.ftz.f32 %0, %1;" : "=f"(r) : "f"(x)); return r;
}
__device__ __forceinline__ float wsum(float v) {
    #pragma unroll
    for (int o = 16; o > 0; o >>= 1) v += __shfl_xor_sync(0xffffffffu, v, o);
    return v;
}

#define L2E 1.4426950408889634f

// ---------------- fused prep: weight split + bias split + LN -----------------
__global__ __launch_bounds__(256) void prep(
    const float* __restrict__ x, const float* __restrict__ lng,
    const float* __restrict__ lnb,
    const float* __restrict__ Wq, const float* __restrict__ Wk,
    const float* __restrict__ Wv, const float* __restrict__ gW,
    const float* __restrict__ Wo, const float* __restrict__ mW,
    const float* __restrict__ rel)
{
    __shared__ float s[64][65];
    int bx = blockIdx.x, tid = threadIdx.x;
    if (bx < 96) {
        int w = bx >> 4, rem = bx & 15;
        int k0 = (rem >> 2) * 64, n0 = (rem & 3) * 64;
        const float* W;
        switch (w) {
            case 0: W = Wq; break; case 1: W = Wk; break; case 2: W = Wv; break;
            case 3: W = gW; break; case 4: W = Wo; break; default: W = mW; break;
        }
        for (int i = tid; i < 4096; i += 256) {
            int r = i >> 6, c = i & 63;
            s[r][c] = W[(size_t)(k0 + r)*EE + n0 + c];
        }
        __syncthreads();
        for (int i = tid; i < 2048; i += 256) {
            int n = i >> 5, kp = i & 31;
            unsigned hi, lo;
            split_pack(s[2*kp][n], s[2*kp+1][n], hi, lo);
            int o = (n0 + n)*128 + k0/2 + kp;
            g_wt[w][0][o] = hi;
            if (w >= 4) g_wt[w][1][o] = lo;   // lo plane only used by ops 4/5
        }
    } else if (bx < 1120) {
        int row = bx - 96;
        #pragma unroll
        for (int j = 0; j < 2; j++) {
            int i = tid + j*256;
            float2 v = *(const float2*)&rel[(size_t)row*SS + 2*i];
            g_rbh[row*512 + i] = pkh(v.x*L2E, v.y*L2E);
        }
    } else {
        int warp = tid >> 5, lane = tid & 31;
        int row = (bx - 1120)*8 + warp;
        const float* xr = x + (size_t)row*EE + lane*8;
        float4 a0 = *(const float4*)xr;
        float4 a1 = *(const float4*)(xr + 4);
        float xv[8] = {a0.x,a0.y,a0.z,a0.w,a1.x,a1.y,a1.z,a1.w};
        float sm = 0.f;
        #pragma unroll
        for (int i = 0; i < 8; i++) sm += xv[i];
        float mean = wsum(sm) * (1.f/EE);
        float vs = 0.f;
        #pragma unroll
        for (int i = 0; i < 8; i++) { float d = xv[i]-mean; vs += d*d; }
        float rstd = rsqrtf(wsum(vs)*(1.f/EE) + 1e-5f);
        float4 g0 = *(const float4*)(lng + lane*8);
        float4 g1 = *(const float4*)(lng + lane*8 + 4);
        float4 b0 = *(const float4*)(lnb + lane*8);
        float4 b1 = *(const float4*)(lnb + lane*8 + 4);
        float gg[8] = {g0.x,g0.y,g0.z,g0.w,g1.x,g1.y,g1.z,g1.w};
        float bb[8] = {b0.x,b0.y,b0.z,b0.w,b1.x,b1.y,b1.z,b1.w};
        float ln[8];
        #pragma unroll
        for (int i = 0; i < 8; i++) ln[i] = (xv[i]-mean)*rstd*gg[i] + bb[i];
        uint4 u, um;
        u.x = pkh(ln[0],ln[1]); u.y = pkh(ln[2],ln[3]);
        u.z = pkh(ln[4],ln[5]); u.w = pkh(ln[6],ln[7]);
        um.x = pkh(xv[0],xv[1]); um.y = pkh(xv[2],xv[3]);
        um.z = pkh(xv[4],xv[5]); um.w = pkh(xv[6],xv[7]);
        *(uint4*)&g_lnh[row*128 + lane*4] = u;
        *(uint4*)&g_mth[row*128 + lane*4] = um;
    }
}

// ---------------- templated fp16 GEMM (ops 0..4), 3-stage cp.async ------------
template<int MT, bool P2>
__global__ __launch_bounds__(256, 2) void gemm_t(
    const float* __restrict__ bq, const float* __restrict__ bk,
    const float* __restrict__ bv, const float* __restrict__ gb,
    const float* __restrict__ bo, const float* __restrict__ Matrix, int op_base)
{
    extern __shared__ __align__(16) unsigned smem[];
    constexpr int WM = MT/32;
    constexpr int WN = 8/WM;
    constexpr int NPW = 128/WN;
    constexpr int PR = NPW/16;
    constexpr int AJ = MT*4/256;
    constexpr unsigned A_STG = MT*GP*4;
    constexpr unsigned B_STG = 128*GP*4;
    constexpr unsigned A_OFF = 0;
    constexpr unsigned BH_OFF = 3*A_STG;
    constexpr unsigned BL_OFF = BH_OFF + 3*B_STG;

    int op = op_base + blockIdx.z;
    const unsigned* Ah;
    const float* bias;
    switch (op) {
        case 0: Ah = g_lnh; bias = bq; break;
        case 1: Ah = g_lnh; bias = bk; break;
        case 2: Ah = g_lnh; bias = bv; break;
        case 3: Ah = g_mth; bias = gb; break;
        default: Ah = g_oph; bias = bo; break;
    }
    const unsigned* Wh = g_wt[op][0];
    const unsigned* Wl = g_wt[op][1];

    int tid = threadIdx.x, lane = tid & 31, warp = tid >> 5;
    int wm = warp / WN, wn = warp % WN;
    int g = lane >> 2, t = lane & 3;
    int m0 = blockIdx.y * MT, n0 = blockIdx.x * 128;

    unsigned s_u = (unsigned)__cvta_generic_to_shared(smem);
    int l16 = lane & 15, secA = lane >> 4;
    unsigned aFrag = s_u + A_OFF + (((wm*32 + l16)*GP) + secA*4)*4;
    int l8 = lane & 7, qd = lane >> 3;
    unsigned bFrag = (((wn*NPW + (qd>>1)*8 + l8)*GP) + (qd&1)*4)*4;

    int arow[2], af4[2], brow[2], bf4[2];
    #pragma unroll
    for (int j = 0; j < 2; j++) {
        int idx = tid + j*256;
        brow[j] = idx >> 2; bf4[j] = idx & 3;
        if (j < AJ) { arow[j] = idx >> 2; af4[j] = idx & 3; }
    }

    float acc[2][2*PR][4];
    #pragma unroll
    for (int mt = 0; mt < 2; mt++)
        #pragma unroll
        for (int nt = 0; nt < 2*PR; nt++)
            #pragma unroll
            for (int i = 0; i < 4; i++) acc[mt][nt][i] = 0.f;

    auto issue = [&](int ch, int bsel) {
        int cc = ch*16;
        #pragma unroll
        for (int j = 0; j < AJ; j++)
            cpa16(s_u + A_OFF + bsel*A_STG + (arow[j]*GP + af4[j]*4)*4,
                  &Ah[(size_t)(m0 + arow[j])*128 + cc + af4[j]*4]);
        #pragma unroll
        for (int j = 0; j < 2; j++)
            cpa16(s_u + BH_OFF + bsel*B_STG + (brow[j]*GP + bf4[j]*4)*4,
                  &Wh[(size_t)(n0 + brow[j])*128 + cc + bf4[j]*4]);
        if (P2) {
            #pragma unroll
            for (int j = 0; j < 2; j++)
                cpa16(s_u + BL_OFF + bsel*B_STG + (brow[j]*GP + bf4[j]*4)*4,
                      &Wl[(size_t)(n0 + brow[j])*128 + cc + bf4[j]*4]);
        }
        cpa_commit();
    };

    issue(0, 0);
    issue(1, 1);

    #pragma unroll 1
    for (int c = 0; c < 8; c++) {
        if (c < 6) {
            issue(c+2, (c+2) % 3);
            asm volatile("cp.async.wait_group 2;");
        } else if (c == 6) {
            asm volatile("cp.async.wait_group 1;");
        } else {
            asm volatile("cp.async.wait_group 0;");
        }
        __syncthreads();

        int bsel = c % 3;
        #pragma unroll
        for (int kk = 0; kk < 2; kk++) {
            unsigned a[2][4];
            #pragma unroll
            for (int mt = 0; mt < 2; mt++)
                ldsm4(a[mt][0], a[mt][1], a[mt][2], a[mt][3],
                      aFrag + bsel*A_STG + mt*(16*GP*4) + kk*32);
            #pragma unroll
            for (int pr = 0; pr < PR; pr++) {
                unsigned b0, b1, b2, b3;
                ldsm4(b0, b1, b2, b3,
                      s_u + BH_OFF + bsel*B_STG + bFrag + pr*(16*GP*4) + kk*32);
                #pragma unroll
                for (int mt = 0; mt < 2; mt++) {
                    mmah(acc[mt][2*pr  ], a[mt][0], a[mt][1], a[mt][2], a[mt][3], b0, b1);
                    mmah(acc[mt][2*pr+1], a[mt][0], a[mt][1], a[mt][2], a[mt][3], b2, b3);
                }
                if (P2) {
                    unsigned c0, c1, c2, c3;
                    ldsm4(c0, c1, c2, c3,
                          s_u + BL_OFF + bsel*B_STG + bFrag + pr*(16*GP*4) + kk*32);
                    #pragma unroll
                    for (int mt = 0; mt < 2; mt++) {
                        mmah(acc[mt][2*pr  ], a[mt][0], a[mt][1], a[mt][2], a[mt][3], c0, c1);
                        mmah(acc[mt][2*pr+1], a[mt][0], a[mt][1], a[mt][2], a[mt][3], c2, c3);
                    }
                }
            }
        }
        __syncthreads();
    }

    const float qscale = 0.17677669529663687f * L2E;
    #pragma unroll
    for (int mt = 0; mt < 2; mt++) {
        int row0 = m0 + wm*32 + mt*16 + g;
        int row1 = row0 + 8;
        #pragma unroll
        for (int nt = 0; nt < 2*PR; nt++) {
            int col = n0 + wn*NPW + nt*8 + t*2;
            int cp  = col >> 1;
            float bv0 = bias[col], bv1 = bias[col+1];
            float v00 = acc[mt][nt][0] + bv0, v01 = acc[mt][nt][1] + bv1;
            float v10 = acc[mt][nt][2] + bv0, v11 = acc[mt][nt][3] + bv1;
            if (op == 0) {
                g_qph[row0*128 + cp] = pkh(v00*qscale, v01*qscale);
                g_qph[row1*128 + cp] = pkh(v10*qscale, v11*qscale);
            } else if (op == 1) {
                g_kph[row0*128 + cp] = pkh(v00, v01);
                g_kph[row1*128 + cp] = pkh(v10, v11);
            } else if (op == 2) {
                g_vph[row0*128 + cp] = pkh(v00, v01);
                g_vph[row1*128 + cp] = pkh(v10, v11);
            } else if (op == 3) {
                v00 = 1.f/(1.f + __expf(-v00)); v01 = 1.f/(1.f + __expf(-v01));
                v10 = 1.f/(1.f + __expf(-v10)); v11 = 1.f/(1.f + __expf(-v11));
                g_g0h[row0*128 + cp] = pkh(v00, v01);
                g_g0h[row1*128 + cp] = pkh(v10, v11);
            } else {  // op 4: gate1 = gate0*rmha + Matrix
                size_t i0 = (size_t)row0*EE + col, i1 = (size_t)row1*EE + col;
                float2 ga0 = up2(g_g0h[row0*128 + cp]);
                float2 ga1 = up2(g_g0h[row1*128 + cp]);
                float2 mx0 = *(const float2*)&Matrix[i0];
                float2 mx1 = *(const float2*)&Matrix[i1];
                v00 = ga0.x*v00 + mx0.x;  v01 = ga0.y*v01 + mx0.y;
                v10 = ga1.x*v10 + mx1.x;  v11 = ga1.y*v11 + mx1.y;
                *(float2*)&g_gate1[i0] = make_float2(v00, v01);
                *(float2*)&g_gate1[i1] = make_float2(v10, v11);
                g_g1h[row0*128 + cp] = pkh(v00, v01);
                g_g1h[row1*128 + cp] = pkh(v10, v11);
            }
        }
    }
}

// ---------------- fused mW GEMM + sigmoid + LN + gated output -----------------
// block: 64 rows x 256 cols (full rows) -> in-block row LN. 2-stage cp.async.
// dyn smem: A[2]@0 (5120B ea), Bh[2]@10240 (20480B ea), Bl[2]@51200, red@92160
__global__ __launch_bounds__(256, 2) void gemm_mlp(
    const float* __restrict__ mb, const float* __restrict__ lng,
    const float* __restrict__ lnb, float* __restrict__ out)
{
    extern __shared__ __align__(16) unsigned smem[];
    constexpr unsigned A_STG = 64*GP*4;      // 5120
    constexpr unsigned B_STG = 256*GP*4;     // 20480
    constexpr unsigned A_OFF = 0;
    constexpr unsigned BH_OFF = 2*A_STG;     // 10240
    constexpr unsigned BL_OFF = BH_OFF + 2*B_STG;  // 51200
    const unsigned* Wh = g_wt[5][0];
    const unsigned* Wl = g_wt[5][1];

    int tid = threadIdx.x, lane = tid & 31, warp = tid >> 5;
    int wm = warp >> 2, wn = warp & 3;
    int g = lane >> 2, t = lane & 3;
    int m0 = blockIdx.x * 64;

    unsigned s_u = (unsigned)__cvta_generic_to_shared(smem);
    int l16 = lane & 15, secA = lane >> 4;
    unsigned aFrag = s_u + A_OFF + (((wm*32 + l16)*GP) + secA*4)*4;
    int l8 = lane & 7, qd = lane >> 3;
    unsigned bFrag = (((wn*64 + (qd>>1)*8 + l8)*GP) + (qd&1)*4)*4;

    int arow = tid >> 2, af4 = tid & 3;   // 64 rows x 4 uint4
    int brow[4], bf4[4];
    #pragma unroll
    for (int j = 0; j < 4; j++) { int idx = tid + j*256; brow[j] = idx >> 2; bf4[j] = idx & 3; }

    float acc[2][8][4];
    #pragma unroll
    for (int mt = 0; mt < 2; mt++)
        #pragma unroll
        for (int nt = 0; nt < 8; nt++)
            #pragma unroll
            for (int i = 0; i < 4; i++) acc[mt][nt][i] = 0.f;

    auto issue = [&](int ch, int bs) {
        int cc = ch*16;
        cpa16(s_u + A_OFF + bs*A_STG + (arow*GP + af4*4)*4,
              &g_g1h[(size_t)(m0 + arow)*128 + cc + af4*4]);
        #pragma unroll
        for (int j = 0; j < 4; j++) {
            cpa16(s_u + BH_OFF + bs*B_STG + (brow[j]*GP + bf4[j]*4)*4,
                  &Wh[(size_t)brow[j]*128 + cc + bf4[j]*4]);
            cpa16(s_u + BL_OFF + bs*B_STG + (brow[j]*GP + bf4[j]*4)*4,
                  &Wl[(size_t)brow[j]*128 + cc + bf4[j]*4]);
        }
        cpa_commit();
    };

    issue(0, 0);

    #pragma unroll 1
    for (int c = 0; c < 8; c++) {
        if (c < 7) {
            issue(c+1, (c+1) & 1);
            asm volatile("cp.async.wait_group 1;");
        } else {
            asm volatile("cp.async.wait_group 0;");
        }
        __syncthreads();

        int bs = c & 1;
        #pragma unroll
        for (int kk = 0; kk < 2; kk++) {
            unsigned a[2][4];
            #pragma unroll
            for (int mt = 0; mt < 2; mt++)
                ldsm4(a[mt][0], a[mt][1], a[mt][2], a[mt][3],
                      aFrag + bs*A_STG + mt*(16*GP*4) + kk*32);
            #pragma unroll
            for (int pr = 0; pr < 4; pr++) {
                unsigned b0, b1, b2, b3;
                ldsm4(b0, b1, b2, b3,
                      s_u + BH_OFF + bs*B_STG + bFrag + pr*(16*GP*4) + kk*32);
                #pragma unroll
                for (int mt = 0; mt < 2; mt++) {
                    mmah(acc[mt][2*pr  ], a[mt][0], a[mt][1], a[mt][2], a[mt][3], b0, b1);
                    mmah(acc[mt][2*pr+1], a[mt][0], a[mt][1], a[mt][2], a[mt][3], b2, b3);
                }
                unsigned c0, c1, c2, c3;
                ldsm4(c0, c1, c2, c3,
                      s_u + BL_OFF + bs*B_STG + bFrag + pr*(16*GP*4) + kk*32);
                #pragma unroll
                for (int mt = 0; mt < 2; mt++) {
                    mmah(acc[mt][2*pr  ], a[mt][0], a[mt][1], a[mt][2], a[mt][3], c0, c1);
                    mmah(acc[mt][2*pr+1], a[mt][0], a[mt][1], a[mt][2], a[mt][3], c2, c3);
                }
            }
        }
        __syncthreads();
    }

    // ---- epilogue: sigmoid + per-row LN (rows fully in block) + gated out ----
    float* sS = (float*)&smem[23040];   // [64][4]
    float* sQ = sS + 256;               // [64][4]

    float psum[2][2] = {{0,0},{0,0}}, psq[2][2] = {{0,0},{0,0}};
    #pragma unroll
    for (int mt = 0; mt < 2; mt++) {
        #pragma unroll
        for (int nt = 0; nt < 8; nt++) {
            int col = wn*64 + nt*8 + t*2;
            float bv0 = mb[col], bv1 = mb[col+1];
            float v00 = 1.f/(1.f + __expf(-(acc[mt][nt][0] + bv0)));
            float v01 = 1.f/(1.f + __expf(-(acc[mt][nt][1] + bv1)));
            float v10 = 1.f/(1.f + __expf(-(acc[mt][nt][2] + bv0)));
            float v11 = 1.f/(1.f + __expf(-(acc[mt][nt][3] + bv1)));
            acc[mt][nt][0] = v00; acc[mt][nt][1] = v01;
            acc[mt][nt][2] = v10; acc[mt][nt][3] = v11;
            psum[mt][0] += v00 + v01;  psq[mt][0] += v00*v00 + v01*v01;
            psum[mt][1] += v10 + v11;  psq[mt][1] += v10*v10 + v11*v11;
        }
    }
    // quad reduce over t (lanes in quad share rows)
    #pragma unroll
    for (int mt = 0; mt < 2; mt++)
        #pragma unroll
        for (int hf = 0; hf < 2; hf++) {
            float s = psum[mt][hf], q = psq[mt][hf];
            s += __shfl_xor_sync(0xffffffffu, s, 1);
            s += __shfl_xor_sync(0xffffffffu, s, 2);
            q += __shfl_xor_sync(0xffffffffu, q, 1);
            q += __shfl_xor_sync(0xffffffffu, q, 2);
            psum[mt][hf] = s; psq[mt][hf] = q;
        }
    if (t == 0) {
        #pragma unroll
        for (int mt = 0; mt < 2; mt++)
            #pragma unroll
            for (int hf = 0; hf < 2; hf++) {
                int r = wm*32 + mt*16 + g + hf*8;
                sS[r*4 + wn] = psum[mt][hf];
                sQ[r*4 + wn] = psq[mt][hf];
            }
    }
    __syncthreads();

    float mean[2][2], rstd[2][2];
    #pragma unroll
    for (int mt = 0; mt < 2; mt++)
        #pragma unroll
        for (int hf = 0; hf < 2; hf++) {
            int r = wm*32 + mt*16 + g + hf*8;
            float s = sS[r*4+0] + sS[r*4+1] + sS[r*4+2] + sS[r*4+3];
            float q = sQ[r*4+0] + sQ[r*4+1] + sQ[r*4+2] + sQ[r*4+3];
            float m = s * (1.f/EE);
            float v = q * (1.f/EE) - m*m;
            mean[mt][hf] = m;
            rstd[mt][hf] = rsqrtf(v + 1e-5f);
        }

    #pragma unroll
    for (int mt = 0; mt < 2; mt++) {
        int row0 = m0 + wm*32 + mt*16 + g;
        int row1 = row0 + 8;
        #pragma unroll
        for (int nt = 0; nt < 8; nt++) {
            int col = wn*64 + nt*8 + t*2;
            float2 gm = *(const float2*)&lng[col];
            float2 bt = *(const float2*)&lnb[col];
            size_t i0 = (size_t)row0*EE + col, i1 = (size_t)row1*EE + col;
            float2 g10 = *(const float2*)&g_gate1[i0];
            float2 g11 = *(const float2*)&g_gate1[i1];
            float ln00 = (acc[mt][nt][0] - mean[mt][0])*rstd[mt][0]*gm.x + bt.x;
            float ln01 = (acc[mt][nt][1] - mean[mt][0])*rstd[mt][0]*gm.y + bt.y;
            float ln10 = (acc[mt][nt][2] - mean[mt][1])*rstd[mt][1]*gm.x + bt.x;
            float ln11 = (acc[mt][nt][3] - mean[mt][1])*rstd[mt][1]*gm.y + bt.y;
            *(float2*)&out[i0] = make_float2(g10.x*(ln00+1.f), g10.y*(ln01+1.f));
            *(float2*)&out[i1] = make_float2(g11.x*(ln10+1.f), g11.y*(ln11+1.f));
        }
    }
}

// ---------------- head-paired fp16 flash attention ----------------------------
// grid (64, 8): block = (b, head-pair), 128 q rows, kv tile 64, 2 heads/block.
// Bias tile loaded once into regs, reused for both heads.
#define AP 36   // smem pitch (uints) for 2-head tiles (32 data + 4 pad)
__global__ __launch_bounds__(256, 2) void attn_h2()
{
    __shared__ __align__(16) unsigned sK[2][64*AP];
    __shared__ __align__(16) unsigned sV[2][64*AP];

    int tid = threadIdx.x, lane = tid & 31, wq = tid >> 5;
    int g = lane >> 2, t = lane & 3;
    int bhp = blockIdx.x;                 // 0..63
    int b = bhp >> 2, hp = bhp & 3;       // head pair hp -> heads 2hp, 2hp+1
    int q0 = blockIdx.y * 128;

    int r0 = q0 + wq*16 + g;
    int qrow0 = b*SS + r0, qrow1 = qrow0 + 8;

    unsigned sK_u = (unsigned)__cvta_generic_to_shared(sK);
    unsigned sV_u = (unsigned)__cvta_generic_to_shared(sV);
    const unsigned KBUF = 64*AP*4;        // 9216 B
    int l8 = lane & 7, qd = lane >> 3;
    unsigned kBase = sK_u + (((qd>>1)*8 + l8)*AP + (qd&1)*4)*4;   // +h*64 +p*(16*AP*4) +kk*32
    unsigned vBase = sV_u + (((qd&1)*8 + l8)*AP)*4 + (qd>>1)*16;  // +h*64 +kk*(16*AP*4) +p*32

    unsigned qhf[2][2][4];
    #pragma unroll
    for (int h = 0; h < 2; h++)
        #pragma unroll
        for (int kk = 0; kk < 2; kk++) {
            int base = hp*32 + h*16 + kk*8 + t;
            int b0 = qrow0*128 + base, b1 = qrow1*128 + base;
            qhf[h][kk][0] = g_qph[b0]; qhf[h][kk][1] = g_qph[b1];
            qhf[h][kk][2] = g_qph[b0+4]; qhf[h][kk][3] = g_qph[b1+4];
        }

    float O[2][4][4];
    #pragma unroll
    for (int h = 0; h < 2; h++)
        #pragma unroll
        for (int dn = 0; dn < 4; dn++)
            #pragma unroll
            for (int i = 0; i < 4; i++) O[h][dn][i] = 0.f;
    float ms0[2] = {-1e30f,-1e30f}, ms1[2] = {-1e30f,-1e30f};
    float ls0[2] = {0.f,0.f}, ls1[2] = {0.f,0.f};

    int lrow[2], lf[2];
    #pragma unroll
    for (int j = 0; j < 2; j++) { int idx = tid + j*256; lrow[j] = idx >> 3; lf[j] = idx & 7; }

    auto issue = [&](int kt, int bs) {
        #pragma unroll
        for (int j = 0; j < 2; j++) {
            size_t src = (size_t)(b*SS + kt*64 + lrow[j])*128 + hp*32 + lf[j]*4;
            unsigned d = (lrow[j]*AP + lf[j]*4)*4;
            cpa16(sK_u + bs*KBUF + d, &g_kph[src]);
            cpa16(sV_u + bs*KBUF + d, &g_vph[src]);
        }
        cpa_commit();
    };
    issue(0, 0);

    const unsigned ONE2 = 0x3C003C00u;

    #pragma unroll 1
    for (int kt = 0; kt < 16; kt++) {
        if (kt < 15) {
            issue(kt+1, (kt+1) & 1);
            asm volatile("cp.async.wait_group 1;");
        } else {
            asm volatile("cp.async.wait_group 0;");
        }
        __syncthreads();
        int bsel = kt & 1;

        // bias tile -> regs (shared by both heads)
        unsigned bf[8][2];
        #pragma unroll
        for (int nt = 0; nt < 8; nt++) {
            int pc = kt*32 + nt*4 + t;
            bf[nt][0] = g_rbh[r0*512 + pc];
            bf[nt][1] = g_rbh[(r0+8)*512 + pc];
        }

        #pragma unroll
        for (int h = 0; h < 2; h++) {
            float S_[8][4];
            #pragma unroll
            for (int nt = 0; nt < 8; nt++)
                #pragma unroll
                for (int i = 0; i < 4; i++) S_[nt][i] = 0.f;
            #pragma unroll
            for (int kk = 0; kk < 2; kk++) {
                #pragma unroll
                for (int p = 0; p < 4; p++) {
                    unsigned k0r, k1r, k2r, k3r;
                    ldsm4(k0r, k1r, k2r, k3r,
                          kBase + h*64 + bsel*KBUF + p*(16*AP*4) + kk*32);
                    mmah(S_[2*p  ], qhf[h][kk][0], qhf[h][kk][1], qhf[h][kk][2], qhf[h][kk][3], k0r, k1r);
                    mmah(S_[2*p+1], qhf[h][kk][0], qhf[h][kk][1], qhf[h][kk][2], qhf[h][kk][3], k2r, k3r);
                }
            }
            #pragma unroll
            for (int nt = 0; nt < 8; nt++) {
                float2 b0v = up2(bf[nt][0]);
                float2 b1v = up2(bf[nt][1]);
                S_[nt][0] += b0v.x; S_[nt][1] += b0v.y;
                S_[nt][2] += b1v.x; S_[nt][3] += b1v.y;
            }

            float tm0 = -1e30f, tm1 = -1e30f;
            #pragma unroll
            for (int nt = 0; nt < 8; nt++) {
                tm0 = fmaxf(tm0, fmaxf(S_[nt][0], S_[nt][1]));
                tm1 = fmaxf(tm1, fmaxf(S_[nt][2], S_[nt][3]));
            }
            tm0 = fmaxf(tm0, __shfl_xor_sync(0xffffffffu, tm0, 1));
            tm0 = fmaxf(tm0, __shfl_xor_sync(0xffffffffu, tm0, 2));
            tm1 = fmaxf(tm1, __shfl_xor_sync(0xffffffffu, tm1, 1));
            tm1 = fmaxf(tm1, __shfl_xor_sync(0xffffffffu, tm1, 2));
            float nm0 = fmaxf(ms0[h], tm0), nm1 = fmaxf(ms1[h], tm1);
            float sc0 = ex2(ms0[h] - nm0), sc1 = ex2(ms1[h] - nm1);

            unsigned pf[8][2];
            #pragma unroll
            for (int nt = 0; nt < 8; nt++) {
                __half2 d0 = __floats2half2_rn(S_[nt][0] - nm0, S_[nt][1] - nm0);
                __half2 d1 = __floats2half2_rn(S_[nt][2] - nm1, S_[nt][3] - nm1);
                __half2 p0 = h2exp2(d0);
                __half2 p1 = h2exp2(d1);
                pf[nt][0] = *reinterpret_cast<unsigned*>(&p0);
                pf[nt][1] = *reinterpret_cast<unsigned*>(&p1);
            }

            float rsA[4] = {0.f, 0.f, 0.f, 0.f};
            #pragma unroll
            for (int kk = 0; kk < 4; kk++)
                mmah(rsA, pf[2*kk][0], pf[2*kk][1], pf[2*kk+1][0], pf[2*kk+1][1], ONE2, ONE2);
            ls0[h] = ls0[h]*sc0 + rsA[0];
            ls1[h] = ls1[h]*sc1 + rsA[2];
            ms0[h] = nm0;  ms1[h] = nm1;
            #pragma unroll
            for (int dn = 0; dn < 4; dn++) {
                O[h][dn][0] *= sc0; O[h][dn][1] *= sc0;
                O[h][dn][2] *= sc1; O[h][dn][3] *= sc1;
            }

            #pragma unroll
            for (int kk = 0; kk < 4; kk++) {
                unsigned a0 = pf[2*kk][0], a1 = pf[2*kk][1];
                unsigned a2 = pf[2*kk+1][0], a3 = pf[2*kk+1][1];
                #pragma unroll
                for (int p = 0; p < 2; p++) {
                    unsigned v0, v1, v2, v3;
                    ldsm4t(v0, v1, v2, v3,
                           vBase + h*64 + bsel*KBUF + kk*(16*AP*4) + p*32);
                    mmah(O[h][2*p  ], a0, a1, a2, a3, v0, v1);
                    mmah(O[h][2*p+1], a0, a1, a2, a3, v2, v3);
                }
            }
        }
        __syncthreads();
    }

    #pragma unroll
    for (int h = 0; h < 2; h++) {
        int hd = hp*2 + h;
        float il0 = 1.f/ls0[h], il1 = 1.f/ls1[h];
        #pragma unroll
        for (int dn = 0; dn < 4; dn++) {
            int cp = hd*16 + dn*4 + t;
            g_oph[qrow0*128 + cp] = pkh(O[h][dn][0]*il0, O[h][dn][1]*il0);
            g_oph[qrow1*128 + cp] = pkh(O[h][dn][2]*il1, O[h][dn][3]*il1);
        }
    }
}

// ---------------- launch ------------------------------------------------------
extern "C" void kernel_launch(void* const* d_in, const int* in_sizes, int n_in,
                              void* d_out, int out_size)
{
    const float* Matrix = (const float*)d_in[0];
    const float* ln_g   = (const float*)d_in[1];
    const float* ln_b   = (const float*)d_in[2];
    const float* Wq     = (const float*)d_in[3];
    const float* bq     = (const float*)d_in[4];
    const float* Wk     = (const float*)d_in[5];
    const float* bk     = (const float*)d_in[6];
    const float* Wv     = (const float*)d_in[7];
    const float* bv     = (const float*)d_in[8];
    const float* Wo     = (const float*)d_in[9];
    const float* bo     = (const float*)d_in[10];
    const float* rel    = (const float*)d_in[11];
    const float* gW     = (const float*)d_in[12];
    const float* gb     = (const float*)d_in[13];
    const float* mW     = (const float*)d_in[14];
    const float* mb     = (const float*)d_in[15];
    float* out = (float*)d_out;

    const int SM1 = 3*(128*GP*4 + 128*GP*4);          // 61440
    const int SM2 = 3*(64*GP*4 + 2*128*GP*4);         // 76800
    const int SMM = 2*(64*GP*4) + 4*(256*GP*4) + 2048; // 94208
    static bool attr_set = false;
    if (!attr_set) {
        cudaFuncSetAttribute(gemm_t<128,false>, cudaFuncAttributeMaxDynamicSharedMemorySize, SM1);
        cudaFuncSetAttribute(gemm_t<64,true>,  cudaFuncAttributeMaxDynamicSharedMemorySize, SM2);
        cudaFuncSetAttribute(gemm_mlp, cudaFuncAttributeMaxDynamicSharedMemorySize, SMM);
        attr_set = true;
    }

    prep<<<3168, 256>>>(Matrix, ln_g, ln_b, Wq, Wk, Wv, gW, Wo, mW, rel);

    gemm_t<128,false><<<dim3(2,128,4), 256, SM1>>>(bq, bk, bv, gb, bo, Matrix, 0);
    attn_h2<<<dim3(64,8), 256>>>();
    gemm_t<64,true><<<dim3(2,256,1), 256, SM2>>>(bq, bk, bv, gb, bo, Matrix, 4);
    gemm_mlp<<<256, 256, SMM>>>(mb, ln_g, ln_b, out);
}

// round 11
// speedup vs baseline: 1.3062x; 1.0630x over previous
#include <cuda_runtime.h>
#include <cuda_fp16.h>
#include <math.h>

#define BB 16
#define SS 1024
#define EE 256
#define HH 8
#define DHD 32
#define MROWS (BB*SS)   // 16384
#define GP 20           // smem pitch (uints); conflict-free for LDSM

// ---------------- scratch ----------------------------------------------------
__device__ unsigned g_wt[6][256*128];        // weight hi planes [n][kpair]
__device__ unsigned g_rbh[SS*512];           // rel_bias * log2e, fp16 pairs
__device__ unsigned g_lnh[MROWS*128];
__device__ unsigned g_mth[MROWS*128];
__device__ unsigned g_qph[MROWS*128];        // pre-scaled by log2e/sqrt(DH)
__device__ unsigned g_kph[MROWS*128];
__device__ unsigned g_vph[MROWS*128];
__device__ unsigned g_oph[MROWS*128];
__device__ unsigned g_g0h[MROWS*128];        // gate0 fp16 pairs
__device__ unsigned g_g1h[MROWS*128];
__device__ float g_gate1[MROWS*EE];

// ---------------- helpers -----------------------------------------------------
__device__ __forceinline__ unsigned pkh(float a, float b) {
    __half2 t = __floats2half2_rn(a, b);
    return *reinterpret_cast<unsigned*>(&t);
}
__device__ __forceinline__ float2 up2(unsigned u) {
    return __half22float2(*reinterpret_cast<__half2*>(&u));
}
__device__ __forceinline__ void mmah(float* c,
    unsigned a0, unsigned a1, unsigned a2, unsigned a3,
    unsigned b0, unsigned b1)
{
    asm volatile(
        "mma.sync.aligned.m16n8k16.row.col.f32.f16.f16.f32 "
        "{%0,%1,%2,%3},{%4,%5,%6,%7},{%8,%9},{%0,%1,%2,%3};"
        : "+f"(c[0]), "+f"(c[1]), "+f"(c[2]), "+f"(c[3])
        : "r"(a0), "r"(a1), "r"(a2), "r"(a3), "r"(b0), "r"(b1));
}
__device__ __forceinline__ void ldsm4(unsigned &r0, unsigned &r1, unsigned &r2, unsigned &r3, unsigned addr) {
    asm volatile("ldmatrix.sync.aligned.m8n8.x4.shared.b16 {%0,%1,%2,%3}, [%4];"
        : "=r"(r0), "=r"(r1), "=r"(r2), "=r"(r3) : "r"(addr));
}
__device__ __forceinline__ void ldsm4t(unsigned &r0, unsigned &r1, unsigned &r2, unsigned &r3, unsigned addr) {
    asm volatile("ldmatrix.sync.aligned.m8n8.x4.trans.shared.b16 {%0,%1,%2,%3}, [%4];"
        : "=r"(r0), "=r"(r1), "=r"(r2), "=r"(r3) : "r"(addr));
}
__device__ __forceinline__ void cpa16(unsigned dst, const void* src) {
    asm volatile("cp.async.cg.shared.global [%0], [%1], 16;" :: "r"(dst), "l"(src));
}
__device__ __forceinline__ void cpa_commit() {
    asm volatile("cp.async.commit_group;");
}
__device__ __forceinline__ float ex2(float x) {
    float r; asm("ex2.approx.ftz.f32 %0, %1;" : "=f"(r) : "f"(x)); return r;
}
__device__ __forceinline__ float wsum(float v) {
    #pragma unroll
    for (int o = 16; o > 0; o >>= 1) v += __shfl_xor_sync(0xffffffffu, v, o);
    return v;
}

#define L2E 1.4426950408889634f

// ---------------- fused prep: weight pack + bias pack + LN --------------------
__global__ __launch_bounds__(256) void prep(
    const float* __restrict__ x, const float* __restrict__ lng,
    const float* __restrict__ lnb,
    const float* __restrict__ Wq, const float* __restrict__ Wk,
    const float* __restrict__ Wv, const float* __restrict__ gW,
    const float* __restrict__ Wo, const float* __restrict__ mW,
    const float* __restrict__ rel)
{
    __shared__ float s[64][65];
    int bx = blockIdx.x, tid = threadIdx.x;
    if (bx < 96) {
        int w = bx >> 4, rem = bx & 15;
        int k0 = (rem >> 2) * 64, n0 = (rem & 3) * 64;
        const float* W;
        switch (w) {
            case 0: W = Wq; break; case 1: W = Wk; break; case 2: W = Wv; break;
            case 3: W = gW; break; case 4: W = Wo; break; default: W = mW; break;
        }
        for (int i = tid; i < 4096; i += 256) {
            int r = i >> 6, c = i & 63;
            s[r][c] = W[(size_t)(k0 + r)*EE + n0 + c];
        }
        __syncthreads();
        for (int i = tid; i < 2048; i += 256) {
            int n = i >> 5, kp = i & 31;
            g_wt[w][(n0 + n)*128 + k0/2 + kp] = pkh(s[2*kp][n], s[2*kp+1][n]);
        }
    } else if (bx < 1120) {
        int row = bx - 96;
        #pragma unroll
        for (int j = 0; j < 2; j++) {
            int i = tid + j*256;
            float2 v = *(const float2*)&rel[(size_t)row*SS + 2*i];
            g_rbh[row*512 + i] = pkh(v.x*L2E, v.y*L2E);
        }
    } else {
        int warp = tid >> 5, lane = tid & 31;
        int row = (bx - 1120)*8 + warp;
        const float* xr = x + (size_t)row*EE + lane*8;
        float4 a0 = *(const float4*)xr;
        float4 a1 = *(const float4*)(xr + 4);
        float xv[8] = {a0.x,a0.y,a0.z,a0.w,a1.x,a1.y,a1.z,a1.w};
        float sm = 0.f;
        #pragma unroll
        for (int i = 0; i < 8; i++) sm += xv[i];
        float mean = wsum(sm) * (1.f/EE);
        float vs = 0.f;
        #pragma unroll
        for (int i = 0; i < 8; i++) { float d = xv[i]-mean; vs += d*d; }
        float rstd = rsqrtf(wsum(vs)*(1.f/EE) + 1e-5f);
        float4 g0 = *(const float4*)(lng + lane*8);
        float4 g1 = *(const float4*)(lng + lane*8 + 4);
        float4 b0 = *(const float4*)(lnb + lane*8);
        float4 b1 = *(const float4*)(lnb + lane*8 + 4);
        float gg[8] = {g0.x,g0.y,g0.z,g0.w,g1.x,g1.y,g1.z,g1.w};
        float bb[8] = {b0.x,b0.y,b0.z,b0.w,b1.x,b1.y,b1.z,b1.w};
        float ln[8];
        #pragma unroll
        for (int i = 0; i < 8; i++) ln[i] = (xv[i]-mean)*rstd*gg[i] + bb[i];
        uint4 u, um;
        u.x = pkh(ln[0],ln[1]); u.y = pkh(ln[2],ln[3]);
        u.z = pkh(ln[4],ln[5]); u.w = pkh(ln[6],ln[7]);
        um.x = pkh(xv[0],xv[1]); um.y = pkh(xv[2],xv[3]);
        um.z = pkh(xv[4],xv[5]); um.w = pkh(xv[6],xv[7]);
        *(uint4*)&g_lnh[row*128 + lane*4] = u;
        *(uint4*)&g_mth[row*128 + lane*4] = um;
    }
}

// ---------------- fp16 GEMM (ops 0..4), 128x128, 1-pass, 3-stage cp.async -----
__global__ __launch_bounds__(256, 2) void gemm_t(
    const float* __restrict__ bq, const float* __restrict__ bk,
    const float* __restrict__ bv, const float* __restrict__ gb,
    const float* __restrict__ bo, const float* __restrict__ Matrix, int op_base)
{
    extern __shared__ __align__(16) unsigned smem[];
    constexpr unsigned A_STG = 128*GP*4;
    constexpr unsigned B_STG = 128*GP*4;
    constexpr unsigned A_OFF = 0;
    constexpr unsigned BH_OFF = 3*A_STG;

    int op = op_base + blockIdx.z;
    const unsigned* Ah;
    const float* bias;
    switch (op) {
        case 0: Ah = g_lnh; bias = bq; break;
        case 1: Ah = g_lnh; bias = bk; break;
        case 2: Ah = g_lnh; bias = bv; break;
        case 3: Ah = g_mth; bias = gb; break;
        default: Ah = g_oph; bias = bo; break;
    }
    const unsigned* Wh = g_wt[op];

    int tid = threadIdx.x, lane = tid & 31, warp = tid >> 5;
    int wm = warp >> 1, wn = warp & 1;
    int g = lane >> 2, t = lane & 3;
    int m0 = blockIdx.y * 128, n0 = blockIdx.x * 128;

    unsigned s_u = (unsigned)__cvta_generic_to_shared(smem);
    int l16 = lane & 15, secA = lane >> 4;
    unsigned aFrag = s_u + A_OFF + (((wm*32 + l16)*GP) + secA*4)*4;
    int l8 = lane & 7, qd = lane >> 3;
    unsigned bFrag = (((wn*64 + (qd>>1)*8 + l8)*GP) + (qd&1)*4)*4;

    int arow[2], af4[2];
    #pragma unroll
    for (int j = 0; j < 2; j++) { int idx = tid + j*256; arow[j] = idx >> 2; af4[j] = idx & 3; }

    float acc[2][8][4];
    #pragma unroll
    for (int mt = 0; mt < 2; mt++)
        #pragma unroll
        for (int nt = 0; nt < 8; nt++)
            #pragma unroll
            for (int i = 0; i < 4; i++) acc[mt][nt][i] = 0.f;

    auto issue = [&](int ch, int bsel) {
        int cc = ch*16;
        #pragma unroll
        for (int j = 0; j < 2; j++) {
            cpa16(s_u + A_OFF + bsel*A_STG + (arow[j]*GP + af4[j]*4)*4,
                  &Ah[(size_t)(m0 + arow[j])*128 + cc + af4[j]*4]);
            cpa16(s_u + BH_OFF + bsel*B_STG + (arow[j]*GP + af4[j]*4)*4,
                  &Wh[(size_t)(n0 + arow[j])*128 + cc + af4[j]*4]);
        }
        cpa_commit();
    };

    issue(0, 0);
    issue(1, 1);

    #pragma unroll 1
    for (int c = 0; c < 8; c++) {
        if (c < 6) {
            issue(c+2, (c+2) % 3);
            asm volatile("cp.async.wait_group 2;");
        } else if (c == 6) {
            asm volatile("cp.async.wait_group 1;");
        } else {
            asm volatile("cp.async.wait_group 0;");
        }
        __syncthreads();

        int bsel = c % 3;
        #pragma unroll
        for (int kk = 0; kk < 2; kk++) {
            unsigned a[2][4];
            #pragma unroll
            for (int mt = 0; mt < 2; mt++)
                ldsm4(a[mt][0], a[mt][1], a[mt][2], a[mt][3],
                      aFrag + bsel*A_STG + mt*(16*GP*4) + kk*32);
            #pragma unroll
            for (int pr = 0; pr < 4; pr++) {
                unsigned b0, b1, b2, b3;
                ldsm4(b0, b1, b2, b3,
                      s_u + BH_OFF + bsel*B_STG + bFrag + pr*(16*GP*4) + kk*32);
                #pragma unroll
                for (int mt = 0; mt < 2; mt++) {
                    mmah(acc[mt][2*pr  ], a[mt][0], a[mt][1], a[mt][2], a[mt][3], b0, b1);
                    mmah(acc[mt][2*pr+1], a[mt][0], a[mt][1], a[mt][2], a[mt][3], b2, b3);
                }
            }
        }
        __syncthreads();
    }

    const float qscale = 0.17677669529663687f * L2E;
    #pragma unroll
    for (int mt = 0; mt < 2; mt++) {
        int row0 = m0 + wm*32 + mt*16 + g;
        int row1 = row0 + 8;
        #pragma unroll
        for (int nt = 0; nt < 8; nt++) {
            int col = n0 + wn*64 + nt*8 + t*2;
            int cp  = col >> 1;
            float bv0 = bias[col], bv1 = bias[col+1];
            float v00 = acc[mt][nt][0] + bv0, v01 = acc[mt][nt][1] + bv1;
            float v10 = acc[mt][nt][2] + bv0, v11 = acc[mt][nt][3] + bv1;
            if (op == 0) {
                g_qph[row0*128 + cp] = pkh(v00*qscale, v01*qscale);
                g_qph[row1*128 + cp] = pkh(v10*qscale, v11*qscale);
            } else if (op == 1) {
                g_kph[row0*128 + cp] = pkh(v00, v01);
                g_kph[row1*128 + cp] = pkh(v10, v11);
            } else if (op == 2) {
                g_vph[row0*128 + cp] = pkh(v00, v01);
                g_vph[row1*128 + cp] = pkh(v10, v11);
            } else if (op == 3) {
                v00 = 1.f/(1.f + __expf(-v00)); v01 = 1.f/(1.f + __expf(-v01));
                v10 = 1.f/(1.f + __expf(-v10)); v11 = 1.f/(1.f + __expf(-v11));
                g_g0h[row0*128 + cp] = pkh(v00, v01);
                g_g0h[row1*128 + cp] = pkh(v10, v11);
            } else {  // op 4: gate1 = gate0*rmha + Matrix
                size_t i0 = (size_t)row0*EE + col, i1 = (size_t)row1*EE + col;
                float2 ga0 = up2(g_g0h[row0*128 + cp]);
                float2 ga1 = up2(g_g0h[row1*128 + cp]);
                float2 mx0 = *(const float2*)&Matrix[i0];
                float2 mx1 = *(const float2*)&Matrix[i1];
                v00 = ga0.x*v00 + mx0.x;  v01 = ga0.y*v01 + mx0.y;
                v10 = ga1.x*v10 + mx1.x;  v11 = ga1.y*v11 + mx1.y;
                *(float2*)&g_gate1[i0] = make_float2(v00, v01);
                *(float2*)&g_gate1[i1] = make_float2(v10, v11);
                g_g1h[row0*128 + cp] = pkh(v00, v01);
                g_g1h[row1*128 + cp] = pkh(v10, v11);
            }
        }
    }
}

// ---------------- fused mW GEMM + sigmoid + LN + gated output (1-pass) --------
// block: 64 rows x 256 cols. dyn smem: A[2]@0, Bh[2]@10240, red@51200
__global__ __launch_bounds__(256, 2) void gemm_mlp(
    const float* __restrict__ mb, const float* __restrict__ lng,
    const float* __restrict__ lnb, float* __restrict__ out)
{
    extern __shared__ __align__(16) unsigned smem[];
    constexpr unsigned A_STG = 64*GP*4;      // 5120
    constexpr unsigned B_STG = 256*GP*4;     // 20480
    constexpr unsigned A_OFF = 0;
    constexpr unsigned BH_OFF = 2*A_STG;     // 10240
    const unsigned* Wh = g_wt[5];

    int tid = threadIdx.x, lane = tid & 31, warp = tid >> 5;
    int wm = warp >> 2, wn = warp & 3;
    int g = lane >> 2, t = lane & 3;
    int m0 = blockIdx.x * 64;

    unsigned s_u = (unsigned)__cvta_generic_to_shared(smem);
    int l16 = lane & 15, secA = lane >> 4;
    unsigned aFrag = s_u + A_OFF + (((wm*32 + l16)*GP) + secA*4)*4;
    int l8 = lane & 7, qd = lane >> 3;
    unsigned bFrag = (((wn*64 + (qd>>1)*8 + l8)*GP) + (qd&1)*4)*4;

    int arow = tid >> 2, af4 = tid & 3;
    int brow[4], bf4[4];
    #pragma unroll
    for (int j = 0; j < 4; j++) { int idx = tid + j*256; brow[j] = idx >> 2; bf4[j] = idx & 3; }

    float acc[2][8][4];
    #pragma unroll
    for (int mt = 0; mt < 2; mt++)
        #pragma unroll
        for (int nt = 0; nt < 8; nt++)
            #pragma unroll
            for (int i = 0; i < 4; i++) acc[mt][nt][i] = 0.f;

    auto issue = [&](int ch, int bs) {
        int cc = ch*16;
        cpa16(s_u + A_OFF + bs*A_STG + (arow*GP + af4*4)*4,
              &g_g1h[(size_t)(m0 + arow)*128 + cc + af4*4]);
        #pragma unroll
        for (int j = 0; j < 4; j++)
            cpa16(s_u + BH_OFF + bs*B_STG + (brow[j]*GP + bf4[j]*4)*4,
                  &Wh[(size_t)brow[j]*128 + cc + bf4[j]*4]);
        cpa_commit();
    };

    issue(0, 0);

    #pragma unroll 1
    for (int c = 0; c < 8; c++) {
        if (c < 7) {
            issue(c+1, (c+1) & 1);
            asm volatile("cp.async.wait_group 1;");
        } else {
            asm volatile("cp.async.wait_group 0;");
        }
        __syncthreads();

        int bs = c & 1;
        #pragma unroll
        for (int kk = 0; kk < 2; kk++) {
            unsigned a[2][4];
            #pragma unroll
            for (int mt = 0; mt < 2; mt++)
                ldsm4(a[mt][0], a[mt][1], a[mt][2], a[mt][3],
                      aFrag + bs*A_STG + mt*(16*GP*4) + kk*32);
            #pragma unroll
            for (int pr = 0; pr < 4; pr++) {
                unsigned b0, b1, b2, b3;
                ldsm4(b0, b1, b2, b3,
                      s_u + BH_OFF + bs*B_STG + bFrag + pr*(16*GP*4) + kk*32);
                #pragma unroll
                for (int mt = 0; mt < 2; mt++) {
                    mmah(acc[mt][2*pr  ], a[mt][0], a[mt][1], a[mt][2], a[mt][3], b0, b1);
                    mmah(acc[mt][2*pr+1], a[mt][0], a[mt][1], a[mt][2], a[mt][3], b2, b3);
                }
            }
        }
        __syncthreads();
    }

    // ---- epilogue: sigmoid + per-row LN + gated output ----
    float* sS = (float*)&smem[12800];   // byte 51200: [64][4]
    float* sQ = sS + 256;

    float psum[2][2] = {{0,0},{0,0}}, psq[2][2] = {{0,0},{0,0}};
    #pragma unroll
    for (int mt = 0; mt < 2; mt++) {
        #pragma unroll
        for (int nt = 0; nt < 8; nt++) {
            int col = wn*64 + nt*8 + t*2;
            float bv0 = mb[col], bv1 = mb[col+1];
            float v00 = 1.f/(1.f + __expf(-(acc[mt][nt][0] + bv0)));
            float v01 = 1.f/(1.f + __expf(-(acc[mt][nt][1] + bv1)));
            float v10 = 1.f/(1.f + __expf(-(acc[mt][nt][2] + bv0)));
            float v11 = 1.f/(1.f + __expf(-(acc[mt][nt][3] + bv1)));
            acc[mt][nt][0] = v00; acc[mt][nt][1] = v01;
            acc[mt][nt][2] = v10; acc[mt][nt][3] = v11;
            psum[mt][0] += v00 + v01;  psq[mt][0] += v00*v00 + v01*v01;
            psum[mt][1] += v10 + v11;  psq[mt][1] += v10*v10 + v11*v11;
        }
    }
    #pragma unroll
    for (int mt = 0; mt < 2; mt++)
        #pragma unroll
        for (int hf = 0; hf < 2; hf++) {
            float s = psum[mt][hf], q = psq[mt][hf];
            s += __shfl_xor_sync(0xffffffffu, s, 1);
            s += __shfl_xor_sync(0xffffffffu, s, 2);
            q += __shfl_xor_sync(0xffffffffu, q, 1);
            q += __shfl_xor_sync(0xffffffffu, q, 2);
            psum[mt][hf] = s; psq[mt][hf] = q;
        }
    if (t == 0) {
        #pragma unroll
        for (int mt = 0; mt < 2; mt++)
            #pragma unroll
            for (int hf = 0; hf < 2; hf++) {
                int r = wm*32 + mt*16 + g + hf*8;
                sS[r*4 + wn] = psum[mt][hf];
                sQ[r*4 + wn] = psq[mt][hf];
            }
    }
    __syncthreads();

    float mean[2][2], rstd[2][2];
    #pragma unroll
    for (int mt = 0; mt < 2; mt++)
        #pragma unroll
        for (int hf = 0; hf < 2; hf++) {
            int r = wm*32 + mt*16 + g + hf*8;
            float s = sS[r*4+0] + sS[r*4+1] + sS[r*4+2] + sS[r*4+3];
            float q = sQ[r*4+0] + sQ[r*4+1] + sQ[r*4+2] + sQ[r*4+3];
            float m = s * (1.f/EE);
            float v = q * (1.f/EE) - m*m;
            mean[mt][hf] = m;
            rstd[mt][hf] = rsqrtf(v + 1e-5f);
        }

    #pragma unroll
    for (int mt = 0; mt < 2; mt++) {
        int row0 = m0 + wm*32 + mt*16 + g;
        int row1 = row0 + 8;
        #pragma unroll
        for (int nt = 0; nt < 8; nt++) {
            int col = wn*64 + nt*8 + t*2;
            float2 gm = *(const float2*)&lng[col];
            float2 bt = *(const float2*)&lnb[col];
            size_t i0 = (size_t)row0*EE + col, i1 = (size_t)row1*EE + col;
            float2 g10 = *(const float2*)&g_gate1[i0];
            float2 g11 = *(const float2*)&g_gate1[i1];
            float ln00 = (acc[mt][nt][0] - mean[mt][0])*rstd[mt][0]*gm.x + bt.x;
            float ln01 = (acc[mt][nt][1] - mean[mt][0])*rstd[mt][0]*gm.y + bt.y;
            float ln10 = (acc[mt][nt][2] - mean[mt][1])*rstd[mt][1]*gm.x + bt.x;
            float ln11 = (acc[mt][nt][3] - mean[mt][1])*rstd[mt][1]*gm.y + bt.y;
            *(float2*)&out[i0] = make_float2(g10.x*(ln00+1.f), g10.y*(ln01+1.f));
            *(float2*)&out[i1] = make_float2(g11.x*(ln10+1.f), g11.y*(ln11+1.f));
        }
    }
}

// ---------------- head-paired fp16 flash attention ----------------------------
#define AP 36
__global__ __launch_bounds__(256, 2) void attn_h2()
{
    __shared__ __align__(16) unsigned sK[2][64*AP];
    __shared__ __align__(16) unsigned sV[2][64*AP];

    int tid = threadIdx.x, lane = tid & 31, wq = tid >> 5;
    int g = lane >> 2, t = lane & 3;
    int bhp = blockIdx.x;
    int b = bhp >> 2, hp = bhp & 3;
    int q0 = blockIdx.y * 128;

    int r0 = q0 + wq*16 + g;
    int qrow0 = b*SS + r0, qrow1 = qrow0 + 8;

    unsigned sK_u = (unsigned)__cvta_generic_to_shared(sK);
    unsigned sV_u = (unsigned)__cvta_generic_to_shared(sV);
    const unsigned KBUF = 64*AP*4;
    int l8 = lane & 7, qd = lane >> 3;
    unsigned kBase = sK_u + (((qd>>1)*8 + l8)*AP + (qd&1)*4)*4;
    unsigned vBase = sV_u + (((qd&1)*8 + l8)*AP)*4 + (qd>>1)*16;

    unsigned qhf[2][2][4];
    #pragma unroll
    for (int h = 0; h < 2; h++)
        #pragma unroll
        for (int kk = 0; kk < 2; kk++) {
            int base = hp*32 + h*16 + kk*8 + t;
            int b0 = qrow0*128 + base, b1 = qrow1*128 + base;
            qhf[h][kk][0] = g_qph[b0]; qhf[h][kk][1] = g_qph[b1];
            qhf[h][kk][2] = g_qph[b0+4]; qhf[h][kk][3] = g_qph[b1+4];
        }

    float O[2][4][4];
    #pragma unroll
    for (int h = 0; h < 2; h++)
        #pragma unroll
        for (int dn = 0; dn < 4; dn++)
            #pragma unroll
            for (int i = 0; i < 4; i++) O[h][dn][i] = 0.f;
    float ms0[2] = {-1e30f,-1e30f}, ms1[2] = {-1e30f,-1e30f};
    float ls0[2] = {0.f,0.f}, ls1[2] = {0.f,0.f};

    int lrow[2], lf[2];
    #pragma unroll
    for (int j = 0; j < 2; j++) { int idx = tid + j*256; lrow[j] = idx >> 3; lf[j] = idx & 7; }

    auto issue = [&](int kt, int bs) {
        #pragma unroll
        for (int j = 0; j < 2; j++) {
            size_t src = (size_t)(b*SS + kt*64 + lrow[j])*128 + hp*32 + lf[j]*4;
            unsigned d = (lrow[j]*AP + lf[j]*4)*4;
            cpa16(sK_u + bs*KBUF + d, &g_kph[src]);
            cpa16(sV_u + bs*KBUF + d, &g_vph[src]);
        }
        cpa_commit();
    };
    issue(0, 0);

    const unsigned ONE2 = 0x3C003C00u;

    #pragma unroll 1
    for (int kt = 0; kt < 16; kt++) {
        if (kt < 15) {
            issue(kt+1, (kt+1) & 1);
            asm volatile("cp.async.wait_group 1;");
        } else {
            asm volatile("cp.async.wait_group 0;");
        }
        __syncthreads();
        int bsel = kt & 1;

        unsigned bf[8][2];
        #pragma unroll
        for (int nt = 0; nt < 8; nt++) {
            int pc = kt*32 + nt*4 + t;
            bf[nt][0] = g_rbh[r0*512 + pc];
            bf[nt][1] = g_rbh[(r0+8)*512 + pc];
        }

        #pragma unroll
        for (int h = 0; h < 2; h++) {
            float S_[8][4];
            #pragma unroll
            for (int nt = 0; nt < 8; nt++)
                #pragma unroll
                for (int i = 0; i < 4; i++) S_[nt][i] = 0.f;
            #pragma unroll
            for (int kk = 0; kk < 2; kk++) {
                #pragma unroll
                for (int p = 0; p < 4; p++) {
                    unsigned k0r, k1r, k2r, k3r;
                    ldsm4(k0r, k1r, k2r, k3r,
                          kBase + h*64 + bsel*KBUF + p*(16*AP*4) + kk*32);
                    mmah(S_[2*p  ], qhf[h][kk][0], qhf[h][kk][1], qhf[h][kk][2], qhf[h][kk][3], k0r, k1r);
                    mmah(S_[2*p+1], qhf[h][kk][0], qhf[h][kk][1], qhf[h][kk][2], qhf[h][kk][3], k2r, k3r);
                }
            }
            #pragma unroll
            for (int nt = 0; nt < 8; nt++) {
                float2 b0v = up2(bf[nt][0]);
                float2 b1v = up2(bf[nt][1]);
                S_[nt][0] += b0v.x; S_[nt][1] += b0v.y;
                S_[nt][2] += b1v.x; S_[nt][3] += b1v.y;
            }

            float tm0 = -1e30f, tm1 = -1e30f;
            #pragma unroll
            for (int nt = 0; nt < 8; nt++) {
                tm0 = fmaxf(tm0, fmaxf(S_[nt][0], S_[nt][1]));
                tm1 = fmaxf(tm1, fmaxf(S_[nt][2], S_[nt][3]));
            }
            tm0 = fmaxf(tm0, __shfl_xor_sync(0xffffffffu, tm0, 1));
            tm0 = fmaxf(tm0, __shfl_xor_sync(0xffffffffu, tm0, 2));
            tm1 = fmaxf(tm1, __shfl_xor_sync(0xffffffffu, tm1, 1));
            tm1 = fmaxf(tm1, __shfl_xor_sync(0xffffffffu, tm1, 2));
            float nm0 = fmaxf(ms0[h], tm0), nm1 = fmaxf(ms1[h], tm1);
            float sc0 = ex2(ms0[h] - nm0), sc1 = ex2(ms1[h] - nm1);

            unsigned pf[8][2];
            #pragma unroll
            for (int nt = 0; nt < 8; nt++) {
                __half2 d0 = __floats2half2_rn(S_[nt][0] - nm0, S_[nt][1] - nm0);
                __half2 d1 = __floats2half2_rn(S_[nt][2] - nm1, S_[nt][3] - nm1);
                __half2 p0 = h2exp2(d0);
                __half2 p1 = h2exp2(d1);
                pf[nt][0] = *reinterpret_cast<unsigned*>(&p0);
                pf[nt][1] = *reinterpret_cast<unsigned*>(&p1);
            }

            float rsA[4] = {0.f, 0.f, 0.f, 0.f};
            #pragma unroll
            for (int kk = 0; kk < 4; kk++)
                mmah(rsA, pf[2*kk][0], pf[2*kk][1], pf[2*kk+1][0], pf[2*kk+1][1], ONE2, ONE2);
            ls0[h] = ls0[h]*sc0 + rsA[0];
            ls1[h] = ls1[h]*sc1 + rsA[2];
            ms0[h] = nm0;  ms1[h] = nm1;
            #pragma unroll
            for (int dn = 0; dn < 4; dn++) {
                O[h][dn][0] *= sc0; O[h][dn][1] *= sc0;
                O[h][dn][2] *= sc1; O[h][dn][3] *= sc1;
            }

            #pragma unroll
            for (int kk = 0; kk < 4; kk++) {
                unsigned a0 = pf[2*kk][0], a1 = pf[2*kk][1];
                unsigned a2 = pf[2*kk+1][0], a3 = pf[2*kk+1][1];
                #pragma unroll
                for (int p = 0; p < 2; p++) {
                    unsigned v0, v1, v2, v3;
                    ldsm4t(v0, v1, v2, v3,
                           vBase + h*64 + bsel*KBUF + kk*(16*AP*4) + p*32);
                    mmah(O[h][2*p  ], a0, a1, a2, a3, v0, v1);
                    mmah(O[h][2*p+1], a0, a1, a2, a3, v2, v3);
                }
            }
        }
        __syncthreads();
    }

    #pragma unroll
    for (int h = 0; h < 2; h++) {
        int hd = hp*2 + h;
        float il0 = 1.f/ls0[h], il1 = 1.f/ls1[h];
        #pragma unroll
        for (int dn = 0; dn < 4; dn++) {
            int cp = hd*16 + dn*4 + t;
            g_oph[qrow0*128 + cp] = pkh(O[h][dn][0]*il0, O[h][dn][1]*il0);
            g_oph[qrow1*128 + cp] = pkh(O[h][dn][2]*il1, O[h][dn][3]*il1);
        }
    }
}

// ---------------- launch ------------------------------------------------------
extern "C" void kernel_launch(void* const* d_in, const int* in_sizes, int n_in,
                              void* d_out, int out_size)
{
    const float* Matrix = (const float*)d_in[0];
    const float* ln_g   = (const float*)d_in[1];
    const float* ln_b   = (const float*)d_in[2];
    const float* Wq     = (const float*)d_in[3];
    const float* bq     = (const float*)d_in[4];
    const float* Wk     = (const float*)d_in[5];
    const float* bk     = (const float*)d_in[6];
    const float* Wv     = (const float*)d_in[7];
    const float* bv     = (const float*)d_in[8];
    const float* Wo     = (const float*)d_in[9];
    const float* bo     = (const float*)d_in[10];
    const float* rel    = (const float*)d_in[11];
    const float* gW     = (const float*)d_in[12];
    const float* gb     = (const float*)d_in[13];
    const float* mW     = (const float*)d_in[14];
    const float* mb     = (const float*)d_in[15];
    float* out = (float*)d_out;

    const int SM1 = 3*(128*GP*4 + 128*GP*4);          // 61440
    const int SMM = 2*(64*GP*4 + 256*GP*4) + 2048;    // 53248
    static bool attr_set = false;
    if (!attr_set) {
        cudaFuncSetAttribute(gemm_t, cudaFuncAttributeMaxDynamicSharedMemorySize, SM1);
        cudaFuncSetAttribute(gemm_mlp, cudaFuncAttributeMaxDynamicSharedMemorySize, SMM);
        attr_set = true;
    }

    prep<<<3168, 256>>>(Matrix, ln_g, ln_b, Wq, Wk, Wv, gW, Wo, mW, rel);

    gemm_t<<<dim3(2,128,4), 256, SM1>>>(bq, bk, bv, gb, bo, Matrix, 0);
    attn_h2<<<dim3(64,8), 256>>>();
    gemm_t<<<dim3(2,128,1), 256, SM1>>>(bq, bk, bv, gb, bo, Matrix, 4);
    gemm_mlp<<<256, 256, SMM>>>(mb, ln_g, ln_b, out);
}

// round 14
// speedup vs baseline: 1.3228x; 1.0127x over previous
#include <cuda_runtime.h>
#include <cuda_fp16.h>
#include <math.h>

#define BB 16
#define SS 1024
#define EE 256
#define HH 8
#define DHD 32
#define MROWS (BB*SS)   // 16384
#define GK 36           // smem pitch (uints) for K=64 chunks: 32 data + 4 pad

// ---------------- scratch ----------------------------------------------------
__device__ unsigned g_wt[6][256*128];        // weight hi planes [n][kpair]
__device__ unsigned g_rbh[SS*512];           // rel_bias * log2e, fp16 pairs
__device__ unsigned g_lnh[MROWS*128];
__device__ unsigned g_mth[MROWS*128];
__device__ unsigned g_qph[MROWS*128];        // pre-scaled by log2e/sqrt(DH)
__device__ unsigned g_kph[MROWS*128];
__device__ unsigned g_vph[MROWS*128];
__device__ unsigned g_oph[MROWS*128];
__device__ unsigned g_g0h[MROWS*128];        // gate0 fp16 pairs
__device__ unsigned g_g1h[MROWS*128];
__device__ float g_gate1[MROWS*EE];

// ---------------- helpers -----------------------------------------------------
__device__ __forceinline__ unsigned pkh(float a, float b) {
    __half2 t = __floats2half2_rn(a, b);
    return *reinterpret_cast<unsigned*>(&t);
}
__device__ __forceinline__ float2 up2(unsigned u) {
    return __half22float2(*reinterpret_cast<__half2*>(&u));
}
__device__ __forceinline__ void mmah(float* c,
    unsigned a0, unsigned a1, unsigned a2, unsigned a3,
    unsigned b0, unsigned b1)
{
    asm volatile(
        "mma.sync.aligned.m16n8k16.row.col.f32.f16.f16.f32 "
        "{%0,%1,%2,%3},{%4,%5,%6,%7},{%8,%9},{%0,%1,%2,%3};"
        : "+f"(c[0]), "+f"(c[1]), "+f"(c[2]), "+f"(c[3])
        : "r"(a0), "r"(a1), "r"(a2), "r"(a3), "r"(b0), "r"(b1));
}
__device__ __forceinline__ void ldsm4(unsigned &r0, unsigned &r1, unsigned &r2, unsigned &r3, unsigned addr) {
    asm volatile("ldmatrix.sync.aligned.m8n8.x4.shared.b16 {%0,%1,%2,%3}, [%4];"
        : "=r"(r0), "=r"(r1), "=r"(r2), "=r"(r3) : "r"(addr));
}
__device__ __forceinline__ void ldsm4t(unsigned &r0, unsigned &r1, unsigned &r2, unsigned &r3, unsigned addr) {
    asm volatile("ldmatrix.sync.aligned.m8n8.x4.trans.shared.b16 {%0,%1,%2,%3}, [%4];"
        : "=r"(r0), "=r"(r1), "=r"(r2), "=r"(r3) : "r"(addr));
}
__device__ __forceinline__ void cpa16(unsigned dst, const void* src) {
    asm volatile("cp.async.cg.shared.global [%0], [%1], 16;" :: "r"(dst), "l"(src));
}
__device__ __forceinline__ void cpa_commit() {
    asm volatile("cp.async.commit_group;");
}
__device__ __forceinline__ float ex2(float x) {
    float r; asm("ex2.approx.ftz.f32 %0, %1;" : "=f"(r) : "f"(x)); return r;
}
__device__ __forceinline__ float wsum(float v) {
    #pragma unroll
    for (int o = 16; o > 0; o >>= 1) v += __shfl_xor_sync(0xffffffffu, v, o);
    return v;
}

#define L2E 1.4426950408889634f

// ---------------- fused prep: weight pack + bias pack + LN --------------------
__global__ __launch_bounds__(256) void prep(
    const float* __restrict__ x, const float* __restrict__ lng,
    const float* __restrict__ lnb,
    const float* __restrict__ Wq, const float* __restrict__ Wk,
    const float* __restrict__ Wv, const float* __restrict__ gW,
    const float* __restrict__ Wo, const float* __restrict__ mW,
    const float* __restrict__ rel)
{
    __shared__ float s[64][65];
    int bx = blockIdx.x, tid = threadIdx.x;
    if (bx < 96) {
        int w = bx >> 4, rem = bx & 15;
        int k0 = (rem >> 2) * 64, n0 = (rem & 3) * 64;
        const float* W;
        switch (w) {
            case 0: W = Wq; break; case 1: W = Wk; break; case 2: W = Wv; break;
            case 3: W = gW; break; case 4: W = Wo; break; default: W = mW; break;
        }
        for (int i = tid; i < 4096; i += 256) {
            int r = i >> 6, c = i & 63;
            s[r][c] = W[(size_t)(k0 + r)*EE + n0 + c];
        }
        __syncthreads();
        for (int i = tid; i < 2048; i += 256) {
            int n = i >> 5, kp = i & 31;
            g_wt[w][(n0 + n)*128 + k0/2 + kp] = pkh(s[2*kp][n], s[2*kp+1][n]);
        }
    } else if (bx < 1120) {
        int row = bx - 96;
        #pragma unroll
        for (int j = 0; j < 2; j++) {
            int i = tid + j*256;
            float2 v = *(const float2*)&rel[(size_t)row*SS + 2*i];
            g_rbh[row*512 + i] = pkh(v.x*L2E, v.y*L2E);
        }
    } else {
        int warp = tid >> 5, lane = tid & 31;
        int row = (bx - 1120)*8 + warp;
        const float* xr = x + (size_t)row*EE + lane*8;
        float4 a0 = *(const float4*)xr;
        float4 a1 = *(const float4*)(xr + 4);
        float xv[8] = {a0.x,a0.y,a0.z,a0.w,a1.x,a1.y,a1.z,a1.w};
        float sm = 0.f;
        #pragma unroll
        for (int i = 0; i < 8; i++) sm += xv[i];
        float mean = wsum(sm) * (1.f/EE);
        float vs = 0.f;
        #pragma unroll
        for (int i = 0; i < 8; i++) { float d = xv[i]-mean; vs += d*d; }
        float rstd = rsqrtf(wsum(vs)*(1.f/EE) + 1e-5f);
        float4 g0 = *(const float4*)(lng + lane*8);
        float4 g1 = *(const float4*)(lng + lane*8 + 4);
        float4 b0 = *(const float4*)(lnb + lane*8);
        float4 b1 = *(const float4*)(lnb + lane*8 + 4);
        float gg[8] = {g0.x,g0.y,g0.z,g0.w,g1.x,g1.y,g1.z,g1.w};
        float bb[8] = {b0.x,b0.y,b0.z,b0.w,b1.x,b1.y,b1.z,b1.w};
        float ln[8];
        #pragma unroll
        for (int i = 0; i < 8; i++) ln[i] = (xv[i]-mean)*rstd*gg[i] + bb[i];
        uint4 u, um;
        u.x = pkh(ln[0],ln[1]); u.y = pkh(ln[2],ln[3]);
        u.z = pkh(ln[4],ln[5]); u.w = pkh(ln[6],ln[7]);
        um.x = pkh(xv[0],xv[1]); um.y = pkh(xv[2],xv[3]);
        um.z = pkh(xv[4],xv[5]); um.w = pkh(xv[6],xv[7]);
        *(uint4*)&g_lnh[row*128 + lane*4] = u;
        *(uint4*)&g_mth[row*128 + lane*4] = um;
    }
}

// ---------------- fp16 GEMM (ops 0..4), 128x128, K-chunk 64, 3-stage ----------
// one barrier per chunk.  dyn smem: A[3] then B[3], stage = 128*GK*4 bytes.
__global__ __launch_bounds__(256, 2) void gemm_t(
    const float* __restrict__ bq, const float* __restrict__ bk,
    const float* __restrict__ bv, const float* __restrict__ gb,
    const float* __restrict__ bo, const float* __restrict__ Matrix, int op_base)
{
    extern __shared__ __align__(16) unsigned smem[];
    constexpr unsigned STG = 128*GK*4;       // 18432 B
    constexpr unsigned B_OFF = 3*STG;

    int op = op_base + blockIdx.z;
    const unsigned* Ah;
    const float* bias;
    switch (op) {
        case 0: Ah = g_lnh; bias = bq; break;
        case 1: Ah = g_lnh; bias = bk; break;
        case 2: Ah = g_lnh; bias = bv; break;
        case 3: Ah = g_mth; bias = gb; break;
        default: Ah = g_oph; bias = bo; break;
    }
    const unsigned* Wh = g_wt[op];

    int tid = threadIdx.x, lane = tid & 31, warp = tid >> 5;
    int wm = warp >> 1, wn = warp & 1;
    int g = lane >> 2, t = lane & 3;
    int m0 = blockIdx.y * 128, n0 = blockIdx.x * 128;

    unsigned s_u = (unsigned)__cvta_generic_to_shared(smem);
    int l16 = lane & 15, secA = lane >> 4;
    unsigned aFrag = s_u + (((wm*32 + l16)*GK) + secA*4)*4;
    int l8 = lane & 7, qd = lane >> 3;
    unsigned bFrag = (((wn*64 + (qd>>1)*8 + l8)*GK) + (qd&1)*4)*4;

    int arow[4], af4[4];
    #pragma unroll
    for (int j = 0; j < 4; j++) { int idx = tid + j*256; arow[j] = idx >> 3; af4[j] = idx & 7; }

    float acc[2][8][4];
    #pragma unroll
    for (int mt = 0; mt < 2; mt++)
        #pragma unroll
        for (int nt = 0; nt < 8; nt++)
            #pragma unroll
            for (int i = 0; i < 4; i++) acc[mt][nt][i] = 0.f;

    auto issue = [&](int ch, int bsel) {
        int cc = ch*32;
        #pragma unroll
        for (int j = 0; j < 4; j++) {
            unsigned d = (arow[j]*GK + af4[j]*4)*4;
            cpa16(s_u + bsel*STG + d, &Ah[(size_t)(m0 + arow[j])*128 + cc + af4[j]*4]);
            cpa16(s_u + B_OFF + bsel*STG + d, &Wh[(size_t)(n0 + arow[j])*128 + cc + af4[j]*4]);
        }
        cpa_commit();
    };

    issue(0, 0);
    issue(1, 1);

    #pragma unroll 1
    for (int c = 0; c < 4; c++) {
        if (c < 3) asm volatile("cp.async.wait_group 1;");
        else       asm volatile("cp.async.wait_group 0;");
        __syncthreads();                  // stage c visible AND all warps done with c-1
        if (c < 2) issue(c+2, (c+2) % 3); // ring-buffer modulo

        int bsel = c % 3;
        #pragma unroll
        for (int kk = 0; kk < 4; kk++) {
            unsigned a[2][4];
            #pragma unroll
            for (int mt = 0; mt < 2; mt++)
                ldsm4(a[mt][0], a[mt][1], a[mt][2], a[mt][3],
                      aFrag + bsel*STG + mt*(16*GK*4) + kk*32);
            #pragma unroll
            for (int pr = 0; pr < 4; pr++) {
                unsigned b0, b1, b2, b3;
                ldsm4(b0, b1, b2, b3,
                      s_u + B_OFF + bsel*STG + bFrag + pr*(16*GK*4) + kk*32);
                #pragma unroll
                for (int mt = 0; mt < 2; mt++) {
                    mmah(acc[mt][2*pr  ], a[mt][0], a[mt][1], a[mt][2], a[mt][3], b0, b1);
                    mmah(acc[mt][2*pr+1], a[mt][0], a[mt][1], a[mt][2], a[mt][3], b2, b3);
                }
            }
        }
    }

    const float qscale = 0.17677669529663687f * L2E;
    #pragma unroll
    for (int mt = 0; mt < 2; mt++) {
        int row0 = m0 + wm*32 + mt*16 + g;
        int row1 = row0 + 8;
        #pragma unroll
        for (int nt = 0; nt < 8; nt++) {
            int col = n0 + wn*64 + nt*8 + t*2;
            int cp  = col >> 1;
            float bv0 = bias[col], bv1 = bias[col+1];
            float v00 = acc[mt][nt][0] + bv0, v01 = acc[mt][nt][1] + bv1;
            float v10 = acc[mt][nt][2] + bv0, v11 = acc[mt][nt][3] + bv1;
            if (op == 0) {
                g_qph[row0*128 + cp] = pkh(v00*qscale, v01*qscale);
                g_qph[row1*128 + cp] = pkh(v10*qscale, v11*qscale);
            } else if (op == 1) {
                g_kph[row0*128 + cp] = pkh(v00, v01);
                g_kph[row1*128 + cp] = pkh(v10, v11);
            } else if (op == 2) {
                g_vph[row0*128 + cp] = pkh(v00, v01);
                g_vph[row1*128 + cp] = pkh(v10, v11);
            } else if (op == 3) {
                v00 = 1.f/(1.f + __expf(-v00)); v01 = 1.f/(1.f + __expf(-v01));
                v10 = 1.f/(1.f + __expf(-v10)); v11 = 1.f/(1.f + __expf(-v11));
                g_g0h[row0*128 + cp] = pkh(v00, v01);
                g_g0h[row1*128 + cp] = pkh(v10, v11);
            } else {  // op 4
                size_t i0 = (size_t)row0*EE + col, i1 = (size_t)row1*EE + col;
                float2 ga0 = up2(g_g0h[row0*128 + cp]);
                float2 ga1 = up2(g_g0h[row1*128 + cp]);
                float2 mx0 = *(const float2*)&Matrix[i0];
                float2 mx1 = *(const float2*)&Matrix[i1];
                v00 = ga0.x*v00 + mx0.x;  v01 = ga0.y*v01 + mx0.y;
                v10 = ga1.x*v10 + mx1.x;  v11 = ga1.y*v11 + mx1.y;
                *(float2*)&g_gate1[i0] = make_float2(v00, v01);
                *(float2*)&g_gate1[i1] = make_float2(v10, v11);
                g_g1h[row0*128 + cp] = pkh(v00, v01);
                g_g1h[row1*128 + cp] = pkh(v10, v11);
            }
        }
    }
}

// ---------------- fused mW GEMM + sigmoid + LN + gated output -----------------
// 64x256 block, K-chunk 64, 2-stage, one barrier per chunk.
__global__ __launch_bounds__(256, 2) void gemm_mlp(
    const float* __restrict__ mb, const float* __restrict__ lng,
    const float* __restrict__ lnb, float* __restrict__ out)
{
    extern __shared__ __align__(16) unsigned smem[];
    constexpr unsigned A_STG = 64*GK*4;      // 9216
    constexpr unsigned B_STG = 256*GK*4;     // 36864
    constexpr unsigned B_OFF = 2*A_STG;      // 18432
    const unsigned* Wh = g_wt[5];

    int tid = threadIdx.x, lane = tid & 31, warp = tid >> 5;
    int wm = warp >> 2, wn = warp & 3;
    int g = lane >> 2, t = lane & 3;
    int m0 = blockIdx.x * 64;

    unsigned s_u = (unsigned)__cvta_generic_to_shared(smem);
    int l16 = lane & 15, secA = lane >> 4;
    unsigned aFrag = s_u + (((wm*32 + l16)*GK) + secA*4)*4;
    int l8 = lane & 7, qd = lane >> 3;
    unsigned bFrag = (((wn*64 + (qd>>1)*8 + l8)*GK) + (qd&1)*4)*4;

    int arow[2], af4[2], brow[8], bf4[8];
    #pragma unroll
    for (int j = 0; j < 8; j++) {
        int idx = tid + j*256;
        brow[j] = idx >> 3; bf4[j] = idx & 7;
        if (j < 2) { arow[j] = idx >> 3; af4[j] = idx & 7; }
    }

    float acc[2][8][4];
    #pragma unroll
    for (int mt = 0; mt < 2; mt++)
        #pragma unroll
        for (int nt = 0; nt < 8; nt++)
            #pragma unroll
            for (int i = 0; i < 4; i++) acc[mt][nt][i] = 0.f;

    auto issue = [&](int ch, int bs) {
        int cc = ch*32;
        #pragma unroll
        for (int j = 0; j < 2; j++)
            cpa16(s_u + bs*A_STG + (arow[j]*GK + af4[j]*4)*4,
                  &g_g1h[(size_t)(m0 + arow[j])*128 + cc + af4[j]*4]);
        #pragma unroll
        for (int j = 0; j < 8; j++)
            cpa16(s_u + B_OFF + bs*B_STG + (brow[j]*GK + bf4[j]*4)*4,
                  &Wh[(size_t)brow[j]*128 + cc + bf4[j]*4]);
        cpa_commit();
    };

    issue(0, 0);

    #pragma unroll 1
    for (int c = 0; c < 4; c++) {
        asm volatile("cp.async.wait_group 0;");
        __syncthreads();
        if (c < 3) issue(c+1, (c+1) & 1);

        int bs = c & 1;
        #pragma unroll
        for (int kk = 0; kk < 4; kk++) {
            unsigned a[2][4];
            #pragma unroll
            for (int mt = 0; mt < 2; mt++)
                ldsm4(a[mt][0], a[mt][1], a[mt][2], a[mt][3],
                      aFrag + bs*A_STG + mt*(16*GK*4) + kk*32);
            #pragma unroll
            for (int pr = 0; pr < 4; pr++) {
                unsigned b0, b1, b2, b3;
                ldsm4(b0, b1, b2, b3,
                      s_u + B_OFF + bs*B_STG + bFrag + pr*(16*GK*4) + kk*32);
                #pragma unroll
                for (int mt = 0; mt < 2; mt++) {
                    mmah(acc[mt][2*pr  ], a[mt][0], a[mt][1], a[mt][2], a[mt][3], b0, b1);
                    mmah(acc[mt][2*pr+1], a[mt][0], a[mt][1], a[mt][2], a[mt][3], b2, b3);
                }
            }
        }
    }
    __syncthreads();   // protect reduction scratch region reuse

    // ---- epilogue: sigmoid + per-row LN + gated output ----
    float* sS = (float*)&smem[23040];   // byte 92160
    float* sQ = sS + 256;

    float psum[2][2] = {{0,0},{0,0}}, psq[2][2] = {{0,0},{0,0}};
    #pragma unroll
    for (int mt = 0; mt < 2; mt++) {
        #pragma unroll
        for (int nt = 0; nt < 8; nt++) {
            int col = wn*64 + nt*8 + t*2;
            float bv0 = mb[col], bv1 = mb[col+1];
            float v00 = 1.f/(1.f + __expf(-(acc[mt][nt][0] + bv0)));
            float v01 = 1.f/(1.f + __expf(-(acc[mt][nt][1] + bv1)));
            float v10 = 1.f/(1.f + __expf(-(acc[mt][nt][2] + bv0)));
            float v11 = 1.f/(1.f + __expf(-(acc[mt][nt][3] + bv1)));
            acc[mt][nt][0] = v00; acc[mt][nt][1] = v01;
            acc[mt][nt][2] = v10; acc[mt][nt][3] = v11;
            psum[mt][0] += v00 + v01;  psq[mt][0] += v00*v00 + v01*v01;
            psum[mt][1] += v10 + v11;  psq[mt][1] += v10*v10 + v11*v11;
        }
    }
    #pragma unroll
    for (int mt = 0; mt < 2; mt++)
        #pragma unroll
        for (int hf = 0; hf < 2; hf++) {
            float s = psum[mt][hf], q = psq[mt][hf];
            s += __shfl_xor_sync(0xffffffffu, s, 1);
            s += __shfl_xor_sync(0xffffffffu, s, 2);
            q += __shfl_xor_sync(0xffffffffu, q, 1);
            q += __shfl_xor_sync(0xffffffffu, q, 2);
            psum[mt][hf] = s; psq[mt][hf] = q;
        }
    if (t == 0) {
        #pragma unroll
        for (int mt = 0; mt < 2; mt++)
            #pragma unroll
            for (int hf = 0; hf < 2; hf++) {
                int r = wm*32 + mt*16 + g + hf*8;
                sS[r*4 + wn] = psum[mt][hf];
                sQ[r*4 + wn] = psq[mt][hf];
            }
    }
    __syncthreads();

    float mean[2][2], rstd[2][2];
    #pragma unroll
    for (int mt = 0; mt < 2; mt++)
        #pragma unroll
        for (int hf = 0; hf < 2; hf++) {
            int r = wm*32 + mt*16 + g + hf*8;
            float s = sS[r*4+0] + sS[r*4+1] + sS[r*4+2] + sS[r*4+3];
            float q = sQ[r*4+0] + sQ[r*4+1] + sQ[r*4+2] + sQ[r*4+3];
            float m = s * (1.f/EE);
            float v = q * (1.f/EE) - m*m;
            mean[mt][hf] = m;
            rstd[mt][hf] = rsqrtf(v + 1e-5f);
        }

    #pragma unroll
    for (int mt = 0; mt < 2; mt++) {
        int row0 = m0 + wm*32 + mt*16 + g;
        int row1 = row0 + 8;
        #pragma unroll
        for (int nt = 0; nt < 8; nt++) {
            int col = wn*64 + nt*8 + t*2;
            float2 gm = *(const float2*)&lng[col];
            float2 bt = *(const float2*)&lnb[col];
            size_t i0 = (size_t)row0*EE + col, i1 = (size_t)row1*EE + col;
            float2 g10 = *(const float2*)&g_gate1[i0];
            float2 g11 = *(const float2*)&g_gate1[i1];
            float ln00 = (acc[mt][nt][0] - mean[mt][0])*rstd[mt][0]*gm.x + bt.x;
            float ln01 = (acc[mt][nt][1] - mean[mt][0])*rstd[mt][0]*gm.y + bt.y;
            float ln10 = (acc[mt][nt][2] - mean[mt][1])*rstd[mt][1]*gm.x + bt.x;
            float ln11 = (acc[mt][nt][3] - mean[mt][1])*rstd[mt][1]*gm.y + bt.y;
            *(float2*)&out[i0] = make_float2(g10.x*(ln00+1.f), g10.y*(ln01+1.f));
            *(float2*)&out[i1] = make_float2(g11.x*(ln10+1.f), g11.y*(ln11+1.f));
        }
    }
}

// ---------------- head-paired fp16 flash attention, 3-stage, 1 barrier/tile ---
#define AP 36
__global__ __launch_bounds__(256, 2) void attn_h2()
{
    extern __shared__ __align__(16) unsigned smem[];
    const unsigned KBUF = 64*AP*4;        // 9216 B per stage

    int tid = threadIdx.x, lane = tid & 31, wq = tid >> 5;
    int g = lane >> 2, t = lane & 3;
    int bhp = blockIdx.x;
    int b = bhp >> 2, hp = bhp & 3;
    int q0 = blockIdx.y * 128;

    int r0 = q0 + wq*16 + g;
    int qrow0 = b*SS + r0, qrow1 = qrow0 + 8;

    unsigned sK_u = (unsigned)__cvta_generic_to_shared(smem);
    unsigned sV_u = sK_u + 3*KBUF;
    int l8 = lane & 7, qd = lane >> 3;
    unsigned kBase = sK_u + (((qd>>1)*8 + l8)*AP + (qd&1)*4)*4;
    unsigned vBase = sV_u + (((qd&1)*8 + l8)*AP)*4 + (qd>>1)*16;

    unsigned qhf[2][2][4];
    #pragma unroll
    for (int h = 0; h < 2; h++)
        #pragma unroll
        for (int kk = 0; kk < 2; kk++) {
            int base = hp*32 + h*16 + kk*8 + t;
            int b0 = qrow0*128 + base, b1 = qrow1*128 + base;
            qhf[h][kk][0] = g_qph[b0]; qhf[h][kk][1] = g_qph[b1];
            qhf[h][kk][2] = g_qph[b0+4]; qhf[h][kk][3] = g_qph[b1+4];
        }

    float O[2][4][4];
    #pragma unroll
    for (int h = 0; h < 2; h++)
        #pragma unroll
        for (int dn = 0; dn < 4; dn++)
            #pragma unroll
            for (int i = 0; i < 4; i++) O[h][dn][i] = 0.f;
    float ms0[2] = {-1e30f,-1e30f}, ms1[2] = {-1e30f,-1e30f};
    float ls0[2] = {0.f,0.f}, ls1[2] = {0.f,0.f};

    int lrow[2], lf[2];
    #pragma unroll
    for (int j = 0; j < 2; j++) { int idx = tid + j*256; lrow[j] = idx >> 3; lf[j] = idx & 7; }

    auto issue = [&](int kt, int bs) {
        #pragma unroll
        for (int j = 0; j < 2; j++) {
            size_t src = (size_t)(b*SS + kt*64 + lrow[j])*128 + hp*32 + lf[j]*4;
            unsigned d = (lrow[j]*AP + lf[j]*4)*4;
            cpa16(sK_u + bs*KBUF + d, &g_kph[src]);
            cpa16(sV_u + bs*KBUF + d, &g_vph[src]);
        }
        cpa_commit();
    };
    issue(0, 0);
    issue(1, 1);

    const unsigned ONE2 = 0x3C003C00u;

    #pragma unroll 1
    for (int kt = 0; kt < 16; kt++) {
        if (kt < 15) asm volatile("cp.async.wait_group 1;");
        else         asm volatile("cp.async.wait_group 0;");
        __syncthreads();
        if (kt < 14) issue(kt+2, (kt+2) % 3);
        int bsel = kt % 3;

        unsigned bf[8][2];
        #pragma unroll
        for (int nt = 0; nt < 8; nt++) {
            int pc = kt*32 + nt*4 + t;
            bf[nt][0] = g_rbh[r0*512 + pc];
            bf[nt][1] = g_rbh[(r0+8)*512 + pc];
        }

        #pragma unroll
        for (int h = 0; h < 2; h++) {
            float S_[8][4];
            #pragma unroll
            for (int nt = 0; nt < 8; nt++)
                #pragma unroll
                for (int i = 0; i < 4; i++) S_[nt][i] = 0.f;
            #pragma unroll
            for (int kk = 0; kk < 2; kk++) {
                #pragma unroll
                for (int p = 0; p < 4; p++) {
                    unsigned k0r, k1r, k2r, k3r;
                    ldsm4(k0r, k1r, k2r, k3r,
                          kBase + h*64 + bsel*KBUF + p*(16*AP*4) + kk*32);
                    mmah(S_[2*p  ], qhf[h][kk][0], qhf[h][kk][1], qhf[h][kk][2], qhf[h][kk][3], k0r, k1r);
                    mmah(S_[2*p+1], qhf[h][kk][0], qhf[h][kk][1], qhf[h][kk][2], qhf[h][kk][3], k2r, k3r);
                }
            }
            #pragma unroll
            for (int nt = 0; nt < 8; nt++) {
                float2 b0v = up2(bf[nt][0]);
                float2 b1v = up2(bf[nt][1]);
                S_[nt][0] += b0v.x; S_[nt][1] += b0v.y;
                S_[nt][2] += b1v.x; S_[nt][3] += b1v.y;
            }

            float tm0 = -1e30f, tm1 = -1e30f;
            #pragma unroll
            for (int nt = 0; nt < 8; nt++) {
                tm0 = fmaxf(tm0, fmaxf(S_[nt][0], S_[nt][1]));
                tm1 = fmaxf(tm1, fmaxf(S_[nt][2], S_[nt][3]));
            }
            tm0 = fmaxf(tm0, __shfl_xor_sync(0xffffffffu, tm0, 1));
            tm0 = fmaxf(tm0, __shfl_xor_sync(0xffffffffu, tm0, 2));
            tm1 = fmaxf(tm1, __shfl_xor_sync(0xffffffffu, tm1, 1));
            tm1 = fmaxf(tm1, __shfl_xor_sync(0xffffffffu, tm1, 2));
            float nm0 = fmaxf(ms0[h], tm0), nm1 = fmaxf(ms1[h], tm1);
            float sc0 = ex2(ms0[h] - nm0), sc1 = ex2(ms1[h] - nm1);

            unsigned pf[8][2];
            #pragma unroll
            for (int nt = 0; nt < 8; nt++) {
                __half2 d0 = __floats2half2_rn(S_[nt][0] - nm0, S_[nt][1] - nm0);
                __half2 d1 = __floats2half2_rn(S_[nt][2] - nm1, S_[nt][3] - nm1);
                __half2 p0 = h2exp2(d0);
                __half2 p1 = h2exp2(d1);
                pf[nt][0] = *reinterpret_cast<unsigned*>(&p0);
                pf[nt][1] = *reinterpret_cast<unsigned*>(&p1);
            }

            float rsA[4] = {0.f, 0.f, 0.f, 0.f};
            #pragma unroll
            for (int kk = 0; kk < 4; kk++)
                mmah(rsA, pf[2*kk][0], pf[2*kk][1], pf[2*kk+1][0], pf[2*kk+1][1], ONE2, ONE2);
            ls0[h] = ls0[h]*sc0 + rsA[0];
            ls1[h] = ls1[h]*sc1 + rsA[2];
            ms0[h] = nm0;  ms1[h] = nm1;
            #pragma unroll
            for (int dn = 0; dn < 4; dn++) {
                O[h][dn][0] *= sc0; O[h][dn][1] *= sc0;
                O[h][dn][2] *= sc1; O[h][dn][3] *= sc1;
            }

            #pragma unroll
            for (int kk = 0; kk < 4; kk++) {
                unsigned a0 = pf[2*kk][0], a1 = pf[2*kk][1];
                unsigned a2 = pf[2*kk+1][0], a3 = pf[2*kk+1][1];
                #pragma unroll
                for (int p = 0; p < 2; p++) {
                    unsigned v0, v1, v2, v3;
                    ldsm4t(v0, v1, v2, v3,
                           vBase + h*64 + bsel*KBUF + kk*(16*AP*4) + p*32);
                    mmah(O[h][2*p  ], a0, a1, a2, a3, v0, v1);
                    mmah(O[h][2*p+1], a0, a1, a2, a3, v2, v3);
                }
            }
        }
    }

    #pragma unroll
    for (int h = 0; h < 2; h++) {
        int hd = hp*2 + h;
        float il0 = 1.f/ls0[h], il1 = 1.f/ls1[h];
        #pragma unroll
        for (int dn = 0; dn < 4; dn++) {
            int cp = hd*16 + dn*4 + t;
            g_oph[qrow0*128 + cp] = pkh(O[h][dn][0]*il0, O[h][dn][1]*il0);
            g_oph[qrow1*128 + cp] = pkh(O[h][dn][2]*il1, O[h][dn][3]*il1);
        }
    }
}

// ---------------- launch ------------------------------------------------------
extern "C" void kernel_launch(void* const* d_in, const int* in_sizes, int n_in,
                              void* d_out, int out_size)
{
    const float* Matrix = (const float*)d_in[0];
    const float* ln_g   = (const float*)d_in[1];
    const float* ln_b   = (const float*)d_in[2];
    const float* Wq     = (const float*)d_in[3];
    const float* bq     = (const float*)d_in[4];
    const float* Wk     = (const float*)d_in[5];
    const float* bk     = (const float*)d_in[6];
    const float* Wv     = (const float*)d_in[7];
    const float* bv     = (const float*)d_in[8];
    const float* Wo     = (const float*)d_in[9];
    const float* bo     = (const float*)d_in[10];
    const float* rel    = (const float*)d_in[11];
    const float* gW     = (const float*)d_in[12];
    const float* gb     = (const float*)d_in[13];
    const float* mW     = (const float*)d_in[14];
    const float* mb     = (const float*)d_in[15];
    float* out = (float*)d_out;

    const int SM1 = 6*(128*GK*4);                     // 110592
    const int SMM = 2*(64*GK*4 + 256*GK*4) + 2048;    // 94208
    const int SMA = 6*(64*AP*4);                      // 55296
    static bool attr_set = false;
    if (!attr_set) {
        cudaFuncSetAttribute(gemm_t, cudaFuncAttributeMaxDynamicSharedMemorySize, SM1);
        cudaFuncSetAttribute(gemm_mlp, cudaFuncAttributeMaxDynamicSharedMemorySize, SMM);
        cudaFuncSetAttribute(attn_h2, cudaFuncAttributeMaxDynamicSharedMemorySize, SMA);
        attr_set = true;
    }

    prep<<<3168, 256>>>(Matrix, ln_g, ln_b, Wq, Wk, Wv, gW, Wo, mW, rel);

    gemm_t<<<dim3(2,128,4), 256, SM1>>>(bq, bk, bv, gb, bo, Matrix, 0);
    attn_h2<<<dim3(64,8), 256, SMA>>>();
    gemm_t<<<dim3(2,128,1), 256, SM1>>>(bq, bk, bv, gb, bo, Matrix, 4);
    gemm_mlp<<<256, 256, SMM>>>(mb, ln_g, ln_b, out);
}

// round 15
// speedup vs baseline: 1.3360x; 1.0100x over previous
#include <cuda_runtime.h>
#include <cuda_fp16.h>
#include <math.h>

#define BB 16
#define SS 1024
#define EE 256
#define HH 8
#define DHD 32
#define MROWS (BB*SS)   // 16384
#define GK 36           // smem pitch (uints) for K=64 chunks: 32 data + 4 pad

// ---------------- scratch ----------------------------------------------------
__device__ unsigned g_wt[6][256*128];        // weight hi planes [n][kpair]
__device__ unsigned g_rbh[SS*512];           // rel_bias * log2e, fp16 pairs
__device__ unsigned g_lnh[MROWS*128];
__device__ unsigned g_mth[MROWS*128];
__device__ unsigned g_qph[MROWS*128];        // pre-scaled by log2e/sqrt(DH)
__device__ unsigned g_kph[MROWS*128];
__device__ unsigned g_vph[MROWS*128];
__device__ unsigned g_oph[MROWS*128];
__device__ unsigned g_g0h[MROWS*128];        // gate0 fp16 pairs
__device__ unsigned g_g1h[MROWS*128];
__device__ float g_gate1[MROWS*EE];

// ---------------- helpers -----------------------------------------------------
__device__ __forceinline__ unsigned pkh(float a, float b) {
    __half2 t = __floats2half2_rn(a, b);
    return *reinterpret_cast<unsigned*>(&t);
}
__device__ __forceinline__ float2 up2(unsigned u) {
    return __half22float2(*reinterpret_cast<__half2*>(&u));
}
__device__ __forceinline__ void mmah(float* c,
    unsigned a0, unsigned a1, unsigned a2, unsigned a3,
    unsigned b0, unsigned b1)
{
    asm volatile(
        "mma.sync.aligned.m16n8k16.row.col.f32.f16.f16.f32 "
        "{%0,%1,%2,%3},{%4,%5,%6,%7},{%8,%9},{%0,%1,%2,%3};"
        : "+f"(c[0]), "+f"(c[1]), "+f"(c[2]), "+f"(c[3])
        : "r"(a0), "r"(a1), "r"(a2), "r"(a3), "r"(b0), "r"(b1));
}
__device__ __forceinline__ void ldsm4(unsigned &r0, unsigned &r1, unsigned &r2, unsigned &r3, unsigned addr) {
    asm volatile("ldmatrix.sync.aligned.m8n8.x4.shared.b16 {%0,%1,%2,%3}, [%4];"
        : "=r"(r0), "=r"(r1), "=r"(r2), "=r"(r3) : "r"(addr));
}
__device__ __forceinline__ void ldsm4t(unsigned &r0, unsigned &r1, unsigned &r2, unsigned &r3, unsigned addr) {
    asm volatile("ldmatrix.sync.aligned.m8n8.x4.trans.shared.b16 {%0,%1,%2,%3}, [%4];"
        : "=r"(r0), "=r"(r1), "=r"(r2), "=r"(r3) : "r"(addr));
}
__device__ __forceinline__ void cpa16(unsigned dst, const void* src) {
    asm volatile("cp.async.cg.shared.global [%0], [%1], 16;" :: "r"(dst), "l"(src));
}
__device__ __forceinline__ void cpa_commit() {
    asm volatile("cp.async.commit_group;");
}
__device__ __forceinline__ float ex2(float x) {
    float r; asm("ex2.approx.ftz.f32 %0, %1;" : "=f"(r) : "f"(x)); return r;
}
__device__ __forceinline__ float wsum(float v) {
    #pragma unroll
    for (int o = 16; o > 0; o >>= 1) v += __shfl_xor_sync(0xffffffffu, v, o);
    return v;
}

#define L2E 1.4426950408889634f

// ---------------- fused prep: weight pack + bias pack + LN --------------------
__global__ __launch_bounds__(256) void prep(
    const float* __restrict__ x, const float* __restrict__ lng,
    const float* __restrict__ lnb,
    const float* __restrict__ Wq, const float* __restrict__ Wk,
    const float* __restrict__ Wv, const float* __restrict__ gW,
    const float* __restrict__ Wo, const float* __restrict__ mW,
    const float* __restrict__ rel)
{
    __shared__ float s[64][65];
    int bx = blockIdx.x, tid = threadIdx.x;
    if (bx < 96) {
        int w = bx >> 4, rem = bx & 15;
        int k0 = (rem >> 2) * 64, n0 = (rem & 3) * 64;
        const float* W;
        switch (w) {
            case 0: W = Wq; break; case 1: W = Wk; break; case 2: W = Wv; break;
            case 3: W = gW; break; case 4: W = Wo; break; default: W = mW; break;
        }
        for (int i = tid; i < 4096; i += 256) {
            int r = i >> 6, c = i & 63;
            s[r][c] = W[(size_t)(k0 + r)*EE + n0 + c];
        }
        __syncthreads();
        for (int i = tid; i < 2048; i += 256) {
            int n = i >> 5, kp = i & 31;
            g_wt[w][(n0 + n)*128 + k0/2 + kp] = pkh(s[2*kp][n], s[2*kp+1][n]);
        }
    } else if (bx < 1120) {
        int row = bx - 96;
        #pragma unroll
        for (int j = 0; j < 2; j++) {
            int i = tid + j*256;
            float2 v = *(const float2*)&rel[(size_t)row*SS + 2*i];
            g_rbh[row*512 + i] = pkh(v.x*L2E, v.y*L2E);
        }
    } else {
        int warp = tid >> 5, lane = tid & 31;
        int row = (bx - 1120)*8 + warp;
        const float* xr = x + (size_t)row*EE + lane*8;
        float4 a0 = *(const float4*)xr;
        float4 a1 = *(const float4*)(xr + 4);
        float xv[8] = {a0.x,a0.y,a0.z,a0.w,a1.x,a1.y,a1.z,a1.w};
        float sm = 0.f;
        #pragma unroll
        for (int i = 0; i < 8; i++) sm += xv[i];
        float mean = wsum(sm) * (1.f/EE);
        float vs = 0.f;
        #pragma unroll
        for (int i = 0; i < 8; i++) { float d = xv[i]-mean; vs += d*d; }
        float rstd = rsqrtf(wsum(vs)*(1.f/EE) + 1e-5f);
        float4 g0 = *(const float4*)(lng + lane*8);
        float4 g1 = *(const float4*)(lng + lane*8 + 4);
        float4 b0 = *(const float4*)(lnb + lane*8);
        float4 b1 = *(const float4*)(lnb + lane*8 + 4);
        float gg[8] = {g0.x,g0.y,g0.z,g0.w,g1.x,g1.y,g1.z,g1.w};
        float bb[8] = {b0.x,b0.y,b0.z,b0.w,b1.x,b1.y,b1.z,b1.w};
        float ln[8];
        #pragma unroll
        for (int i = 0; i < 8; i++) ln[i] = (xv[i]-mean)*rstd*gg[i] + bb[i];
        uint4 u, um;
        u.x = pkh(ln[0],ln[1]); u.y = pkh(ln[2],ln[3]);
        u.z = pkh(ln[4],ln[5]); u.w = pkh(ln[6],ln[7]);
        um.x = pkh(xv[0],xv[1]); um.y = pkh(xv[2],xv[3]);
        um.z = pkh(xv[4],xv[5]); um.w = pkh(xv[6],xv[7]);
        *(uint4*)&g_lnh[row*128 + lane*4] = u;
        *(uint4*)&g_mth[row*128 + lane*4] = um;
    }
}

// ---------------- fp16 GEMM (ops 0..4): 128x64 tile, K-chunk 64, 2-stage ------
// 3 blocks/SM target.  dyn smem: A[2] (18432B ea) then B[2] (9216B ea).
__global__ __launch_bounds__(256, 3) void gemm_t(
    const float* __restrict__ bq, const float* __restrict__ bk,
    const float* __restrict__ bv, const float* __restrict__ gb,
    const float* __restrict__ bo, const float* __restrict__ Matrix, int op_base)
{
    extern __shared__ __align__(16) unsigned smem[];
    constexpr unsigned A_STG = 128*GK*4;     // 18432 B
    constexpr unsigned B_STG = 64*GK*4;      // 9216 B
    constexpr unsigned B_OFF = 2*A_STG;      // 36864

    int op = op_base + blockIdx.z;
    const unsigned* Ah;
    const float* bias;
    switch (op) {
        case 0: Ah = g_lnh; bias = bq; break;
        case 1: Ah = g_lnh; bias = bk; break;
        case 2: Ah = g_lnh; bias = bv; break;
        case 3: Ah = g_mth; bias = gb; break;
        default: Ah = g_oph; bias = bo; break;
    }
    const unsigned* Wh = g_wt[op];

    int tid = threadIdx.x, lane = tid & 31, warp = tid >> 5;
    int wm = warp >> 1, wn = warp & 1;       // 4m x 2n, warp tile 32x32
    int g = lane >> 2, t = lane & 3;
    int m0 = blockIdx.y * 128, n0 = blockIdx.x * 64;

    unsigned s_u = (unsigned)__cvta_generic_to_shared(smem);
    int l16 = lane & 15, secA = lane >> 4;
    unsigned aFrag = s_u + (((wm*32 + l16)*GK) + secA*4)*4;
    int l8 = lane & 7, qd = lane >> 3;
    unsigned bFrag = (((wn*32 + (qd>>1)*8 + l8)*GK) + (qd&1)*4)*4;

    // A chunk: 128 rows x 8 uint4 -> 4 per thread; B chunk: 64 rows -> 2 per thread
    int arow[4], af4[4];
    #pragma unroll
    for (int j = 0; j < 4; j++) { int idx = tid + j*256; arow[j] = idx >> 3; af4[j] = idx & 7; }

    float acc[2][4][4];
    #pragma unroll
    for (int mt = 0; mt < 2; mt++)
        #pragma unroll
        for (int nt = 0; nt < 4; nt++)
            #pragma unroll
            for (int i = 0; i < 4; i++) acc[mt][nt][i] = 0.f;

    auto issue = [&](int ch, int bs) {
        int cc = ch*32;
        #pragma unroll
        for (int j = 0; j < 4; j++)
            cpa16(s_u + bs*A_STG + (arow[j]*GK + af4[j]*4)*4,
                  &Ah[(size_t)(m0 + arow[j])*128 + cc + af4[j]*4]);
        #pragma unroll
        for (int j = 0; j < 2; j++)
            cpa16(s_u + B_OFF + bs*B_STG + (arow[j]*GK + af4[j]*4)*4,
                  &Wh[(size_t)(n0 + arow[j])*128 + cc + af4[j]*4]);
        cpa_commit();
    };

    issue(0, 0);

    #pragma unroll 1
    for (int c = 0; c < 4; c++) {
        asm volatile("cp.async.wait_group 0;");
        __syncthreads();                   // chunk c visible; all warps done with c-1
        if (c < 3) issue(c+1, (c+1) & 1);  // overwrites buffer read at c-1: safe

        int bs = c & 1;
        #pragma unroll
        for (int kk = 0; kk < 4; kk++) {
            unsigned a[2][4];
            #pragma unroll
            for (int mt = 0; mt < 2; mt++)
                ldsm4(a[mt][0], a[mt][1], a[mt][2], a[mt][3],
                      aFrag + bs*A_STG + mt*(16*GK*4) + kk*32);
            #pragma unroll
            for (int pr = 0; pr < 2; pr++) {
                unsigned b0, b1, b2, b3;
                ldsm4(b0, b1, b2, b3,
                      s_u + B_OFF + bs*B_STG + bFrag + pr*(16*GK*4) + kk*32);
                #pragma unroll
                for (int mt = 0; mt < 2; mt++) {
                    mmah(acc[mt][2*pr  ], a[mt][0], a[mt][1], a[mt][2], a[mt][3], b0, b1);
                    mmah(acc[mt][2*pr+1], a[mt][0], a[mt][1], a[mt][2], a[mt][3], b2, b3);
                }
            }
        }
    }

    const float qscale = 0.17677669529663687f * L2E;
    #pragma unroll
    for (int mt = 0; mt < 2; mt++) {
        int row0 = m0 + wm*32 + mt*16 + g;
        int row1 = row0 + 8;
        #pragma unroll
        for (int nt = 0; nt < 4; nt++) {
            int col = n0 + wn*32 + nt*8 + t*2;
            int cp  = col >> 1;
            float bv0 = bias[col], bv1 = bias[col+1];
            float v00 = acc[mt][nt][0] + bv0, v01 = acc[mt][nt][1] + bv1;
            float v10 = acc[mt][nt][2] + bv0, v11 = acc[mt][nt][3] + bv1;
            if (op == 0) {
                g_qph[row0*128 + cp] = pkh(v00*qscale, v01*qscale);
                g_qph[row1*128 + cp] = pkh(v10*qscale, v11*qscale);
            } else if (op == 1) {
                g_kph[row0*128 + cp] = pkh(v00, v01);
                g_kph[row1*128 + cp] = pkh(v10, v11);
            } else if (op == 2) {
                g_vph[row0*128 + cp] = pkh(v00, v01);
                g_vph[row1*128 + cp] = pkh(v10, v11);
            } else if (op == 3) {
                v00 = 1.f/(1.f + __expf(-v00)); v01 = 1.f/(1.f + __expf(-v01));
                v10 = 1.f/(1.f + __expf(-v10)); v11 = 1.f/(1.f + __expf(-v11));
                g_g0h[row0*128 + cp] = pkh(v00, v01);
                g_g0h[row1*128 + cp] = pkh(v10, v11);
            } else {  // op 4
                size_t i0 = (size_t)row0*EE + col, i1 = (size_t)row1*EE + col;
                float2 ga0 = up2(g_g0h[row0*128 + cp]);
                float2 ga1 = up2(g_g0h[row1*128 + cp]);
                float2 mx0 = *(const float2*)&Matrix[i0];
                float2 mx1 = *(const float2*)&Matrix[i1];
                v00 = ga0.x*v00 + mx0.x;  v01 = ga0.y*v01 + mx0.y;
                v10 = ga1.x*v10 + mx1.x;  v11 = ga1.y*v11 + mx1.y;
                *(float2*)&g_gate1[i0] = make_float2(v00, v01);
                *(float2*)&g_gate1[i1] = make_float2(v10, v11);
                g_g1h[row0*128 + cp] = pkh(v00, v01);
                g_g1h[row1*128 + cp] = pkh(v10, v11);
            }
        }
    }
}

// ---------------- fused mW GEMM + sigmoid + LN + gated output -----------------
// 64x256 block, K-chunk 64, 2-stage, one barrier per chunk.
__global__ __launch_bounds__(256, 2) void gemm_mlp(
    const float* __restrict__ mb, const float* __restrict__ lng,
    const float* __restrict__ lnb, float* __restrict__ out)
{
    extern __shared__ __align__(16) unsigned smem[];
    constexpr unsigned A_STG = 64*GK*4;      // 9216
    constexpr unsigned B_STG = 256*GK*4;     // 36864
    constexpr unsigned B_OFF = 2*A_STG;      // 18432
    const unsigned* Wh = g_wt[5];

    int tid = threadIdx.x, lane = tid & 31, warp = tid >> 5;
    int wm = warp >> 2, wn = warp & 3;
    int g = lane >> 2, t = lane & 3;
    int m0 = blockIdx.x * 64;

    unsigned s_u = (unsigned)__cvta_generic_to_shared(smem);
    int l16 = lane & 15, secA = lane >> 4;
    unsigned aFrag = s_u + (((wm*32 + l16)*GK) + secA*4)*4;
    int l8 = lane & 7, qd = lane >> 3;
    unsigned bFrag = (((wn*64 + (qd>>1)*8 + l8)*GK) + (qd&1)*4)*4;

    int arow[2], af4[2], brow[8], bf4[8];
    #pragma unroll
    for (int j = 0; j < 8; j++) {
        int idx = tid + j*256;
        brow[j] = idx >> 3; bf4[j] = idx & 7;
        if (j < 2) { arow[j] = idx >> 3; af4[j] = idx & 7; }
    }

    float acc[2][8][4];
    #pragma unroll
    for (int mt = 0; mt < 2; mt++)
        #pragma unroll
        for (int nt = 0; nt < 8; nt++)
            #pragma unroll
            for (int i = 0; i < 4; i++) acc[mt][nt][i] = 0.f;

    auto issue = [&](int ch, int bs) {
        int cc = ch*32;
        #pragma unroll
        for (int j = 0; j < 2; j++)
            cpa16(s_u + bs*A_STG + (arow[j]*GK + af4[j]*4)*4,
                  &g_g1h[(size_t)(m0 + arow[j])*128 + cc + af4[j]*4]);
        #pragma unroll
        for (int j = 0; j < 8; j++)
            cpa16(s_u + B_OFF + bs*B_STG + (brow[j]*GK + bf4[j]*4)*4,
                  &Wh[(size_t)brow[j]*128 + cc + bf4[j]*4]);
        cpa_commit();
    };

    issue(0, 0);

    #pragma unroll 1
    for (int c = 0; c < 4; c++) {
        asm volatile("cp.async.wait_group 0;");
        __syncthreads();
        if (c < 3) issue(c+1, (c+1) & 1);

        int bs = c & 1;
        #pragma unroll
        for (int kk = 0; kk < 4; kk++) {
            unsigned a[2][4];
            #pragma unroll
            for (int mt = 0; mt < 2; mt++)
                ldsm4(a[mt][0], a[mt][1], a[mt][2], a[mt][3],
                      aFrag + bs*A_STG + mt*(16*GK*4) + kk*32);
            #pragma unroll
            for (int pr = 0; pr < 4; pr++) {
                unsigned b0, b1, b2, b3;
                ldsm4(b0, b1, b2, b3,
                      s_u + B_OFF + bs*B_STG + bFrag + pr*(16*GK*4) + kk*32);
                #pragma unroll
                for (int mt = 0; mt < 2; mt++) {
                    mmah(acc[mt][2*pr  ], a[mt][0], a[mt][1], a[mt][2], a[mt][3], b0, b1);
                    mmah(acc[mt][2*pr+1], a[mt][0], a[mt][1], a[mt][2], a[mt][3], b2, b3);
                }
            }
        }
    }
    __syncthreads();   // protect reduction scratch region reuse

    // ---- epilogue: sigmoid + per-row LN + gated output ----
    float* sS = (float*)&smem[23040];   // byte 92160
    float* sQ = sS + 256;

    float psum[2][2] = {{0,0},{0,0}}, psq[2][2] = {{0,0},{0,0}};
    #pragma unroll
    for (int mt = 0; mt < 2; mt++) {
        #pragma unroll
        for (int nt = 0; nt < 8; nt++) {
            int col = wn*64 + nt*8 + t*2;
            float bv0 = mb[col], bv1 = mb[col+1];
            float v00 = 1.f/(1.f + __expf(-(acc[mt][nt][0] + bv0)));
            float v01 = 1.f/(1.f + __expf(-(acc[mt][nt][1] + bv1)));
            float v10 = 1.f/(1.f + __expf(-(acc[mt][nt][2] + bv0)));
            float v11 = 1.f/(1.f + __expf(-(acc[mt][nt][3] + bv1)));
            acc[mt][nt][0] = v00; acc[mt][nt][1] = v01;
            acc[mt][nt][2] = v10; acc[mt][nt][3] = v11;
            psum[mt][0] += v00 + v01;  psq[mt][0] += v00*v00 + v01*v01;
            psum[mt][1] += v10 + v11;  psq[mt][1] += v10*v10 + v11*v11;
        }
    }
    #pragma unroll
    for (int mt = 0; mt < 2; mt++)
        #pragma unroll
        for (int hf = 0; hf < 2; hf++) {
            float s = psum[mt][hf], q = psq[mt][hf];
            s += __shfl_xor_sync(0xffffffffu, s, 1);
            s += __shfl_xor_sync(0xffffffffu, s, 2);
            q += __shfl_xor_sync(0xffffffffu, q, 1);
            q += __shfl_xor_sync(0xffffffffu, q, 2);
            psum[mt][hf] = s; psq[mt][hf] = q;
        }
    if (t == 0) {
        #pragma unroll
        for (int mt = 0; mt < 2; mt++)
            #pragma unroll
            for (int hf = 0; hf < 2; hf++) {
                int r = wm*32 + mt*16 + g + hf*8;
                sS[r*4 + wn] = psum[mt][hf];
                sQ[r*4 + wn] = psq[mt][hf];
            }
    }
    __syncthreads();

    float mean[2][2], rstd[2][2];
    #pragma unroll
    for (int mt = 0; mt < 2; mt++)
        #pragma unroll
        for (int hf = 0; hf < 2; hf++) {
            int r = wm*32 + mt*16 + g + hf*8;
            float s = sS[r*4+0] + sS[r*4+1] + sS[r*4+2] + sS[r*4+3];
            float q = sQ[r*4+0] + sQ[r*4+1] + sQ[r*4+2] + sQ[r*4+3];
            float m = s * (1.f/EE);
            float v = q * (1.f/EE) - m*m;
            mean[mt][hf] = m;
            rstd[mt][hf] = rsqrtf(v + 1e-5f);
        }

    #pragma unroll
    for (int mt = 0; mt < 2; mt++) {
        int row0 = m0 + wm*32 + mt*16 + g;
        int row1 = row0 + 8;
        #pragma unroll
        for (int nt = 0; nt < 8; nt++) {
            int col = wn*64 + nt*8 + t*2;
            float2 gm = *(const float2*)&lng[col];
            float2 bt = *(const float2*)&lnb[col];
            size_t i0 = (size_t)row0*EE + col, i1 = (size_t)row1*EE + col;
            float2 g10 = *(const float2*)&g_gate1[i0];
            float2 g11 = *(const float2*)&g_gate1[i1];
            float ln00 = (acc[mt][nt][0] - mean[mt][0])*rstd[mt][0]*gm.x + bt.x;
            float ln01 = (acc[mt][nt][1] - mean[mt][0])*rstd[mt][0]*gm.y + bt.y;
            float ln10 = (acc[mt][nt][2] - mean[mt][1])*rstd[mt][1]*gm.x + bt.x;
            float ln11 = (acc[mt][nt][3] - mean[mt][1])*rstd[mt][1]*gm.y + bt.y;
            *(float2*)&out[i0] = make_float2(g10.x*(ln00+1.f), g10.y*(ln01+1.f));
            *(float2*)&out[i1] = make_float2(g11.x*(ln10+1.f), g11.y*(ln11+1.f));
        }
    }
}

// ---------------- head-paired fp16 flash attention, 3-stage, 1 barrier/tile ---
#define AP 36
__global__ __launch_bounds__(256, 2) void attn_h2()
{
    extern __shared__ __align__(16) unsigned smem[];
    const unsigned KBUF = 64*AP*4;        // 9216 B per stage

    int tid = threadIdx.x, lane = tid & 31, wq = tid >> 5;
    int g = lane >> 2, t = lane & 3;
    int bhp = blockIdx.x;
    int b = bhp >> 2, hp = bhp & 3;
    int q0 = blockIdx.y * 128;

    int r0 = q0 + wq*16 + g;
    int qrow0 = b*SS + r0, qrow1 = qrow0 + 8;

    unsigned sK_u = (unsigned)__cvta_generic_to_shared(smem);
    unsigned sV_u = sK_u + 3*KBUF;
    int l8 = lane & 7, qd = lane >> 3;
    unsigned kBase = sK_u + (((qd>>1)*8 + l8)*AP + (qd&1)*4)*4;
    unsigned vBase = sV_u + (((qd&1)*8 + l8)*AP)*4 + (qd>>1)*16;

    unsigned qhf[2][2][4];
    #pragma unroll
    for (int h = 0; h < 2; h++)
        #pragma unroll
        for (int kk = 0; kk < 2; kk++) {
            int base = hp*32 + h*16 + kk*8 + t;
            int b0 = qrow0*128 + base, b1 = qrow1*128 + base;
            qhf[h][kk][0] = g_qph[b0]; qhf[h][kk][1] = g_qph[b1];
            qhf[h][kk][2] = g_qph[b0+4]; qhf[h][kk][3] = g_qph[b1+4];
        }

    float O[2][4][4];
    #pragma unroll
    for (int h = 0; h < 2; h++)
        #pragma unroll
        for (int dn = 0; dn < 4; dn++)
            #pragma unroll
            for (int i = 0; i < 4; i++) O[h][dn][i] = 0.f;
    float ms0[2] = {-1e30f,-1e30f}, ms1[2] = {-1e30f,-1e30f};
    float ls0[2] = {0.f,0.f}, ls1[2] = {0.f,0.f};

    int lrow[2], lf[2];
    #pragma unroll
    for (int j = 0; j < 2; j++) { int idx = tid + j*256; lrow[j] = idx >> 3; lf[j] = idx & 7; }

    auto issue = [&](int kt, int bs) {
        #pragma unroll
        for (int j = 0; j < 2; j++) {
            size_t src = (size_t)(b*SS + kt*64 + lrow[j])*128 + hp*32 + lf[j]*4;
            unsigned d = (lrow[j]*AP + lf[j]*4)*4;
            cpa16(sK_u + bs*KBUF + d, &g_kph[src]);
            cpa16(sV_u + bs*KBUF + d, &g_vph[src]);
        }
        cpa_commit();
    };
    issue(0, 0);
    issue(1, 1);

    const unsigned ONE2 = 0x3C003C00u;

    #pragma unroll 1
    for (int kt = 0; kt < 16; kt++) {
        if (kt < 15) asm volatile("cp.async.wait_group 1;");
        else         asm volatile("cp.async.wait_group 0;");
        __syncthreads();
        if (kt < 14) issue(kt+2, (kt+2) % 3);
        int bsel = kt % 3;

        unsigned bf[8][2];
        #pragma unroll
        for (int nt = 0; nt < 8; nt++) {
            int pc = kt*32 + nt*4 + t;
            bf[nt][0] = g_rbh[r0*512 + pc];
            bf[nt][1] = g_rbh[(r0+8)*512 + pc];
        }

        #pragma unroll
        for (int h = 0; h < 2; h++) {
            float S_[8][4];
            #pragma unroll
            for (int nt = 0; nt < 8; nt++)
                #pragma unroll
                for (int i = 0; i < 4; i++) S_[nt][i] = 0.f;
            #pragma unroll
            for (int kk = 0; kk < 2; kk++) {
                #pragma unroll
                for (int p = 0; p < 4; p++) {
                    unsigned k0r, k1r, k2r, k3r;
                    ldsm4(k0r, k1r, k2r, k3r,
                          kBase + h*64 + bsel*KBUF + p*(16*AP*4) + kk*32);
                    mmah(S_[2*p  ], qhf[h][kk][0], qhf[h][kk][1], qhf[h][kk][2], qhf[h][kk][3], k0r, k1r);
                    mmah(S_[2*p+1], qhf[h][kk][0], qhf[h][kk][1], qhf[h][kk][2], qhf[h][kk][3], k2r, k3r);
                }
            }
            #pragma unroll
            for (int nt = 0; nt < 8; nt++) {
                float2 b0v = up2(bf[nt][0]);
                float2 b1v = up2(bf[nt][1]);
                S_[nt][0] += b0v.x; S_[nt][1] += b0v.y;
                S_[nt][2] += b1v.x; S_[nt][3] += b1v.y;
            }

            float tm0 = -1e30f, tm1 = -1e30f;
            #pragma unroll
            for (int nt = 0; nt < 8; nt++) {
                tm0 = fmaxf(tm0, fmaxf(S_[nt][0], S_[nt][1]));
                tm1 = fmaxf(tm1, fmaxf(S_[nt][2], S_[nt][3]));
            }
            tm0 = fmaxf(tm0, __shfl_xor_sync(0xffffffffu, tm0, 1));
            tm0 = fmaxf(tm0, __shfl_xor_sync(0xffffffffu, tm0, 2));
            tm1 = fmaxf(tm1, __shfl_xor_sync(0xffffffffu, tm1, 1));
            tm1 = fmaxf(tm1, __shfl_xor_sync(0xffffffffu, tm1, 2));
            float nm0 = fmaxf(ms0[h], tm0), nm1 = fmaxf(ms1[h], tm1);
            float sc0 = ex2(ms0[h] - nm0), sc1 = ex2(ms1[h] - nm1);

            unsigned pf[8][2];
            #pragma unroll
            for (int nt = 0; nt < 8; nt++) {
                __half2 d0 = __floats2half2_rn(S_[nt][0] - nm0, S_[nt][1] - nm0);
                __half2 d1 = __floats2half2_rn(S_[nt][2] - nm1, S_[nt][3] - nm1);
                __half2 p0 = h2exp2(d0);
                __half2 p1 = h2exp2(d1);
                pf[nt][0] = *reinterpret_cast<unsigned*>(&p0);
                pf[nt][1] = *reinterpret_cast<unsigned*>(&p1);
            }

            float rsA[4] = {0.f, 0.f, 0.f, 0.f};
            #pragma unroll
            for (int kk = 0; kk < 4; kk++)
                mmah(rsA, pf[2*kk][0], pf[2*kk][1], pf[2*kk+1][0], pf[2*kk+1][1], ONE2, ONE2);
            ls0[h] = ls0[h]*sc0 + rsA[0];
            ls1[h] = ls1[h]*sc1 + rsA[2];
            ms0[h] = nm0;  ms1[h] = nm1;
            #pragma unroll
            for (int dn = 0; dn < 4; dn++) {
                O[h][dn][0] *= sc0; O[h][dn][1] *= sc0;
                O[h][dn][2] *= sc1; O[h][dn][3] *= sc1;
            }

            #pragma unroll
            for (int kk = 0; kk < 4; kk++) {
                unsigned a0 = pf[2*kk][0], a1 = pf[2*kk][1];
                unsigned a2 = pf[2*kk+1][0], a3 = pf[2*kk+1][1];
                #pragma unroll
                for (int p = 0; p < 2; p++) {
                    unsigned v0, v1, v2, v3;
                    ldsm4t(v0, v1, v2, v3,
                           vBase + h*64 + bsel*KBUF + kk*(16*AP*4) + p*32);
                    mmah(O[h][2*p  ], a0, a1, a2, a3, v0, v1);
                    mmah(O[h][2*p+1], a0, a1, a2, a3, v2, v3);
                }
            }
        }
    }

    #pragma unroll
    for (int h = 0; h < 2; h++) {
        int hd = hp*2 + h;
        float il0 = 1.f/ls0[h], il1 = 1.f/ls1[h];
        #pragma unroll
        for (int dn = 0; dn < 4; dn++) {
            int cp = hd*16 + dn*4 + t;
            g_oph[qrow0*128 + cp] = pkh(O[h][dn][0]*il0, O[h][dn][1]*il0);
            g_oph[qrow1*128 + cp] = pkh(O[h][dn][2]*il1, O[h][dn][3]*il1);
        }
    }
}

// ---------------- launch ------------------------------------------------------
extern "C" void kernel_launch(void* const* d_in, const int* in_sizes, int n_in,
                              void* d_out, int out_size)
{
    const float* Matrix = (const float*)d_in[0];
    const float* ln_g   = (const float*)d_in[1];
    const float* ln_b   = (const float*)d_in[2];
    const float* Wq     = (const float*)d_in[3];
    const float* bq     = (const float*)d_in[4];
    const float* Wk     = (const float*)d_in[5];
    const float* bk     = (const float*)d_in[6];
    const float* Wv     = (const float*)d_in[7];
    const float* bv     = (const float*)d_in[8];
    const float* Wo     = (const float*)d_in[9];
    const float* bo     = (const float*)d_in[10];
    const float* rel    = (const float*)d_in[11];
    const float* gW     = (const float*)d_in[12];
    const float* gb     = (const float*)d_in[13];
    const float* mW     = (const float*)d_in[14];
    const float* mb     = (const float*)d_in[15];
    float* out = (float*)d_out;

    const int SM1 = 2*(128*GK*4) + 2*(64*GK*4);       // 55296
    const int SMM = 2*(64*GK*4 + 256*GK*4) + 2048;    // 94208
    const int SMA = 6*(64*AP*4);                      // 55296
    static bool attr_set = false;
    if (!attr_set) {
        cudaFuncSetAttribute(gemm_t, cudaFuncAttributeMaxDynamicSharedMemorySize, SM1);
        cudaFuncSetAttribute(gemm_mlp, cudaFuncAttributeMaxDynamicSharedMemorySize, SMM);
        cudaFuncSetAttribute(attn_h2, cudaFuncAttributeMaxDynamicSharedMemorySize, SMA);
        attr_set = true;
    }

    prep<<<3168, 256>>>(Matrix, ln_g, ln_b, Wq, Wk, Wv, gW, Wo, mW, rel);

    gemm_t<<<dim3(4,128,4), 256, SM1>>>(bq, bk, bv, gb, bo, Matrix, 0);
    attn_h2<<<dim3(64,8), 256, SMA>>>();
    gemm_t<<<dim3(4,128,1), 256, SM1>>>(bq, bk, bv, gb, bo, Matrix, 4);
    gemm_mlp<<<256, 256, SMM>>>(mb, ln_g, ln_b, out);
}

// round 16
// speedup vs baseline: 1.3477x; 1.0088x over previous
#include <cuda_runtime.h>
#include <cuda_fp16.h>
#include <math.h>

#define BB 16
#define SS 1024
#define EE 256
#define HH 8
#define DHD 32
#define MROWS (BB*SS)   // 16384
#define GK 36           // smem pitch (uints) for K=64 chunks: 32 data + 4 pad

// ---------------- scratch ----------------------------------------------------
__device__ unsigned g_wt[6][256*128];        // weight hi planes [n][kpair]
__device__ unsigned g_rbh[SS*512];           // rel_bias * log2e, fp16 pairs
__device__ unsigned g_lnh[MROWS*128];
__device__ unsigned g_mth[MROWS*128];
__device__ unsigned g_qph[MROWS*128];        // pre-scaled by log2e/sqrt(DH)
__device__ unsigned g_kph[MROWS*128];
__device__ unsigned g_vph[MROWS*128];
__device__ unsigned g_oph[MROWS*128];
__device__ unsigned g_g0h[MROWS*128];        // gate0 fp16 pairs
__device__ unsigned g_g1h[MROWS*128];        // gate1 fp16 pairs (sole copy)

// ---------------- helpers -----------------------------------------------------
__device__ __forceinline__ unsigned pkh(float a, float b) {
    __half2 t = __floats2half2_rn(a, b);
    return *reinterpret_cast<unsigned*>(&t);
}
__device__ __forceinline__ float2 up2(unsigned u) {
    return __half22float2(*reinterpret_cast<__half2*>(&u));
}
__device__ __forceinline__ void mmah(float* c,
    unsigned a0, unsigned a1, unsigned a2, unsigned a3,
    unsigned b0, unsigned b1)
{
    asm volatile(
        "mma.sync.aligned.m16n8k16.row.col.f32.f16.f16.f32 "
        "{%0,%1,%2,%3},{%4,%5,%6,%7},{%8,%9},{%0,%1,%2,%3};"
        : "+f"(c[0]), "+f"(c[1]), "+f"(c[2]), "+f"(c[3])
        : "r"(a0), "r"(a1), "r"(a2), "r"(a3), "r"(b0), "r"(b1));
}
__device__ __forceinline__ void ldsm4(unsigned &r0, unsigned &r1, unsigned &r2, unsigned &r3, unsigned addr) {
    asm volatile("ldmatrix.sync.aligned.m8n8.x4.shared.b16 {%0,%1,%2,%3}, [%4];"
        : "=r"(r0), "=r"(r1), "=r"(r2), "=r"(r3) : "r"(addr));
}
__device__ __forceinline__ void ldsm4t(unsigned &r0, unsigned &r1, unsigned &r2, unsigned &r3, unsigned addr) {
    asm volatile("ldmatrix.sync.aligned.m8n8.x4.trans.shared.b16 {%0,%1,%2,%3}, [%4];"
        : "=r"(r0), "=r"(r1), "=r"(r2), "=r"(r3) : "r"(addr));
}
__device__ __forceinline__ void cpa16(unsigned dst, const void* src) {
    asm volatile("cp.async.cg.shared.global [%0], [%1], 16;" :: "r"(dst), "l"(src));
}
__device__ __forceinline__ void cpa_commit() {
    asm volatile("cp.async.commit_group;");
}
__device__ __forceinline__ float ex2(float x) {
    float r; asm("ex2.approx.ftz.f32 %0, %1;" : "=f"(r) : "f"(x)); return r;
}
__device__ __forceinline__ float wsum(float v) {
    #pragma unroll
    for (int o = 16; o > 0; o >>= 1) v += __shfl_xor_sync(0xffffffffu, v, o);
    return v;
}

#define L2E 1.4426950408889634f

// ---------------- fused prep: weight pack + bias pack + LN --------------------
__global__ __launch_bounds__(256) void prep(
    const float* __restrict__ x, const float* __restrict__ lng,
    const float* __restrict__ lnb,
    const float* __restrict__ Wq, const float* __restrict__ Wk,
    const float* __restrict__ Wv, const float* __restrict__ gW,
    const float* __restrict__ Wo, const float* __restrict__ mW,
    const float* __restrict__ rel)
{
    __shared__ float s[64][65];
    int bx = blockIdx.x, tid = threadIdx.x;
    if (bx < 96) {
        int w = bx >> 4, rem = bx & 15;
        int k0 = (rem >> 2) * 64, n0 = (rem & 3) * 64;
        const float* W;
        switch (w) {
            case 0: W = Wq; break; case 1: W = Wk; break; case 2: W = Wv; break;
            case 3: W = gW; break; case 4: W = Wo; break; default: W = mW; break;
        }
        for (int i = tid; i < 4096; i += 256) {
            int r = i >> 6, c = i & 63;
            s[r][c] = W[(size_t)(k0 + r)*EE + n0 + c];
        }
        __syncthreads();
        for (int i = tid; i < 2048; i += 256) {
            int n = i >> 5, kp = i & 31;
            g_wt[w][(n0 + n)*128 + k0/2 + kp] = pkh(s[2*kp][n], s[2*kp+1][n]);
        }
    } else if (bx < 1120) {
        int row = bx - 96;
        #pragma unroll
        for (int j = 0; j < 2; j++) {
            int i = tid + j*256;
            float2 v = *(const float2*)&rel[(size_t)row*SS + 2*i];
            g_rbh[row*512 + i] = pkh(v.x*L2E, v.y*L2E);
        }
    } else {
        int warp = tid >> 5, lane = tid & 31;
        int row = (bx - 1120)*8 + warp;
        const float* xr = x + (size_t)row*EE + lane*8;
        float4 a0 = *(const float4*)xr;
        float4 a1 = *(const float4*)(xr + 4);
        float xv[8] = {a0.x,a0.y,a0.z,a0.w,a1.x,a1.y,a1.z,a1.w};
        float sm = 0.f;
        #pragma unroll
        for (int i = 0; i < 8; i++) sm += xv[i];
        float mean = wsum(sm) * (1.f/EE);
        float vs = 0.f;
        #pragma unroll
        for (int i = 0; i < 8; i++) { float d = xv[i]-mean; vs += d*d; }
        float rstd = rsqrtf(wsum(vs)*(1.f/EE) + 1e-5f);
        float4 g0 = *(const float4*)(lng + lane*8);
        float4 g1 = *(const float4*)(lng + lane*8 + 4);
        float4 b0 = *(const float4*)(lnb + lane*8);
        float4 b1 = *(const float4*)(lnb + lane*8 + 4);
        float gg[8] = {g0.x,g0.y,g0.z,g0.w,g1.x,g1.y,g1.z,g1.w};
        float bb[8] = {b0.x,b0.y,b0.z,b0.w,b1.x,b1.y,b1.z,b1.w};
        float ln[8];
        #pragma unroll
        for (int i = 0; i < 8; i++) ln[i] = (xv[i]-mean)*rstd*gg[i] + bb[i];
        uint4 u, um;
        u.x = pkh(ln[0],ln[1]); u.y = pkh(ln[2],ln[3]);
        u.z = pkh(ln[4],ln[5]); u.w = pkh(ln[6],ln[7]);
        um.x = pkh(xv[0],xv[1]); um.y = pkh(xv[2],xv[3]);
        um.z = pkh(xv[4],xv[5]); um.w = pkh(xv[6],xv[7]);
        *(uint4*)&g_lnh[row*128 + lane*4] = u;
        *(uint4*)&g_mth[row*128 + lane*4] = um;
    }
}

// ---------------- fp16 GEMM (ops 0..4): 128x64 tile, K-chunk 64, 2-stage ------
__global__ __launch_bounds__(256, 3) void gemm_t(
    const float* __restrict__ bq, const float* __restrict__ bk,
    const float* __restrict__ bv, const float* __restrict__ gb,
    const float* __restrict__ bo, int op_base)
{
    extern __shared__ __align__(16) unsigned smem[];
    constexpr unsigned A_STG = 128*GK*4;     // 18432 B
    constexpr unsigned B_STG = 64*GK*4;      // 9216 B
    constexpr unsigned B_OFF = 2*A_STG;      // 36864

    int op = op_base + blockIdx.z;
    const unsigned* Ah;
    const float* bias;
    switch (op) {
        case 0: Ah = g_lnh; bias = bq; break;
        case 1: Ah = g_lnh; bias = bk; break;
        case 2: Ah = g_lnh; bias = bv; break;
        case 3: Ah = g_mth; bias = gb; break;
        default: Ah = g_oph; bias = bo; break;
    }
    const unsigned* Wh = g_wt[op];

    int tid = threadIdx.x, lane = tid & 31, warp = tid >> 5;
    int wm = warp >> 1, wn = warp & 1;       // 4m x 2n, warp tile 32x32
    int g = lane >> 2, t = lane & 3;
    int m0 = blockIdx.y * 128, n0 = blockIdx.x * 64;

    unsigned s_u = (unsigned)__cvta_generic_to_shared(smem);
    int l16 = lane & 15, secA = lane >> 4;
    unsigned aFrag = s_u + (((wm*32 + l16)*GK) + secA*4)*4;
    int l8 = lane & 7, qd = lane >> 3;
    unsigned bFrag = (((wn*32 + (qd>>1)*8 + l8)*GK) + (qd&1)*4)*4;

    int arow[4], af4[4];
    #pragma unroll
    for (int j = 0; j < 4; j++) { int idx = tid + j*256; arow[j] = idx >> 3; af4[j] = idx & 7; }

    float acc[2][4][4];
    #pragma unroll
    for (int mt = 0; mt < 2; mt++)
        #pragma unroll
        for (int nt = 0; nt < 4; nt++)
            #pragma unroll
            for (int i = 0; i < 4; i++) acc[mt][nt][i] = 0.f;

    auto issue = [&](int ch, int bs) {
        int cc = ch*32;
        #pragma unroll
        for (int j = 0; j < 4; j++)
            cpa16(s_u + bs*A_STG + (arow[j]*GK + af4[j]*4)*4,
                  &Ah[(size_t)(m0 + arow[j])*128 + cc + af4[j]*4]);
        #pragma unroll
        for (int j = 0; j < 2; j++)
            cpa16(s_u + B_OFF + bs*B_STG + (arow[j]*GK + af4[j]*4)*4,
                  &Wh[(size_t)(n0 + arow[j])*128 + cc + af4[j]*4]);
        cpa_commit();
    };

    issue(0, 0);

    #pragma unroll 1
    for (int c = 0; c < 4; c++) {
        asm volatile("cp.async.wait_group 0;");
        __syncthreads();
        if (c < 3) issue(c+1, (c+1) & 1);

        int bs = c & 1;
        #pragma unroll
        for (int kk = 0; kk < 4; kk++) {
            unsigned a[2][4];
            #pragma unroll
            for (int mt = 0; mt < 2; mt++)
                ldsm4(a[mt][0], a[mt][1], a[mt][2], a[mt][3],
                      aFrag + bs*A_STG + mt*(16*GK*4) + kk*32);
            #pragma unroll
            for (int pr = 0; pr < 2; pr++) {
                unsigned b0, b1, b2, b3;
                ldsm4(b0, b1, b2, b3,
                      s_u + B_OFF + bs*B_STG + bFrag + pr*(16*GK*4) + kk*32);
                #pragma unroll
                for (int mt = 0; mt < 2; mt++) {
                    mmah(acc[mt][2*pr  ], a[mt][0], a[mt][1], a[mt][2], a[mt][3], b0, b1);
                    mmah(acc[mt][2*pr+1], a[mt][0], a[mt][1], a[mt][2], a[mt][3], b2, b3);
                }
            }
        }
    }

    const float qscale = 0.17677669529663687f * L2E;
    #pragma unroll
    for (int mt = 0; mt < 2; mt++) {
        int row0 = m0 + wm*32 + mt*16 + g;
        int row1 = row0 + 8;
        #pragma unroll
        for (int nt = 0; nt < 4; nt++) {
            int col = n0 + wn*32 + nt*8 + t*2;
            int cp  = col >> 1;
            float bv0 = bias[col], bv1 = bias[col+1];
            float v00 = acc[mt][nt][0] + bv0, v01 = acc[mt][nt][1] + bv1;
            float v10 = acc[mt][nt][2] + bv0, v11 = acc[mt][nt][3] + bv1;
            if (op == 0) {
                g_qph[row0*128 + cp] = pkh(v00*qscale, v01*qscale);
                g_qph[row1*128 + cp] = pkh(v10*qscale, v11*qscale);
            } else if (op == 1) {
                g_kph[row0*128 + cp] = pkh(v00, v01);
                g_kph[row1*128 + cp] = pkh(v10, v11);
            } else if (op == 2) {
                g_vph[row0*128 + cp] = pkh(v00, v01);
                g_vph[row1*128 + cp] = pkh(v10, v11);
            } else if (op == 3) {
                v00 = 1.f/(1.f + __expf(-v00)); v01 = 1.f/(1.f + __expf(-v01));
                v10 = 1.f/(1.f + __expf(-v10)); v11 = 1.f/(1.f + __expf(-v11));
                g_g0h[row0*128 + cp] = pkh(v00, v01);
                g_g0h[row1*128 + cp] = pkh(v10, v11);
            } else {  // op 4: gate1 = gate0*rmha + Matrix(fp16 plane), fp16-only store
                float2 ga0 = up2(g_g0h[row0*128 + cp]);
                float2 ga1 = up2(g_g0h[row1*128 + cp]);
                float2 mx0 = up2(g_mth[row0*128 + cp]);
                float2 mx1 = up2(g_mth[row1*128 + cp]);
                v00 = ga0.x*v00 + mx0.x;  v01 = ga0.y*v01 + mx0.y;
                v10 = ga1.x*v10 + mx1.x;  v11 = ga1.y*v11 + mx1.y;
                g_g1h[row0*128 + cp] = pkh(v00, v01);
                g_g1h[row1*128 + cp] = pkh(v10, v11);
            }
        }
    }
}

// ---------------- fused mW GEMM + sigmoid + LN + gated output -----------------
__global__ __launch_bounds__(256, 2) void gemm_mlp(
    const float* __restrict__ mb, const float* __restrict__ lng,
    const float* __restrict__ lnb, float* __restrict__ out)
{
    extern __shared__ __align__(16) unsigned smem[];
    constexpr unsigned A_STG = 64*GK*4;      // 9216
    constexpr unsigned B_STG = 256*GK*4;     // 36864
    constexpr unsigned B_OFF = 2*A_STG;      // 18432
    const unsigned* Wh = g_wt[5];

    int tid = threadIdx.x, lane = tid & 31, warp = tid >> 5;
    int wm = warp >> 2, wn = warp & 3;
    int g = lane >> 2, t = lane & 3;
    int m0 = blockIdx.x * 64;

    unsigned s_u = (unsigned)__cvta_generic_to_shared(smem);
    int l16 = lane & 15, secA = lane >> 4;
    unsigned aFrag = s_u + (((wm*32 + l16)*GK) + secA*4)*4;
    int l8 = lane & 7, qd = lane >> 3;
    unsigned bFrag = (((wn*64 + (qd>>1)*8 + l8)*GK) + (qd&1)*4)*4;

    int arow[2], af4[2], brow[8], bf4[8];
    #pragma unroll
    for (int j = 0; j < 8; j++) {
        int idx = tid + j*256;
        brow[j] = idx >> 3; bf4[j] = idx & 7;
        if (j < 2) { arow[j] = idx >> 3; af4[j] = idx & 7; }
    }

    float acc[2][8][4];
    #pragma unroll
    for (int mt = 0; mt < 2; mt++)
        #pragma unroll
        for (int nt = 0; nt < 8; nt++)
            #pragma unroll
            for (int i = 0; i < 4; i++) acc[mt][nt][i] = 0.f;

    auto issue = [&](int ch, int bs) {
        int cc = ch*32;
        #pragma unroll
        for (int j = 0; j < 2; j++)
            cpa16(s_u + bs*A_STG + (arow[j]*GK + af4[j]*4)*4,
                  &g_g1h[(size_t)(m0 + arow[j])*128 + cc + af4[j]*4]);
        #pragma unroll
        for (int j = 0; j < 8; j++)
            cpa16(s_u + B_OFF + bs*B_STG + (brow[j]*GK + bf4[j]*4)*4,
                  &Wh[(size_t)brow[j]*128 + cc + bf4[j]*4]);
        cpa_commit();
    };

    issue(0, 0);

    #pragma unroll 1
    for (int c = 0; c < 4; c++) {
        asm volatile("cp.async.wait_group 0;");
        __syncthreads();
        if (c < 3) issue(c+1, (c+1) & 1);

        int bs = c & 1;
        #pragma unroll
        for (int kk = 0; kk < 4; kk++) {
            unsigned a[2][4];
            #pragma unroll
            for (int mt = 0; mt < 2; mt++)
                ldsm4(a[mt][0], a[mt][1], a[mt][2], a[mt][3],
                      aFrag + bs*A_STG + mt*(16*GK*4) + kk*32);
            #pragma unroll
            for (int pr = 0; pr < 4; pr++) {
                unsigned b0, b1, b2, b3;
                ldsm4(b0, b1, b2, b3,
                      s_u + B_OFF + bs*B_STG + bFrag + pr*(16*GK*4) + kk*32);
                #pragma unroll
                for (int mt = 0; mt < 2; mt++) {
                    mmah(acc[mt][2*pr  ], a[mt][0], a[mt][1], a[mt][2], a[mt][3], b0, b1);
                    mmah(acc[mt][2*pr+1], a[mt][0], a[mt][1], a[mt][2], a[mt][3], b2, b3);
                }
            }
        }
    }
    __syncthreads();   // protect reduction scratch region reuse

    // ---- epilogue: sigmoid + per-row LN + gated output ----
    float* sS = (float*)&smem[23040];   // byte 92160
    float* sQ = sS + 256;

    float psum[2][2] = {{0,0},{0,0}}, psq[2][2] = {{0,0},{0,0}};
    #pragma unroll
    for (int mt = 0; mt < 2; mt++) {
        #pragma unroll
        for (int nt = 0; nt < 8; nt++) {
            int col = wn*64 + nt*8 + t*2;
            float bv0 = mb[col], bv1 = mb[col+1];
            float v00 = 1.f/(1.f + __expf(-(acc[mt][nt][0] + bv0)));
            float v01 = 1.f/(1.f + __expf(-(acc[mt][nt][1] + bv1)));
            float v10 = 1.f/(1.f + __expf(-(acc[mt][nt][2] + bv0)));
            float v11 = 1.f/(1.f + __expf(-(acc[mt][nt][3] + bv1)));
            acc[mt][nt][0] = v00; acc[mt][nt][1] = v01;
            acc[mt][nt][2] = v10; acc[mt][nt][3] = v11;
            psum[mt][0] += v00 + v01;  psq[mt][0] += v00*v00 + v01*v01;
            psum[mt][1] += v10 + v11;  psq[mt][1] += v10*v10 + v11*v11;
        }
    }
    #pragma unroll
    for (int mt = 0; mt < 2; mt++)
        #pragma unroll
        for (int hf = 0; hf < 2; hf++) {
            float s = psum[mt][hf], q = psq[mt][hf];
            s += __shfl_xor_sync(0xffffffffu, s, 1);
            s += __shfl_xor_sync(0xffffffffu, s, 2);
            q += __shfl_xor_sync(0xffffffffu, q, 1);
            q += __shfl_xor_sync(0xffffffffu, q, 2);
            psum[mt][hf] = s; psq[mt][hf] = q;
        }
    if (t == 0) {
        #pragma unroll
        for (int mt = 0; mt < 2; mt++)
            #pragma unroll
            for (int hf = 0; hf < 2; hf++) {
                int r = wm*32 + mt*16 + g + hf*8;
                sS[r*4 + wn] = psum[mt][hf];
                sQ[r*4 + wn] = psq[mt][hf];
            }
    }
    __syncthreads();

    float mean[2][2], rstd[2][2];
    #pragma unroll
    for (int mt = 0; mt < 2; mt++)
        #pragma unroll
        for (int hf = 0; hf < 2; hf++) {
            int r = wm*32 + mt*16 + g + hf*8;
            float s = sS[r*4+0] + sS[r*4+1] + sS[r*4+2] + sS[r*4+3];
            float q = sQ[r*4+0] + sQ[r*4+1] + sQ[r*4+2] + sQ[r*4+3];
            float m = s * (1.f/EE);
            float v = q * (1.f/EE) - m*m;
            mean[mt][hf] = m;
            rstd[mt][hf] = rsqrtf(v + 1e-5f);
        }

    #pragma unroll
    for (int mt = 0; mt < 2; mt++) {
        int row0 = m0 + wm*32 + mt*16 + g;
        int row1 = row0 + 8;
        #pragma unroll
        for (int nt = 0; nt < 8; nt++) {
            int col = wn*64 + nt*8 + t*2;
            int cp  = col >> 1;
            float2 gm = *(const float2*)&lng[col];
            float2 bt = *(const float2*)&lnb[col];
            size_t i0 = (size_t)row0*EE + col, i1 = (size_t)row1*EE + col;
            float2 g10 = up2(g_g1h[row0*128 + cp]);
            float2 g11 = up2(g_g1h[row1*128 + cp]);
            float ln00 = (acc[mt][nt][0] - mean[mt][0])*rstd[mt][0]*gm.x + bt.x;
            float ln01 = (acc[mt][nt][1] - mean[mt][0])*rstd[mt][0]*gm.y + bt.y;
            float ln10 = (acc[mt][nt][2] - mean[mt][1])*rstd[mt][1]*gm.x + bt.x;
            float ln11 = (acc[mt][nt][3] - mean[mt][1])*rstd[mt][1]*gm.y + bt.y;
            *(float2*)&out[i0] = make_float2(g10.x*(ln00+1.f), g10.y*(ln01+1.f));
            *(float2*)&out[i1] = make_float2(g11.x*(ln10+1.f), g11.y*(ln11+1.f));
        }
    }
}

// ---------------- head-paired fp16 flash attention, 3-stage, 1 barrier/tile ---
#define AP 36
__global__ __launch_bounds__(256, 2) void attn_h2()
{
    extern __shared__ __align__(16) unsigned smem[];
    const unsigned KBUF = 64*AP*4;        // 9216 B per stage

    int tid = threadIdx.x, lane = tid & 31, wq = tid >> 5;
    int g = lane >> 2, t = lane & 3;
    int bhp = blockIdx.x;
    int b = bhp >> 2, hp = bhp & 3;
    int q0 = blockIdx.y * 128;

    int r0 = q0 + wq*16 + g;
    int qrow0 = b*SS + r0, qrow1 = qrow0 + 8;

    unsigned sK_u = (unsigned)__cvta_generic_to_shared(smem);
    unsigned sV_u = sK_u + 3*KBUF;
    int l8 = lane & 7, qd = lane >> 3;
    unsigned kBase = sK_u + (((qd>>1)*8 + l8)*AP + (qd&1)*4)*4;
    unsigned vBase = sV_u + (((qd&1)*8 + l8)*AP)*4 + (qd>>1)*16;

    unsigned qhf[2][2][4];
    #pragma unroll
    for (int h = 0; h < 2; h++)
        #pragma unroll
        for (int kk = 0; kk < 2; kk++) {
            int base = hp*32 + h*16 + kk*8 + t;
            int b0 = qrow0*128 + base, b1 = qrow1*128 + base;
            qhf[h][kk][0] = g_qph[b0]; qhf[h][kk][1] = g_qph[b1];
            qhf[h][kk][2] = g_qph[b0+4]; qhf[h][kk][3] = g_qph[b1+4];
        }

    float O[2][4][4];
    #pragma unroll
    for (int h = 0; h < 2; h++)
        #pragma unroll
        for (int dn = 0; dn < 4; dn++)
            #pragma unroll
            for (int i = 0; i < 4; i++) O[h][dn][i] = 0.f;
    float ms0[2] = {-1e30f,-1e30f}, ms1[2] = {-1e30f,-1e30f};
    float ls0[2] = {0.f,0.f}, ls1[2] = {0.f,0.f};

    int lrow[2], lf[2];
    #pragma unroll
    for (int j = 0; j < 2; j++) { int idx = tid + j*256; lrow[j] = idx >> 3; lf[j] = idx & 7; }

    auto issue = [&](int kt, int bs) {
        #pragma unroll
        for (int j = 0; j < 2; j++) {
            size_t src = (size_t)(b*SS + kt*64 + lrow[j])*128 + hp*32 + lf[j]*4;
            unsigned d = (lrow[j]*AP + lf[j]*4)*4;
            cpa16(sK_u + bs*KBUF + d, &g_kph[src]);
            cpa16(sV_u + bs*KBUF + d, &g_vph[src]);
        }
        cpa_commit();
    };
    issue(0, 0);
    issue(1, 1);

    const unsigned ONE2 = 0x3C003C00u;

    #pragma unroll 1
    for (int kt = 0; kt < 16; kt++) {
        if (kt < 15) asm volatile("cp.async.wait_group 1;");
        else         asm volatile("cp.async.wait_group 0;");
        __syncthreads();
        if (kt < 14) issue(kt+2, (kt+2) % 3);
        int bsel = kt % 3;

        unsigned bf[8][2];
        #pragma unroll
        for (int nt = 0; nt < 8; nt++) {
            int pc = kt*32 + nt*4 + t;
            bf[nt][0] = g_rbh[r0*512 + pc];
            bf[nt][1] = g_rbh[(r0+8)*512 + pc];
        }

        #pragma unroll
        for (int h = 0; h < 2; h++) {
            float S_[8][4];
            #pragma unroll
            for (int nt = 0; nt < 8; nt++)
                #pragma unroll
                for (int i = 0; i < 4; i++) S_[nt][i] = 0.f;
            #pragma unroll
            for (int kk = 0; kk < 2; kk++) {
                #pragma unroll
                for (int p = 0; p < 4; p++) {
                    unsigned k0r, k1r, k2r, k3r;
                    ldsm4(k0r, k1r, k2r, k3r,
                          kBase + h*64 + bsel*KBUF + p*(16*AP*4) + kk*32);
                    mmah(S_[2*p  ], qhf[h][kk][0], qhf[h][kk][1], qhf[h][kk][2], qhf[h][kk][3], k0r, k1r);
                    mmah(S_[2*p+1], qhf[h][kk][0], qhf[h][kk][1], qhf[h][kk][2], qhf[h][kk][3], k2r, k3r);
                }
            }
            #pragma unroll
            for (int nt = 0; nt < 8; nt++) {
                float2 b0v = up2(bf[nt][0]);
                float2 b1v = up2(bf[nt][1]);
                S_[nt][0] += b0v.x; S_[nt][1] += b0v.y;
                S_[nt][2] += b1v.x; S_[nt][3] += b1v.y;
            }

            float tm0 = -1e30f, tm1 = -1e30f;
            #pragma unroll
            for (int nt = 0; nt < 8; nt++) {
                tm0 = fmaxf(tm0, fmaxf(S_[nt][0], S_[nt][1]));
                tm1 = fmaxf(tm1, fmaxf(S_[nt][2], S_[nt][3]));
            }
            tm0 = fmaxf(tm0, __shfl_xor_sync(0xffffffffu, tm0, 1));
            tm0 = fmaxf(tm0, __shfl_xor_sync(0xffffffffu, tm0, 2));
            tm1 = fmaxf(tm1, __shfl_xor_sync(0xffffffffu, tm1, 1));
            tm1 = fmaxf(tm1, __shfl_xor_sync(0xffffffffu, tm1, 2));
            float nm0 = fmaxf(ms0[h], tm0), nm1 = fmaxf(ms1[h], tm1);
            float sc0 = ex2(ms0[h] - nm0), sc1 = ex2(ms1[h] - nm1);

            unsigned pf[8][2];
            #pragma unroll
            for (int nt = 0; nt < 8; nt++) {
                __half2 d0 = __floats2half2_rn(S_[nt][0] - nm0, S_[nt][1] - nm0);
                __half2 d1 = __floats2half2_rn(S_[nt][2] - nm1, S_[nt][3] - nm1);
                __half2 p0 = h2exp2(d0);
                __half2 p1 = h2exp2(d1);
                pf[nt][0] = *reinterpret_cast<unsigned*>(&p0);
                pf[nt][1] = *reinterpret_cast<unsigned*>(&p1);
            }

            float rsA[4] = {0.f, 0.f, 0.f, 0.f};
            #pragma unroll
            for (int kk = 0; kk < 4; kk++)
                mmah(rsA, pf[2*kk][0], pf[2*kk][1], pf[2*kk+1][0], pf[2*kk+1][1], ONE2, ONE2);
            ls0[h] = ls0[h]*sc0 + rsA[0];
            ls1[h] = ls1[h]*sc1 + rsA[2];
            ms0[h] = nm0;  ms1[h] = nm1;
            #pragma unroll
            for (int dn = 0; dn < 4; dn++) {
                O[h][dn][0] *= sc0; O[h][dn][1] *= sc0;
                O[h][dn][2] *= sc1; O[h][dn][3] *= sc1;
            }

            #pragma unroll
            for (int kk = 0; kk < 4; kk++) {
                unsigned a0 = pf[2*kk][0], a1 = pf[2*kk][1];
                unsigned a2 = pf[2*kk+1][0], a3 = pf[2*kk+1][1];
                #pragma unroll
                for (int p = 0; p < 2; p++) {
                    unsigned v0, v1, v2, v3;
                    ldsm4t(v0, v1, v2, v3,
                           vBase + h*64 + bsel*KBUF + kk*(16*AP*4) + p*32);
                    mmah(O[h][2*p  ], a0, a1, a2, a3, v0, v1);
                    mmah(O[h][2*p+1], a0, a1, a2, a3, v2, v3);
                }
            }
        }
    }

    #pragma unroll
    for (int h = 0; h < 2; h++) {
        int hd = hp*2 + h;
        float il0 = 1.f/ls0[h], il1 = 1.f/ls1[h];
        #pragma unroll
        for (int dn = 0; dn < 4; dn++) {
            int cp = hd*16 + dn*4 + t;
            g_oph[qrow0*128 + cp] = pkh(O[h][dn][0]*il0, O[h][dn][1]*il0);
            g_oph[qrow1*128 + cp] = pkh(O[h][dn][2]*il1, O[h][dn][3]*il1);
        }
    }
}

// ---------------- launch ------------------------------------------------------
extern "C" void kernel_launch(void* const* d_in, const int* in_sizes, int n_in,
                              void* d_out, int out_size)
{
    const float* Matrix = (const float*)d_in[0];
    const float* ln_g   = (const float*)d_in[1];
    const float* ln_b   = (const float*)d_in[2];
    const float* Wq     = (const float*)d_in[3];
    const float* bq     = (const float*)d_in[4];
    const float* Wk     = (const float*)d_in[5];
    const float* bk     = (const float*)d_in[6];
    const float* Wv     = (const float*)d_in[7];
    const float* bv     = (const float*)d_in[8];
    const float* Wo     = (const float*)d_in[9];
    const float* bo     = (const float*)d_in[10];
    const float* rel    = (const float*)d_in[11];
    const float* gW     = (const float*)d_in[12];
    const float* gb     = (const float*)d_in[13];
    const float* mW     = (const float*)d_in[14];
    const float* mb     = (const float*)d_in[15];
    float* out = (float*)d_out;

    const int SM1 = 2*(128*GK*4) + 2*(64*GK*4);       // 55296
    const int SMM = 2*(64*GK*4 + 256*GK*4) + 2048;    // 94208
    const int SMA = 6*(64*AP*4);                      // 55296
    static bool attr_set = false;
    if (!attr_set) {
        cudaFuncSetAttribute(gemm_t, cudaFuncAttributeMaxDynamicSharedMemorySize, SM1);
        cudaFuncSetAttribute(gemm_mlp, cudaFuncAttributeMaxDynamicSharedMemorySize, SMM);
        cudaFuncSetAttribute(attn_h2, cudaFuncAttributeMaxDynamicSharedMemorySize, SMA);
        attr_set = true;
    }

    prep<<<3168, 256>>>(Matrix, ln_g, ln_b, Wq, Wk, Wv, gW, Wo, mW, rel);

    gemm_t<<<dim3(4,128,4), 256, SM1>>>(bq, bk, bv, gb, bo, 0);
    attn_h2<<<dim3(64,8), 256, SMA>>>();
    gemm_t<<<dim3(4,128,1), 256, SM1>>>(bq, bk, bv, gb, bo, 4);
    gemm_mlp<<<256, 256, SMM>>>(mb, ln_g, ln_b, out);
}

// round 17
// speedup vs baseline: 1.4416x; 1.0696x over previous
#include <cuda_runtime.h>
#include <cuda_fp16.h>
#include <math.h>

#define BB 16
#define SS 1024
#define EE 256
#define HH 8
#define DHD 32
#define MROWS (BB*SS)   // 16384
#define GK 36           // smem pitch (uints) for K=64 chunks: 32 data + 4 pad

// ---------------- scratch ----------------------------------------------------
__device__ unsigned g_wt[6][256*128];        // weight hi planes [n][kpair]
__device__ unsigned g_rbh[SS*512];           // rel_bias * log2e, fp16 pairs
__device__ unsigned g_lnh[MROWS*128];
__device__ unsigned g_mth[MROWS*128];
__device__ unsigned g_qph[MROWS*128];        // pre-scaled by log2e/sqrt(DH)
__device__ unsigned g_kph[MROWS*128];
__device__ unsigned g_vph[MROWS*128];
__device__ unsigned g_oph[MROWS*128];
__device__ unsigned g_g0h[MROWS*128];        // gate0 fp16 pairs

// ---------------- helpers -----------------------------------------------------
__device__ __forceinline__ unsigned pkh(float a, float b) {
    __half2 t = __floats2half2_rn(a, b);
    return *reinterpret_cast<unsigned*>(&t);
}
__device__ __forceinline__ float2 up2(unsigned u) {
    return __half22float2(*reinterpret_cast<__half2*>(&u));
}
__device__ __forceinline__ void mmah(float* c,
    unsigned a0, unsigned a1, unsigned a2, unsigned a3,
    unsigned b0, unsigned b1)
{
    asm volatile(
        "mma.sync.aligned.m16n8k16.row.col.f32.f16.f16.f32 "
        "{%0,%1,%2,%3},{%4,%5,%6,%7},{%8,%9},{%0,%1,%2,%3};"
        : "+f"(c[0]), "+f"(c[1]), "+f"(c[2]), "+f"(c[3])
        : "r"(a0), "r"(a1), "r"(a2), "r"(a3), "r"(b0), "r"(b1));
}
__device__ __forceinline__ void ldsm4(unsigned &r0, unsigned &r1, unsigned &r2, unsigned &r3, unsigned addr) {
    asm volatile("ldmatrix.sync.aligned.m8n8.x4.shared.b16 {%0,%1,%2,%3}, [%4];"
        : "=r"(r0), "=r"(r1), "=r"(r2), "=r"(r3) : "r"(addr));
}
__device__ __forceinline__ void ldsm4t(unsigned &r0, unsigned &r1, unsigned &r2, unsigned &r3, unsigned addr) {
    asm volatile("ldmatrix.sync.aligned.m8n8.x4.trans.shared.b16 {%0,%1,%2,%3}, [%4];"
        : "=r"(r0), "=r"(r1), "=r"(r2), "=r"(r3) : "r"(addr));
}
__device__ __forceinline__ void cpa16(unsigned dst, const void* src) {
    asm volatile("cp.async.cg.shared.global [%0], [%1], 16;" :: "r"(dst), "l"(src));
}
__device__ __forceinline__ void cpa_commit() {
    asm volatile("cp.async.commit_group;");
}
__device__ __forceinline__ float ex2(float x) {
    float r; asm("ex2.approx.ftz.f32 %0, %1;" : "=f"(r) : "f"(x)); return r;
}
__device__ __forceinline__ float wsum(float v) {
    #pragma unroll
    for (int o = 16; o > 0; o >>= 1) v += __shfl_xor_sync(0xffffffffu, v, o);
    return v;
}

#define L2E 1.4426950408889634f

// ---------------- fused prep: weight pack + bias pack + LN --------------------
__global__ __launch_bounds__(256) void prep(
    const float* __restrict__ x, const float* __restrict__ lng,
    const float* __restrict__ lnb,
    const float* __restrict__ Wq, const float* __restrict__ Wk,
    const float* __restrict__ Wv, const float* __restrict__ gW,
    const float* __restrict__ Wo, const float* __restrict__ mW,
    const float* __restrict__ rel)
{
    __shared__ float s[64][65];
    int bx = blockIdx.x, tid = threadIdx.x;
    if (bx < 96) {
        int w = bx >> 4, rem = bx & 15;
        int k0 = (rem >> 2) * 64, n0 = (rem & 3) * 64;
        const float* W;
        switch (w) {
            case 0: W = Wq; break; case 1: W = Wk; break; case 2: W = Wv; break;
            case 3: W = gW; break; case 4: W = Wo; break; default: W = mW; break;
        }
        for (int i = tid; i < 4096; i += 256) {
            int r = i >> 6, c = i & 63;
            s[r][c] = W[(size_t)(k0 + r)*EE + n0 + c];
        }
        __syncthreads();
        for (int i = tid; i < 2048; i += 256) {
            int n = i >> 5, kp = i & 31;
            g_wt[w][(n0 + n)*128 + k0/2 + kp] = pkh(s[2*kp][n], s[2*kp+1][n]);
        }
    } else if (bx < 1120) {
        int row = bx - 96;
        #pragma unroll
        for (int j = 0; j < 2; j++) {
            int i = tid + j*256;
            float2 v = *(const float2*)&rel[(size_t)row*SS + 2*i];
            g_rbh[row*512 + i] = pkh(v.x*L2E, v.y*L2E);
        }
    } else {
        int warp = tid >> 5, lane = tid & 31;
        int row = (bx - 1120)*8 + warp;
        const float* xr = x + (size_t)row*EE + lane*8;
        float4 a0 = *(const float4*)xr;
        float4 a1 = *(const float4*)(xr + 4);
        float xv[8] = {a0.x,a0.y,a0.z,a0.w,a1.x,a1.y,a1.z,a1.w};
        float sm = 0.f;
        #pragma unroll
        for (int i = 0; i < 8; i++) sm += xv[i];
        float mean = wsum(sm) * (1.f/EE);
        float vs = 0.f;
        #pragma unroll
        for (int i = 0; i < 8; i++) { float d = xv[i]-mean; vs += d*d; }
        float rstd = rsqrtf(wsum(vs)*(1.f/EE) + 1e-5f);
        float4 g0 = *(const float4*)(lng + lane*8);
        float4 g1 = *(const float4*)(lng + lane*8 + 4);
        float4 b0 = *(const float4*)(lnb + lane*8);
        float4 b1 = *(const float4*)(lnb + lane*8 + 4);
        float gg[8] = {g0.x,g0.y,g0.z,g0.w,g1.x,g1.y,g1.z,g1.w};
        float bb[8] = {b0.x,b0.y,b0.z,b0.w,b1.x,b1.y,b1.z,b1.w};
        float ln[8];
        #pragma unroll
        for (int i = 0; i < 8; i++) ln[i] = (xv[i]-mean)*rstd*gg[i] + bb[i];
        uint4 u, um;
        u.x = pkh(ln[0],ln[1]); u.y = pkh(ln[2],ln[3]);
        u.z = pkh(ln[4],ln[5]); u.w = pkh(ln[6],ln[7]);
        um.x = pkh(xv[0],xv[1]); um.y = pkh(xv[2],xv[3]);
        um.z = pkh(xv[4],xv[5]); um.w = pkh(xv[6],xv[7]);
        *(uint4*)&g_lnh[row*128 + lane*4] = u;
        *(uint4*)&g_mth[row*128 + lane*4] = um;
    }
}

// ---------------- fp16 GEMM (ops 0..3): 128x64 tile, K-chunk 64, 2-stage ------
__global__ __launch_bounds__(256, 3) void gemm_t(
    const float* __restrict__ bq, const float* __restrict__ bk,
    const float* __restrict__ bv, const float* __restrict__ gb)
{
    extern __shared__ __align__(16) unsigned smem[];
    constexpr unsigned A_STG = 128*GK*4;     // 18432 B
    constexpr unsigned B_STG = 64*GK*4;      // 9216 B
    constexpr unsigned B_OFF = 2*A_STG;      // 36864

    int op = blockIdx.z;
    const unsigned* Ah = (op == 3) ? g_mth : g_lnh;
    const float* bias;
    switch (op) {
        case 0: bias = bq; break;
        case 1: bias = bk; break;
        case 2: bias = bv; break;
        default: bias = gb; break;
    }
    const unsigned* Wh = g_wt[op];

    int tid = threadIdx.x, lane = tid & 31, warp = tid >> 5;
    int wm = warp >> 1, wn = warp & 1;       // 4m x 2n, warp tile 32x32
    int g = lane >> 2, t = lane & 3;
    int m0 = blockIdx.y * 128, n0 = blockIdx.x * 64;

    unsigned s_u = (unsigned)__cvta_generic_to_shared(smem);
    int l16 = lane & 15, secA = lane >> 4;
    unsigned aFrag = s_u + (((wm*32 + l16)*GK) + secA*4)*4;
    int l8 = lane & 7, qd = lane >> 3;
    unsigned bFrag = (((wn*32 + (qd>>1)*8 + l8)*GK) + (qd&1)*4)*4;

    int arow[4], af4[4];
    #pragma unroll
    for (int j = 0; j < 4; j++) { int idx = tid + j*256; arow[j] = idx >> 3; af4[j] = idx & 7; }

    float acc[2][4][4];
    #pragma unroll
    for (int mt = 0; mt < 2; mt++)
        #pragma unroll
        for (int nt = 0; nt < 4; nt++)
            #pragma unroll
            for (int i = 0; i < 4; i++) acc[mt][nt][i] = 0.f;

    auto issue = [&](int ch, int bs) {
        int cc = ch*32;
        #pragma unroll
        for (int j = 0; j < 4; j++)
            cpa16(s_u + bs*A_STG + (arow[j]*GK + af4[j]*4)*4,
                  &Ah[(size_t)(m0 + arow[j])*128 + cc + af4[j]*4]);
        #pragma unroll
        for (int j = 0; j < 2; j++)
            cpa16(s_u + B_OFF + bs*B_STG + (arow[j]*GK + af4[j]*4)*4,
                  &Wh[(size_t)(n0 + arow[j])*128 + cc + af4[j]*4]);
        cpa_commit();
    };

    issue(0, 0);

    #pragma unroll 1
    for (int c = 0; c < 4; c++) {
        asm volatile("cp.async.wait_group 0;");
        __syncthreads();
        if (c < 3) issue(c+1, (c+1) & 1);

        int bs = c & 1;
        #pragma unroll
        for (int kk = 0; kk < 4; kk++) {
            unsigned a[2][4];
            #pragma unroll
            for (int mt = 0; mt < 2; mt++)
                ldsm4(a[mt][0], a[mt][1], a[mt][2], a[mt][3],
                      aFrag + bs*A_STG + mt*(16*GK*4) + kk*32);
            #pragma unroll
            for (int pr = 0; pr < 2; pr++) {
                unsigned b0, b1, b2, b3;
                ldsm4(b0, b1, b2, b3,
                      s_u + B_OFF + bs*B_STG + bFrag + pr*(16*GK*4) + kk*32);
                #pragma unroll
                for (int mt = 0; mt < 2; mt++) {
                    mmah(acc[mt][2*pr  ], a[mt][0], a[mt][1], a[mt][2], a[mt][3], b0, b1);
                    mmah(acc[mt][2*pr+1], a[mt][0], a[mt][1], a[mt][2], a[mt][3], b2, b3);
                }
            }
        }
    }

    const float qscale = 0.17677669529663687f * L2E;
    #pragma unroll
    for (int mt = 0; mt < 2; mt++) {
        int row0 = m0 + wm*32 + mt*16 + g;
        int row1 = row0 + 8;
        #pragma unroll
        for (int nt = 0; nt < 4; nt++) {
            int col = n0 + wn*32 + nt*8 + t*2;
            int cp  = col >> 1;
            float bv0 = bias[col], bv1 = bias[col+1];
            float v00 = acc[mt][nt][0] + bv0, v01 = acc[mt][nt][1] + bv1;
            float v10 = acc[mt][nt][2] + bv0, v11 = acc[mt][nt][3] + bv1;
            if (op == 0) {
                g_qph[row0*128 + cp] = pkh(v00*qscale, v01*qscale);
                g_qph[row1*128 + cp] = pkh(v10*qscale, v11*qscale);
            } else if (op == 1) {
                g_kph[row0*128 + cp] = pkh(v00, v01);
                g_kph[row1*128 + cp] = pkh(v10, v11);
            } else if (op == 2) {
                g_vph[row0*128 + cp] = pkh(v00, v01);
                g_vph[row1*128 + cp] = pkh(v10, v11);
            } else {
                v00 = 1.f/(1.f + __expf(-v00)); v01 = 1.f/(1.f + __expf(-v01));
                v10 = 1.f/(1.f + __expf(-v10)); v11 = 1.f/(1.f + __expf(-v11));
                g_g0h[row0*128 + cp] = pkh(v00, v01);
                g_g0h[row1*128 + cp] = pkh(v10, v11);
            }
        }
    }
}

// ---------------- fused tail: Wo GEMM -> gate1(smem) -> mW GEMM -> LN -> out --
// block = 64 rows x 256 cols, 8 warps (2m x 4n), warp 32x64, K-chunk 64.
// smem layout (bytes): [0,18432) phase1-A dbuf (later gate1 chunks 0,1)
//   [18432,92160) B dbuf (2x36864)   [92160,110592) gate1 chunks 2,3
//   LN scratch at byte 18432 after phase2 mainloop.
__global__ __launch_bounds__(256, 2) void gemm_tail(
    const float* __restrict__ bo, const float* __restrict__ mb,
    const float* __restrict__ lng, const float* __restrict__ lnb,
    float* __restrict__ out)
{
    extern __shared__ __align__(16) unsigned smem[];
    constexpr unsigned A_STG = 64*GK*4;      // 9216
    constexpr unsigned B_STG = 256*GK*4;     // 36864
    constexpr unsigned B_OFF = 2*A_STG;      // 18432
    constexpr unsigned G23_OFF = B_OFF + 2*B_STG;  // 92160

    int tid = threadIdx.x, lane = tid & 31, warp = tid >> 5;
    int wm = warp >> 2, wn = warp & 3;
    int g = lane >> 2, t = lane & 3;
    int m0 = blockIdx.x * 64;

    unsigned s_u = (unsigned)__cvta_generic_to_shared(smem);
    int l16 = lane & 15, secA = lane >> 4;
    unsigned aOff = (((wm*32 + l16)*GK) + secA*4)*4;   // fragment offset within a 64-row chunk
    int l8 = lane & 7, qd = lane >> 3;
    unsigned bFrag = (((wn*64 + (qd>>1)*8 + l8)*GK) + (qd&1)*4)*4;

    auto g1base = [](int c) -> unsigned { return (c < 2) ? c*A_STG : G23_OFF + (c-2)*A_STG; };

    int arow[2], af4[2], brow[8], bf4[8];
    #pragma unroll
    for (int j = 0; j < 8; j++) {
        int idx = tid + j*256;
        brow[j] = idx >> 3; bf4[j] = idx & 7;
        if (j < 2) { arow[j] = idx >> 3; af4[j] = idx & 7; }
    }

    float acc[2][8][4];
    #pragma unroll
    for (int mt = 0; mt < 2; mt++)
        #pragma unroll
        for (int nt = 0; nt < 8; nt++)
            #pragma unroll
            for (int i = 0; i < 4; i++) acc[mt][nt][i] = 0.f;

    // ---- phase 1: rmha = o @ Wo ----
    const unsigned* WoP = g_wt[4];
    auto issue1 = [&](int ch, int bs) {
        int cc = ch*32;
        #pragma unroll
        for (int j = 0; j < 2; j++)
            cpa16(s_u + bs*A_STG + (arow[j]*GK + af4[j]*4)*4,
                  &g_oph[(size_t)(m0 + arow[j])*128 + cc + af4[j]*4]);
        #pragma unroll
        for (int j = 0; j < 8; j++)
            cpa16(s_u + B_OFF + bs*B_STG + (brow[j]*GK + bf4[j]*4)*4,
                  &WoP[(size_t)brow[j]*128 + cc + bf4[j]*4]);
        cpa_commit();
    };
    issue1(0, 0);
    #pragma unroll 1
    for (int c = 0; c < 4; c++) {
        asm volatile("cp.async.wait_group 0;");
        __syncthreads();
        if (c < 3) issue1(c+1, (c+1) & 1);
        int bs = c & 1;
        #pragma unroll
        for (int kk = 0; kk < 4; kk++) {
            unsigned a[2][4];
            #pragma unroll
            for (int mt = 0; mt < 2; mt++)
                ldsm4(a[mt][0], a[mt][1], a[mt][2], a[mt][3],
                      s_u + bs*A_STG + aOff + mt*(16*GK*4) + kk*32);
            #pragma unroll
            for (int pr = 0; pr < 4; pr++) {
                unsigned b0, b1, b2, b3;
                ldsm4(b0, b1, b2, b3,
                      s_u + B_OFF + bs*B_STG + bFrag + pr*(16*GK*4) + kk*32);
                #pragma unroll
                for (int mt = 0; mt < 2; mt++) {
                    mmah(acc[mt][2*pr  ], a[mt][0], a[mt][1], a[mt][2], a[mt][3], b0, b1);
                    mmah(acc[mt][2*pr+1], a[mt][0], a[mt][1], a[mt][2], a[mt][3], b2, b3);
                }
            }
        }
    }

    // ---- start phase-2 chunk-0 B load early (B buffers free after the loop) --
    const unsigned* mWP = g_wt[5];
    auto issue2 = [&](int ch, int bs) {
        int cc = ch*32;
        #pragma unroll
        for (int j = 0; j < 8; j++)
            cpa16(s_u + B_OFF + bs*B_STG + (brow[j]*GK + bf4[j]*4)*4,
                  &mWP[(size_t)brow[j]*128 + cc + bf4[j]*4]);
        cpa_commit();
    };
    issue2(0, 0);

    // ---- phase-1 epilogue: gate1 = gate0*(rmha+bo) + Matrix(fp16) -> smem ----
    #pragma unroll
    for (int mt = 0; mt < 2; mt++) {
        int rl0 = wm*32 + mt*16 + g, rl1 = rl0 + 8;
        int row0 = m0 + rl0, row1 = m0 + rl1;
        #pragma unroll
        for (int nt = 0; nt < 8; nt++) {
            int col = wn*64 + nt*8 + t*2;
            int cp  = col >> 1;
            int ch = cp >> 5, cc = cp & 31;
            float bv0 = bo[col], bv1 = bo[col+1];
            float v00 = acc[mt][nt][0] + bv0, v01 = acc[mt][nt][1] + bv1;
            float v10 = acc[mt][nt][2] + bv0, v11 = acc[mt][nt][3] + bv1;
            float2 ga0 = up2(g_g0h[row0*128 + cp]);
            float2 ga1 = up2(g_g0h[row1*128 + cp]);
            float2 mx0 = up2(g_mth[row0*128 + cp]);
            float2 mx1 = up2(g_mth[row1*128 + cp]);
            v00 = ga0.x*v00 + mx0.x;  v01 = ga0.y*v01 + mx0.y;
            v10 = ga1.x*v10 + mx1.x;  v11 = ga1.y*v11 + mx1.y;
            smem[(g1base(ch) >> 2) + rl0*GK + cc] = pkh(v00, v01);
            smem[(g1base(ch) >> 2) + rl1*GK + cc] = pkh(v10, v11);
        }
    }

    // ---- phase 2: mlp = gate1 @ mW (A from smem gate1) ----
    #pragma unroll
    for (int mt = 0; mt < 2; mt++)
        #pragma unroll
        for (int nt = 0; nt < 8; nt++)
            #pragma unroll
            for (int i = 0; i < 4; i++) acc[mt][nt][i] = 0.f;

    #pragma unroll 1
    for (int c = 0; c < 4; c++) {
        asm volatile("cp.async.wait_group 0;");
        __syncthreads();   // B chunk c visible; gate1 visible (1st iter); compute c-1 done
        if (c < 3) issue2(c+1, (c+1) & 1);
        int bs = c & 1;
        #pragma unroll
        for (int kk = 0; kk < 4; kk++) {
            unsigned a[2][4];
            #pragma unroll
            for (int mt = 0; mt < 2; mt++)
                ldsm4(a[mt][0], a[mt][1], a[mt][2], a[mt][3],
                      s_u + g1base(c) + aOff + mt*(16*GK*4) + kk*32);
            #pragma unroll
            for (int pr = 0; pr < 4; pr++) {
                unsigned b0, b1, b2, b3;
                ldsm4(b0, b1, b2, b3,
                      s_u + B_OFF + bs*B_STG + bFrag + pr*(16*GK*4) + kk*32);
                #pragma unroll
                for (int mt = 0; mt < 2; mt++) {
                    mmah(acc[mt][2*pr  ], a[mt][0], a[mt][1], a[mt][2], a[mt][3], b0, b1);
                    mmah(acc[mt][2*pr+1], a[mt][0], a[mt][1], a[mt][2], a[mt][3], b2, b3);
                }
            }
        }
    }
    __syncthreads();   // B region free -> LN scratch

    // ---- phase-2 epilogue: sigmoid + per-row LN + gated output ----
    float* sS = (float*)&smem[B_OFF >> 2];   // 512 floats inside B region
    float* sQ = sS + 256;

    float psum[2][2] = {{0,0},{0,0}}, psq[2][2] = {{0,0},{0,0}};
    #pragma unroll
    for (int mt = 0; mt < 2; mt++) {
        #pragma unroll
        for (int nt = 0; nt < 8; nt++) {
            int col = wn*64 + nt*8 + t*2;
            float bv0 = mb[col], bv1 = mb[col+1];
            float v00 = 1.f/(1.f + __expf(-(acc[mt][nt][0] + bv0)));
            float v01 = 1.f/(1.f + __expf(-(acc[mt][nt][1] + bv1)));
            float v10 = 1.f/(1.f + __expf(-(acc[mt][nt][2] + bv0)));
            float v11 = 1.f/(1.f + __expf(-(acc[mt][nt][3] + bv1)));
            acc[mt][nt][0] = v00; acc[mt][nt][1] = v01;
            acc[mt][nt][2] = v10; acc[mt][nt][3] = v11;
            psum[mt][0] += v00 + v01;  psq[mt][0] += v00*v00 + v01*v01;
            psum[mt][1] += v10 + v11;  psq[mt][1] += v10*v10 + v11*v11;
        }
    }
    #pragma unroll
    for (int mt = 0; mt < 2; mt++)
        #pragma unroll
        for (int hf = 0; hf < 2; hf++) {
            float s = psum[mt][hf], q = psq[mt][hf];
            s += __shfl_xor_sync(0xffffffffu, s, 1);
            s += __shfl_xor_sync(0xffffffffu, s, 2);
            q += __shfl_xor_sync(0xffffffffu, q, 1);
            q += __shfl_xor_sync(0xffffffffu, q, 2);
            psum[mt][hf] = s; psq[mt][hf] = q;
        }
    if (t == 0) {
        #pragma unroll
        for (int mt = 0; mt < 2; mt++)
            #pragma unroll
            for (int hf = 0; hf < 2; hf++) {
                int r = wm*32 + mt*16 + g + hf*8;
                sS[r*4 + wn] = psum[mt][hf];
                sQ[r*4 + wn] = psq[mt][hf];
            }
    }
    __syncthreads();

    float mean[2][2], rstd[2][2];
    #pragma unroll
    for (int mt = 0; mt < 2; mt++)
        #pragma unroll
        for (int hf = 0; hf < 2; hf++) {
            int r = wm*32 + mt*16 + g + hf*8;
            float s = sS[r*4+0] + sS[r*4+1] + sS[r*4+2] + sS[r*4+3];
            float q = sQ[r*4+0] + sQ[r*4+1] + sQ[r*4+2] + sQ[r*4+3];
            float m = s * (1.f/EE);
            float v = q * (1.f/EE) - m*m;
            mean[mt][hf] = m;
            rstd[mt][hf] = rsqrtf(v + 1e-5f);
        }

    #pragma unroll
    for (int mt = 0; mt < 2; mt++) {
        int rl0 = wm*32 + mt*16 + g, rl1 = rl0 + 8;
        int row0 = m0 + rl0, row1 = m0 + rl1;
        #pragma unroll
        for (int nt = 0; nt < 8; nt++) {
            int col = wn*64 + nt*8 + t*2;
            int cp  = col >> 1;
            int ch = cp >> 5, cc = cp & 31;
            float2 gm = *(const float2*)&lng[col];
            float2 bt = *(const float2*)&lnb[col];
            size_t i0 = (size_t)row0*EE + col, i1 = (size_t)row1*EE + col;
            float2 g10 = up2(smem[(g1base(ch) >> 2) + rl0*GK + cc]);
            float2 g11 = up2(smem[(g1base(ch) >> 2) + rl1*GK + cc]);
            float ln00 = (acc[mt][nt][0] - mean[mt][0])*rstd[mt][0]*gm.x + bt.x;
            float ln01 = (acc[mt][nt][1] - mean[mt][0])*rstd[mt][0]*gm.y + bt.y;
            float ln10 = (acc[mt][nt][2] - mean[mt][1])*rstd[mt][1]*gm.x + bt.x;
            float ln11 = (acc[mt][nt][3] - mean[mt][1])*rstd[mt][1]*gm.y + bt.y;
            *(float2*)&out[i0] = make_float2(g10.x*(ln00+1.f), g10.y*(ln01+1.f));
            *(float2*)&out[i1] = make_float2(g11.x*(ln10+1.f), g11.y*(ln11+1.f));
        }
    }
}

// ---------------- head-paired fp16 flash attention, 3-stage, 1 barrier/tile ---
#define AP 36
__global__ __launch_bounds__(256, 2) void attn_h2()
{
    extern __shared__ __align__(16) unsigned smem[];
    const unsigned KBUF = 64*AP*4;        // 9216 B per stage

    int tid = threadIdx.x, lane = tid & 31, wq = tid >> 5;
    int g = lane >> 2, t = lane & 3;
    int bhp = blockIdx.x;
    int b = bhp >> 2, hp = bhp & 3;
    int q0 = blockIdx.y * 128;

    int r0 = q0 + wq*16 + g;
    int qrow0 = b*SS + r0, qrow1 = qrow0 + 8;

    unsigned sK_u = (unsigned)__cvta_generic_to_shared(smem);
    unsigned sV_u = sK_u + 3*KBUF;
    int l8 = lane & 7, qd = lane >> 3;
    unsigned kBase = sK_u + (((qd>>1)*8 + l8)*AP + (qd&1)*4)*4;
    unsigned vBase = sV_u + (((qd&1)*8 + l8)*AP)*4 + (qd>>1)*16;

    unsigned qhf[2][2][4];
    #pragma unroll
    for (int h = 0; h < 2; h++)
        #pragma unroll
        for (int kk = 0; kk < 2; kk++) {
            int base = hp*32 + h*16 + kk*8 + t;
            int b0 = qrow0*128 + base, b1 = qrow1*128 + base;
            qhf[h][kk][0] = g_qph[b0]; qhf[h][kk][1] = g_qph[b1];
            qhf[h][kk][2] = g_qph[b0+4]; qhf[h][kk][3] = g_qph[b1+4];
        }

    float O[2][4][4];
    #pragma unroll
    for (int h = 0; h < 2; h++)
        #pragma unroll
        for (int dn = 0; dn < 4; dn++)
            #pragma unroll
            for (int i = 0; i < 4; i++) O[h][dn][i] = 0.f;
    float ms0[2] = {-1e30f,-1e30f}, ms1[2] = {-1e30f,-1e30f};
    float ls0[2] = {0.f,0.f}, ls1[2] = {0.f,0.f};

    int lrow[2], lf[2];
    #pragma unroll
    for (int j = 0; j < 2; j++) { int idx = tid + j*256; lrow[j] = idx >> 3; lf[j] = idx & 7; }

    auto issue = [&](int kt, int bs) {
        #pragma unroll
        for (int j = 0; j < 2; j++) {
            size_t src = (size_t)(b*SS + kt*64 + lrow[j])*128 + hp*32 + lf[j]*4;
            unsigned d = (lrow[j]*AP + lf[j]*4)*4;
            cpa16(sK_u + bs*KBUF + d, &g_kph[src]);
            cpa16(sV_u + bs*KBUF + d, &g_vph[src]);
        }
        cpa_commit();
    };
    issue(0, 0);
    issue(1, 1);

    const unsigned ONE2 = 0x3C003C00u;

    #pragma unroll 1
    for (int kt = 0; kt < 16; kt++) {
        if (kt < 15) asm volatile("cp.async.wait_group 1;");
        else         asm volatile("cp.async.wait_group 0;");
        __syncthreads();
        if (kt < 14) issue(kt+2, (kt+2) % 3);
        int bsel = kt % 3;

        unsigned bf[8][2];
        #pragma unroll
        for (int nt = 0; nt < 8; nt++) {
            int pc = kt*32 + nt*4 + t;
            bf[nt][0] = g_rbh[r0*512 + pc];
            bf[nt][1] = g_rbh[(r0+8)*512 + pc];
        }

        #pragma unroll
        for (int h = 0; h < 2; h++) {
            float S_[8][4];
            #pragma unroll
            for (int nt = 0; nt < 8; nt++)
                #pragma unroll
                for (int i = 0; i < 4; i++) S_[nt][i] = 0.f;
            #pragma unroll
            for (int kk = 0; kk < 2; kk++) {
                #pragma unroll
                for (int p = 0; p < 4; p++) {
                    unsigned k0r, k1r, k2r, k3r;
                    ldsm4(k0r, k1r, k2r, k3r,
                          kBase + h*64 + bsel*KBUF + p*(16*AP*4) + kk*32);
                    mmah(S_[2*p  ], qhf[h][kk][0], qhf[h][kk][1], qhf[h][kk][2], qhf[h][kk][3], k0r, k1r);
                    mmah(S_[2*p+1], qhf[h][kk][0], qhf[h][kk][1], qhf[h][kk][2], qhf[h][kk][3], k2r, k3r);
                }
            }
            #pragma unroll
            for (int nt = 0; nt < 8; nt++) {
                float2 b0v = up2(bf[nt][0]);
                float2 b1v = up2(bf[nt][1]);
                S_[nt][0] += b0v.x; S_[nt][1] += b0v.y;
                S_[nt][2] += b1v.x; S_[nt][3] += b1v.y;
            }

            float tm0 = -1e30f, tm1 = -1e30f;
            #pragma unroll
            for (int nt = 0; nt < 8; nt++) {
                tm0 = fmaxf(tm0, fmaxf(S_[nt][0], S_[nt][1]));
                tm1 = fmaxf(tm1, fmaxf(S_[nt][2], S_[nt][3]));
            }
            tm0 = fmaxf(tm0, __shfl_xor_sync(0xffffffffu, tm0, 1));
            tm0 = fmaxf(tm0, __shfl_xor_sync(0xffffffffu, tm0, 2));
            tm1 = fmaxf(tm1, __shfl_xor_sync(0xffffffffu, tm1, 1));
            tm1 = fmaxf(tm1, __shfl_xor_sync(0xffffffffu, tm1, 2));
            float nm0 = fmaxf(ms0[h], tm0), nm1 = fmaxf(ms1[h], tm1);
            float sc0 = ex2(ms0[h] - nm0), sc1 = ex2(ms1[h] - nm1);

            unsigned pf[8][2];
            #pragma unroll
            for (int nt = 0; nt < 8; nt++) {
                __half2 d0 = __floats2half2_rn(S_[nt][0] - nm0, S_[nt][1] - nm0);
                __half2 d1 = __floats2half2_rn(S_[nt][2] - nm1, S_[nt][3] - nm1);
                __half2 p0 = h2exp2(d0);
                __half2 p1 = h2exp2(d1);
                pf[nt][0] = *reinterpret_cast<unsigned*>(&p0);
                pf[nt][1] = *reinterpret_cast<unsigned*>(&p1);
            }

            float rsA[4] = {0.f, 0.f, 0.f, 0.f};
            #pragma unroll
            for (int kk = 0; kk < 4; kk++)
                mmah(rsA, pf[2*kk][0], pf[2*kk][1], pf[2*kk+1][0], pf[2*kk+1][1], ONE2, ONE2);
            ls0[h] = ls0[h]*sc0 + rsA[0];
            ls1[h] = ls1[h]*sc1 + rsA[2];
            ms0[h] = nm0;  ms1[h] = nm1;
            #pragma unroll
            for (int dn = 0; dn < 4; dn++) {
                O[h][dn][0] *= sc0; O[h][dn][1] *= sc0;
                O[h][dn][2] *= sc1; O[h][dn][3] *= sc1;
            }

            #pragma unroll
            for (int kk = 0; kk < 4; kk++) {
                unsigned a0 = pf[2*kk][0], a1 = pf[2*kk][1];
                unsigned a2 = pf[2*kk+1][0], a3 = pf[2*kk+1][1];
                #pragma unroll
                for (int p = 0; p < 2; p++) {
                    unsigned v0, v1, v2, v3;
                    ldsm4t(v0, v1, v2, v3,
                           vBase + h*64 + bsel*KBUF + kk*(16*AP*4) + p*32);
                    mmah(O[h][2*p  ], a0, a1, a2, a3, v0, v1);
                    mmah(O[h][2*p+1], a0, a1, a2, a3, v2, v3);
                }
            }
        }
    }

    #pragma unroll
    for (int h = 0; h < 2; h++) {
        int hd = hp*2 + h;
        float il0 = 1.f/ls0[h], il1 = 1.f/ls1[h];
        #pragma unroll
        for (int dn = 0; dn < 4; dn++) {
            int cp = hd*16 + dn*4 + t;
            g_oph[qrow0*128 + cp] = pkh(O[h][dn][0]*il0, O[h][dn][1]*il0);
            g_oph[qrow1*128 + cp] = pkh(O[h][dn][2]*il1, O[h][dn][3]*il1);
        }
    }
}

// ---------------- launch ------------------------------------------------------
extern "C" void kernel_launch(void* const* d_in, const int* in_sizes, int n_in,
                              void* d_out, int out_size)
{
    const float* Matrix = (const float*)d_in[0];
    const float* ln_g   = (const float*)d_in[1];
    const float* ln_b   = (const float*)d_in[2];
    const float* Wq     = (const float*)d_in[3];
    const float* bq     = (const float*)d_in[4];
    const float* Wk     = (const float*)d_in[5];
    const float* bk     = (const float*)d_in[6];
    const float* Wv     = (const float*)d_in[7];
    const float* bv     = (const float*)d_in[8];
    const float* Wo     = (const float*)d_in[9];
    const float* bo     = (const float*)d_in[10];
    const float* rel    = (const float*)d_in[11];
    const float* gW     = (const float*)d_in[12];
    const float* gb     = (const float*)d_in[13];
    const float* mW     = (const float*)d_in[14];
    const float* mb     = (const float*)d_in[15];
    float* out = (float*)d_out;

    const int SM1 = 2*(128*GK*4) + 2*(64*GK*4);             // 55296
    const int SMT = 2*(64*GK*4) + 2*(256*GK*4) + 2*(64*GK*4); // 110592
    const int SMA = 6*(64*AP*4);                            // 55296
    static bool attr_set = false;
    if (!attr_set) {
        cudaFuncSetAttribute(gemm_t, cudaFuncAttributeMaxDynamicSharedMemorySize, SM1);
        cudaFuncSetAttribute(gemm_tail, cudaFuncAttributeMaxDynamicSharedMemorySize, SMT);
        cudaFuncSetAttribute(attn_h2, cudaFuncAttributeMaxDynamicSharedMemorySize, SMA);
        attr_set = true;
    }

    prep<<<3168, 256>>>(Matrix, ln_g, ln_b, Wq, Wk, Wv, gW, Wo, mW, rel);

    gemm_t<<<dim3(4,128,4), 256, SM1>>>(bq, bk, bv, gb);
    attn_h2<<<dim3(64,8), 256, SMA>>>();
    gemm_tail<<<256, 256, SMT>>>(bo, mb, ln_g, ln_b, out);
}